// round 6
// baseline (speedup 1.0000x reference)
#include <cuda_runtime.h>
#include <cuda_bf16.h>
#include <cstdint>

#define Bn 4
#define Tn 512
#define Dn 1024
#define Hn 16
#define HSn 64
#define Ln 8
#define Vn 32000
#define Mn (Bn*Tn)       // 2048
#define FFn (4*Dn)       // 4096
#define BHn (Bn*Hn)      // 64

typedef __nv_bfloat16 bf16;

// ---------------- fp32 scratch ----------------
__device__ float g_h[Mn*Dn];
__device__ float g_y[Mn*Dn];
__device__ float g_q[Mn*Dn];
__device__ float g_k[Mn*Dn];
__device__ float g_v[Mn*Dn];
__device__ float g_o[Mn*Dn];
__device__ float g_a[Mn*FFn];
__device__ float g_s[(size_t)BHn*Tn*Tn];

// ---------------- bf16 hi/lo planes (activations) ----------------
__device__ bf16 g_yH[Mn*Dn],  g_yL[Mn*Dn];
__device__ bf16 g_qH[Mn*Dn],  g_qL[Mn*Dn];
__device__ bf16 g_kH[Mn*Dn],  g_kL[Mn*Dn];
__device__ bf16 g_vtH[Mn*Dn], g_vtL[Mn*Dn];
__device__ bf16 g_oH[Mn*Dn],  g_oL[Mn*Dn];
__device__ bf16 g_aH[Mn*FFn], g_aL[Mn*FFn];
__device__ bf16 g_sH[(size_t)BHn*Tn*Tn], g_sL[(size_t)BHn*Tn*Tn];

// ---------------- bf16 hi/lo planes (weights, transposed [N,K]) -----------
__device__ bf16 g_wqH[Ln*Dn*Dn], g_wqL[Ln*Dn*Dn];
__device__ bf16 g_wkH[Ln*Dn*Dn], g_wkL[Ln*Dn*Dn];
__device__ bf16 g_wvH[Ln*Dn*Dn], g_wvL[Ln*Dn*Dn];
__device__ bf16 g_woH[Ln*Dn*Dn], g_woL[Ln*Dn*Dn];
__device__ bf16 g_w1H[Ln*Dn*FFn], g_w1L[Ln*Dn*FFn];
__device__ bf16 g_w2H[Ln*Dn*FFn], g_w2L[Ln*Dn*FFn];
__device__ bf16 g_wfH[(size_t)Dn*Vn], g_wfL[(size_t)Dn*Vn];

// ==================== helpers ====================
__device__ __forceinline__ uint32_t smem_u32(const void* p){
    uint32_t a;
    asm("{ .reg .u64 t; cvta.to.shared.u64 t, %1; cvt.u32.u64 %0, t; }" : "=r"(a) : "l"(p));
    return a;
}
#define CP16(dst, src) \
    asm volatile("cp.async.cg.shared.global [%0], [%1], 16;" :: "r"(dst), "l"(src))
#define CP_COMMIT() asm volatile("cp.async.commit_group;" ::: "memory")
#define CP_WAIT1() asm volatile("cp.async.wait_group 1;" ::: "memory")
#define CP_WAIT0() asm volatile("cp.async.wait_group 0;" ::: "memory")

#define LDSM4(r0,r1,r2,r3,addr) \
    asm volatile("ldmatrix.sync.aligned.m8n8.x4.shared.b16 {%0,%1,%2,%3}, [%4];" \
        : "=r"(r0),"=r"(r1),"=r"(r2),"=r"(r3) : "r"(addr))

#define MMA16816(d, a, b) \
    asm volatile("mma.sync.aligned.m16n8k16.row.col.f32.bf16.bf16.f32 " \
        "{%0,%1,%2,%3}, {%4,%5,%6,%7}, {%8,%9}, {%0,%1,%2,%3};" \
        : "+f"((d)[0]),"+f"((d)[1]),"+f"((d)[2]),"+f"((d)[3]) \
        : "r"((a)[0]),"r"((a)[1]),"r"((a)[2]),"r"((a)[3]), "r"((b)[0]),"r"((b)[1]))

// ==================== reductions ====================
__device__ __forceinline__ float warpSum(float v){
#pragma unroll
    for (int o = 16; o > 0; o >>= 1) v += __shfl_down_sync(0xffffffffu, v, o);
    return v;
}
__device__ __forceinline__ float warpMax(float v){
#pragma unroll
    for (int o = 16; o > 0; o >>= 1) v = fmaxf(v, __shfl_down_sync(0xffffffffu, v, o));
    return v;
}
__device__ __forceinline__ float blockSum(float v, float* sh){
    int lane = threadIdx.x & 31, w = threadIdx.x >> 5;
    v = warpSum(v);
    __syncthreads();
    if (lane == 0) sh[w] = v;
    __syncthreads();
    int nw = blockDim.x >> 5;
    v = (threadIdx.x < (unsigned)nw) ? sh[threadIdx.x] : 0.f;
    if (w == 0) v = warpSum(v);
    if (threadIdx.x == 0) sh[0] = v;
    __syncthreads();
    return sh[0];
}
__device__ __forceinline__ float blockMax(float v, float* sh){
    int lane = threadIdx.x & 31, w = threadIdx.x >> 5;
    v = warpMax(v);
    __syncthreads();
    if (lane == 0) sh[w] = v;
    __syncthreads();
    int nw = blockDim.x >> 5;
    v = (threadIdx.x < (unsigned)nw) ? sh[threadIdx.x] : -3.0e38f;
    if (w == 0) v = warpMax(v);
    if (threadIdx.x == 0) sh[0] = v;
    __syncthreads();
    return sh[0];
}

// ==================== small kernels ====================
__global__ void embed_k(const int* __restrict__ x, const float* __restrict__ ce,
                        const float* __restrict__ pe){
    int idx = blockIdx.x * blockDim.x + threadIdx.x;
    int d  = idx & (Dn - 1);
    int mt = idx >> 10;
    int t  = mt & (Tn - 1);
    g_h[idx] = ce[(size_t)x[mt] * Dn + d] + pe[t * Dn + d];
}

__global__ __launch_bounds__(256) void ln_k(const float* __restrict__ in,
                                            float* __restrict__ out,
                                            const float* __restrict__ gs,
                                            const float* __restrict__ gb){
    __shared__ float sh[32];
    int row = blockIdx.x;
    const float* xr = in + (size_t)row * Dn;
    float s = 0.f, sq = 0.f;
    for (int i = threadIdx.x; i < Dn; i += 256){ float v = xr[i]; s += v; sq += v * v; }
    s  = blockSum(s, sh);
    sq = blockSum(sq, sh);
    float mean = s * (1.f / Dn);
    float var  = sq * (1.f / Dn) - mean * mean;
    float r = rsqrtf(var + 1e-5f);
    float* orow = out + (size_t)row * Dn;
    for (int i = threadIdx.x; i < Dn; i += 256)
        orow[i] = (xr[i] - mean) * r * gs[i] + gb[i];
}

__global__ __launch_bounds__(128) void softmax_k(){
    __shared__ float sh[32];
    int row = blockIdx.x;           // 0 .. BHn*Tn-1
    int i = row & (Tn - 1);
    float* sr = g_s + (size_t)row * Tn;
    float mx = -3.0e38f;
    for (int j = threadIdx.x; j <= i; j += 128) mx = fmaxf(mx, sr[j]);
    mx = blockMax(mx, sh);
    float sum = 0.f;
    for (int j = threadIdx.x; j <= i; j += 128){
        float e = expf(sr[j] - mx);
        sr[j] = e;
        sum += e;
    }
    sum = blockSum(sum, sh);
    float inv = 1.f / sum;
    for (int j = threadIdx.x; j <= i; j += 128) sr[j] *= inv;
    for (int j = i + 1 + threadIdx.x; j < Tn; j += 128) sr[j] = 0.f;
}

// elementwise fp32 -> bf16 hi/lo planes (float4 granularity)
__global__ void convA(const float* __restrict__ in, bf16* __restrict__ oh,
                      bf16* __restrict__ ol, int n4){
    int i = blockIdx.x * blockDim.x + threadIdx.x;
    if (i >= n4) return;
    float4 v = ((const float4*)in)[i];
    bf16 h0 = __float2bfloat16(v.x), h1 = __float2bfloat16(v.y);
    bf16 h2 = __float2bfloat16(v.z), h3 = __float2bfloat16(v.w);
    bf16 l0 = __float2bfloat16(v.x - __bfloat162float(h0));
    bf16 l1 = __float2bfloat16(v.y - __bfloat162float(h1));
    bf16 l2 = __float2bfloat16(v.z - __bfloat162float(h2));
    bf16 l3 = __float2bfloat16(v.w - __bfloat162float(h3));
    __nv_bfloat162* ohp = (__nv_bfloat162*)oh;
    __nv_bfloat162* olp = (__nv_bfloat162*)ol;
    ohp[2*i]   = __nv_bfloat162(h0, h1);
    ohp[2*i+1] = __nv_bfloat162(h2, h3);
    olp[2*i]   = __nv_bfloat162(l0, l1);
    olp[2*i+1] = __nv_bfloat162(l2, l3);
}

// transpose + convert: in [R,C] fp32 -> out [C,R] bf16 hi/lo
__global__ __launch_bounds__(256) void convT(const float* __restrict__ in,
                                             bf16* __restrict__ oh, bf16* __restrict__ ol,
                                             int ldin, int ldout, int zH,
                                             long long sIb, long long sIh,
                                             long long sOb, long long sOh){
    __shared__ float t[32][33];
    int z = blockIdx.z, bz = z / zH, hz = z % zH;
    const float* pin = in + bz * sIb + hz * sIh;
    bf16* poh = oh + bz * sOb + hz * sOh;
    bf16* pol = ol + bz * sOb + hz * sOh;
    int cb = blockIdx.x * 32, rb = blockIdx.y * 32;
    int tx = threadIdx.x, ty = threadIdx.y;  // (32, 8)
#pragma unroll
    for (int i = 0; i < 4; i++)
        t[ty + 8*i][tx] = pin[(size_t)(rb + ty + 8*i) * ldin + cb + tx];
    __syncthreads();
#pragma unroll
    for (int i = 0; i < 4; i++){
        float v = t[tx][ty + 8*i];
        bf16 h = __float2bfloat16(v);
        bf16 l = __float2bfloat16(v - __bfloat162float(h));
        size_t o = (size_t)(cb + ty + 8*i) * ldout + rb + tx;
        poh[o] = h; pol[o] = l;
    }
}

// ==================== bf16-split mma.sync GEMM ====================
// C[z][M,N] = A[z][M,K] @ B[z][N,K]^T  via 3-pass split bf16, fp32 accum.
#define F_BIAS   1
#define F_RES    2
#define F_RELU   4
#define F_SCALE  8
#define F_CAUSAL 16

template<int BN>
__global__ __launch_bounds__(256) void gemm_mma(
    const bf16* __restrict__ Ah, const bf16* __restrict__ Al,
    const bf16* __restrict__ Bh, const bf16* __restrict__ Bl,
    const float* __restrict__ bias, const float* __restrict__ res,
    float* __restrict__ C,
    int K, int lda, int ldb, int ldc,
    int zH, long long sAb, long long sAh, long long sBb, long long sBh,
    long long sCb, long long sCh,
    int flags, float scale)
{
    constexpr int BM = 128, BK = 32;
    constexpr int SA = 40;                 // padded smem row (bf16 elems) -> 80B
    constexpr int ABYTES = BM * SA * 2;    // 10240
    constexpr int BBYTES = BN * SA * 2;
    constexpr int STAGE = 2 * ABYTES + 2 * BBYTES;
    constexpr int WN = BN / 2;
    constexpr int NA = WN / 8;             // n atoms per warp

    const int bm = blockIdx.y * BM, bn = blockIdx.x * BN;
    if ((flags & F_CAUSAL) && bn >= bm + BM) return;

    extern __shared__ char sm[];
    const uint32_t smb = smem_u32(sm);

    const int tid = threadIdx.x, lane = tid & 31, wid = tid >> 5;
    const int wm = wid & 3, wn = wid >> 2;

    const int z = blockIdx.z;
    const int bz = z / zH, hz = z % zH;
    const bf16* pAh = Ah + bz * sAb + hz * sAh;
    const bf16* pAl = Al + bz * sAb + hz * sAh;
    const bf16* pBh = Bh + bz * sBb + hz * sBh;
    const bf16* pBl = Bl + bz * sBb + hz * sBh;
    float* pC = C + bz * sCb + hz * sCh;
    const float* pres = res ? (res + bz * sCb + hz * sCh) : nullptr;

    const int nKB = K >> 5;

    auto loadStage = [&](int kb, int s){
        const int k0 = kb * BK;
        const uint32_t stg = smb + s * STAGE;
#pragma unroll
        for (int i = 0; i < 2; i++){             // A: 512 chunks/plane
            int idx = i * 256 + tid;
            int r = idx >> 2, c = idx & 3;
            uint32_t dst = stg + r * 80 + c * 16;
            const bf16* sH = pAh + (size_t)(bm + r) * lda + k0 + c * 8;
            const bf16* sL = pAl + (size_t)(bm + r) * lda + k0 + c * 8;
            CP16(dst, sH);
            CP16(dst + ABYTES, sL);
        }
#pragma unroll
        for (int i = 0; i < BN / 64; i++){       // B: BN*4 chunks/plane
            int idx = i * 256 + tid;
            int r = idx >> 2, c = idx & 3;
            uint32_t dst = stg + 2 * ABYTES + r * 80 + c * 16;
            const bf16* sH = pBh + (size_t)(bn + r) * ldb + k0 + c * 8;
            const bf16* sL = pBl + (size_t)(bn + r) * ldb + k0 + c * 8;
            CP16(dst, sH);
            CP16(dst + BBYTES, sL);
        }
        CP_COMMIT();
    };

    float acc[2][NA][4];
#pragma unroll
    for (int i = 0; i < 2; i++)
#pragma unroll
        for (int j = 0; j < NA; j++)
#pragma unroll
            for (int q = 0; q < 4; q++) acc[i][j][q] = 0.f;

    loadStage(0, 0);

    for (int kb = 0; kb < nKB; kb++){
        const int s = kb & 1;
        if (kb + 1 < nKB){ loadStage(kb + 1, s ^ 1); CP_WAIT1(); }
        else             { CP_WAIT0(); }
        __syncthreads();

        const uint32_t stg = smb + s * STAGE;
#pragma unroll
        for (int ks = 0; ks < 2; ks++){
            const int kc = ks * 16;
            uint32_t a_h[2][4], a_l[2][4];
#pragma unroll
            for (int mi = 0; mi < 2; mi++){
                int row = wm * 32 + mi * 16 + (lane & 15);
                int colb = (kc + ((lane >> 4) << 3)) * 2;
                uint32_t ad = stg + row * 80 + colb;
                LDSM4(a_h[mi][0], a_h[mi][1], a_h[mi][2], a_h[mi][3], ad);
                LDSM4(a_l[mi][0], a_l[mi][1], a_l[mi][2], a_l[mi][3], ad + ABYTES);
            }
            uint32_t b_h[NA][2], b_l[NA][2];
#pragma unroll
            for (int p = 0; p < NA / 2; p++){
                int rowb = wn * WN + p * 16 + (lane & 7) + ((lane >> 4) << 3);
                int colb = (kc + (((lane >> 3) & 1) << 3)) * 2;
                uint32_t ad = stg + 2 * ABYTES + rowb * 80 + colb;
                uint32_t r0, r1, r2, r3;
                LDSM4(r0, r1, r2, r3, ad);
                b_h[2*p][0] = r0; b_h[2*p][1] = r1;
                b_h[2*p+1][0] = r2; b_h[2*p+1][1] = r3;
                LDSM4(r0, r1, r2, r3, ad + BBYTES);
                b_l[2*p][0] = r0; b_l[2*p][1] = r1;
                b_l[2*p+1][0] = r2; b_l[2*p+1][1] = r3;
            }
#pragma unroll
            for (int mi = 0; mi < 2; mi++)
#pragma unroll
                for (int ni = 0; ni < NA; ni++){
                    MMA16816(acc[mi][ni], a_h[mi], b_h[ni]);
                    MMA16816(acc[mi][ni], a_l[mi], b_h[ni]);
                    MMA16816(acc[mi][ni], a_h[mi], b_l[ni]);
                }
        }
        __syncthreads();
    }

    // epilogue
#pragma unroll
    for (int mi = 0; mi < 2; mi++){
#pragma unroll
        for (int ni = 0; ni < NA; ni++){
            int r0 = bm + wm * 32 + mi * 16 + (lane >> 2);
            int c0 = bn + wn * WN + ni * 8 + (lane & 3) * 2;
#pragma unroll
            for (int half = 0; half < 2; half++){
                int r = r0 + half * 8;
                float vx = acc[mi][ni][half * 2 + 0];
                float vy = acc[mi][ni][half * 2 + 1];
                if (flags & F_SCALE){ vx *= scale; vy *= scale; }
                if (flags & F_BIAS){ vx += bias[c0]; vy += bias[c0 + 1]; }
                if (flags & F_RES){
                    const float* rp = pres + (size_t)r * ldc + c0;
                    vx += rp[0]; vy += rp[1];
                }
                if (flags & F_RELU){ vx = fmaxf(vx, 0.f); vy = fmaxf(vy, 0.f); }
                if (flags & F_CAUSAL){
                    if (c0 > r)     vx = -3.0e38f;
                    if (c0 + 1 > r) vy = -3.0e38f;
                }
                float2 o2; o2.x = vx; o2.y = vy;
                *(float2*)(pC + (size_t)r * ldc + c0) = o2;
            }
        }
    }
}

// ==================== host orchestration ====================
extern "C" void kernel_launch(void* const* d_in, const int* in_sizes, int n_in,
                              void* d_out, int out_size){
    (void)in_sizes; (void)n_in; (void)out_size;
    const int*   x     = (const int*)  d_in[0];
    const float* ce    = (const float*)d_in[1];
    const float* pe    = (const float*)d_in[2];
    const float* ln1_s = (const float*)d_in[5];
    const float* ln1_b = (const float*)d_in[6];
    const float* wq    = (const float*)d_in[7];
    const float* wk    = (const float*)d_in[8];
    const float* wv    = (const float*)d_in[9];
    const float* wo    = (const float*)d_in[10];
    const float* bo    = (const float*)d_in[11];
    const float* ln2_s = (const float*)d_in[12];
    const float* ln2_b = (const float*)d_in[13];
    const float* w1    = (const float*)d_in[14];
    const float* b1    = (const float*)d_in[15];
    const float* w2    = (const float*)d_in[16];
    const float* b2    = (const float*)d_in[17];
    const float* lnf_s = (const float*)d_in[18];
    const float* lnf_b = (const float*)d_in[19];
    const float* wf    = (const float*)d_in[20];
    const float* bf    = (const float*)d_in[21];

    float *h, *y, *q, *k, *v, *o, *a, *s;
    cudaGetSymbolAddress((void**)&h, g_h);
    cudaGetSymbolAddress((void**)&y, g_y);
    cudaGetSymbolAddress((void**)&q, g_q);
    cudaGetSymbolAddress((void**)&k, g_k);
    cudaGetSymbolAddress((void**)&v, g_v);
    cudaGetSymbolAddress((void**)&o, g_o);
    cudaGetSymbolAddress((void**)&a, g_a);
    cudaGetSymbolAddress((void**)&s, g_s);

    bf16 *yH,*yL,*qH,*qL,*kH,*kL,*vtH,*vtL,*oH,*oL,*aH,*aL,*sH,*sL;
    cudaGetSymbolAddress((void**)&yH, g_yH);  cudaGetSymbolAddress((void**)&yL, g_yL);
    cudaGetSymbolAddress((void**)&qH, g_qH);  cudaGetSymbolAddress((void**)&qL, g_qL);
    cudaGetSymbolAddress((void**)&kH, g_kH);  cudaGetSymbolAddress((void**)&kL, g_kL);
    cudaGetSymbolAddress((void**)&vtH, g_vtH);cudaGetSymbolAddress((void**)&vtL, g_vtL);
    cudaGetSymbolAddress((void**)&oH, g_oH);  cudaGetSymbolAddress((void**)&oL, g_oL);
    cudaGetSymbolAddress((void**)&aH, g_aH);  cudaGetSymbolAddress((void**)&aL, g_aL);
    cudaGetSymbolAddress((void**)&sH, g_sH);  cudaGetSymbolAddress((void**)&sL, g_sL);

    bf16 *wqH,*wqL,*wkH,*wkL,*wvH,*wvL,*woH,*woL,*w1H,*w1L,*w2H,*w2L,*wfH,*wfL;
    cudaGetSymbolAddress((void**)&wqH, g_wqH); cudaGetSymbolAddress((void**)&wqL, g_wqL);
    cudaGetSymbolAddress((void**)&wkH, g_wkH); cudaGetSymbolAddress((void**)&wkL, g_wkL);
    cudaGetSymbolAddress((void**)&wvH, g_wvH); cudaGetSymbolAddress((void**)&wvL, g_wvL);
    cudaGetSymbolAddress((void**)&woH, g_woH); cudaGetSymbolAddress((void**)&woL, g_woL);
    cudaGetSymbolAddress((void**)&w1H, g_w1H); cudaGetSymbolAddress((void**)&w1L, g_w1L);
    cudaGetSymbolAddress((void**)&w2H, g_w2H); cudaGetSymbolAddress((void**)&w2L, g_w2L);
    cudaGetSymbolAddress((void**)&wfH, g_wfH); cudaGetSymbolAddress((void**)&wfL, g_wfL);

    // dynamic smem: BN=128 -> 2*(2*10240+2*10240)=81920 ; BN=64 -> 61440
    const int SM128 = 81920, SM64 = 61440;
    cudaFuncSetAttribute(gemm_mma<128>, cudaFuncAttributeMaxDynamicSharedMemorySize, SM128);
    cudaFuncSetAttribute(gemm_mma<64>,  cudaFuncAttributeMaxDynamicSharedMemorySize, SM64);

    dim3 cb(32, 8);
    const long long DD = (long long)Dn * Dn;
    const long long DF = (long long)Dn * FFn;
    convT<<<dim3(Dn/32, Dn/32, Ln), cb>>>(wq, wqH, wqL, Dn, Dn, 1, DD, 0, DD, 0);
    convT<<<dim3(Dn/32, Dn/32, Ln), cb>>>(wk, wkH, wkL, Dn, Dn, 1, DD, 0, DD, 0);
    convT<<<dim3(Dn/32, Dn/32, Ln), cb>>>(wv, wvH, wvL, Dn, Dn, 1, DD, 0, DD, 0);
    convT<<<dim3(Dn/32, Dn/32, Ln), cb>>>(wo, woH, woL, Dn, Dn, 1, DD, 0, DD, 0);
    convT<<<dim3(FFn/32, Dn/32, Ln), cb>>>(w1, w1H, w1L, FFn, Dn, 1, DF, 0, DF, 0);
    convT<<<dim3(Dn/32, FFn/32, Ln), cb>>>(w2, w2H, w2L, Dn, FFn, 1, DF, 0, DF, 0);
    convT<<<dim3(Vn/32, Dn/32, 1),  cb>>>(wf, wfH, wfL, Vn, Dn, 1, 0, 0, 0, 0);

    embed_k<<<(Mn * Dn) / 256, 256>>>(x, ce, pe);

    const int nD4 = Mn * Dn / 4;
    const int nF4 = Mn * FFn / 4;
    const int nS4 = BHn * Tn * Tn / 4;
    const long long SAB = (long long)Tn * Dn;
    const long long SS1 = (long long)Tn * Tn;
    const long long SVT = (long long)HSn * Tn;

    for (int l = 0; l < Ln; l++){
        ln_k<<<Mn, 256>>>(h, y, ln1_s + l*Dn, ln1_b + l*Dn);
        convA<<<(nD4 + 255)/256, 256>>>(y, yH, yL, nD4);

        gemm_mma<128><<<dim3(8,16,1), 256, SM128>>>(yH, yL, wqH + (size_t)l*DD, wqL + (size_t)l*DD,
            nullptr, nullptr, q, Dn, Dn, Dn, Dn, 1, 0,0,0,0,0,0, 0, 1.f);
        gemm_mma<128><<<dim3(8,16,1), 256, SM128>>>(yH, yL, wkH + (size_t)l*DD, wkL + (size_t)l*DD,
            nullptr, nullptr, k, Dn, Dn, Dn, Dn, 1, 0,0,0,0,0,0, 0, 1.f);
        gemm_mma<128><<<dim3(8,16,1), 256, SM128>>>(yH, yL, wvH + (size_t)l*DD, wvL + (size_t)l*DD,
            nullptr, nullptr, v, Dn, Dn, Dn, Dn, 1, 0,0,0,0,0,0, 0, 1.f);

        convA<<<(nD4 + 255)/256, 256>>>(q, qH, qL, nD4);
        convA<<<(nD4 + 255)/256, 256>>>(k, kH, kL, nD4);
        convT<<<dim3(HSn/32, Tn/32, BHn), cb>>>(v, vtH, vtL, Dn, Tn, Hn,
            SAB, (long long)HSn, (long long)Hn*SVT, SVT);

        gemm_mma<128><<<dim3(4,4,BHn), 256, SM128>>>(qH, qL, kH, kL, nullptr, nullptr, s,
            HSn, Dn, Dn, Tn, Hn, SAB, (long long)HSn, SAB, (long long)HSn,
            (long long)Hn*SS1, SS1, F_SCALE | F_CAUSAL, 0.125f);
        softmax_k<<<BHn*Tn, 128>>>();
        convA<<<(nS4 + 255)/256, 256>>>(s, sH, sL, nS4);

        gemm_mma<64><<<dim3(1,4,BHn), 256, SM64>>>(sH, sL, vtH, vtL, nullptr, nullptr, o,
            Tn, Tn, Tn, Dn, Hn, (long long)Hn*SS1, SS1, (long long)Hn*SVT, SVT,
            SAB, (long long)HSn, 0, 1.f);

        convA<<<(nD4 + 255)/256, 256>>>(o, oH, oL, nD4);
        gemm_mma<128><<<dim3(8,16,1), 256, SM128>>>(oH, oL, woH + (size_t)l*DD, woL + (size_t)l*DD,
            bo + l*Dn, h, h, Dn, Dn, Dn, Dn, 1, 0,0,0,0,0,0, F_BIAS | F_RES, 1.f);

        ln_k<<<Mn, 256>>>(h, y, ln2_s + l*Dn, ln2_b + l*Dn);
        convA<<<(nD4 + 255)/256, 256>>>(y, yH, yL, nD4);
        gemm_mma<128><<<dim3(32,16,1), 256, SM128>>>(yH, yL, w1H + (size_t)l*DF, w1L + (size_t)l*DF,
            b1 + l*FFn, nullptr, a, Dn, Dn, Dn, FFn, 1, 0,0,0,0,0,0, F_BIAS | F_RELU, 1.f);
        convA<<<(nF4 + 255)/256, 256>>>(a, aH, aL, nF4);
        gemm_mma<128><<<dim3(8,16,1), 256, SM128>>>(aH, aL, w2H + (size_t)l*DF, w2L + (size_t)l*DF,
            b2 + l*Dn, h, h, FFn, FFn, FFn, Dn, 1, 0,0,0,0,0,0, F_BIAS | F_RES, 1.f);
    }

    ln_k<<<Mn, 256>>>(h, y, lnf_s, lnf_b);
    convA<<<(nD4 + 255)/256, 256>>>(y, yH, yL, nD4);
    gemm_mma<128><<<dim3(Vn/128, 16, 1), 256, SM128>>>(yH, yL, wfH, wfL,
        bf, nullptr, (float*)d_out, Dn, Dn, Dn, Vn, 1, 0,0,0,0,0,0, F_BIAS, 1.f);
}

// round 7
// speedup vs baseline: 1.4511x; 1.4511x over previous
#include <cuda_runtime.h>
#include <cuda_fp16.h>
#include <cstdint>

#define Bn 4
#define Tn 512
#define Dn 1024
#define Hn 16
#define HSn 64
#define Ln 8
#define Vn 32000
#define Mn (Bn*Tn)       // 2048
#define FFn (4*Dn)       // 4096
#define BHn (Bn*Hn)      // 64

// ---------------- fp32 scratch ----------------
__device__ float g_h[Mn*Dn];
__device__ float g_v[Mn*Dn];
__device__ float g_s[(size_t)BHn*Tn*Tn];

// ---------------- fp16 planes ----------------
__device__ __half g_yH[Mn*Dn],  g_yL[Mn*Dn];
__device__ __half g_qH[Mn*Dn],  g_qL[Mn*Dn];
__device__ __half g_kS[Mn*Dn];
__device__ __half g_vtS[Mn*Dn];
__device__ __half g_oH[Mn*Dn],  g_oL[Mn*Dn];
__device__ __half g_aH[Mn*FFn], g_aL[Mn*FFn];
__device__ __half g_sH[(size_t)BHn*Tn*Tn], g_sL[(size_t)BHn*Tn*Tn];

// ---------------- fp16 weights (transposed [N,K], single plane) -----------
__device__ __half g_wqS[Ln*Dn*Dn];
__device__ __half g_wkS[Ln*Dn*Dn];
__device__ __half g_wvS[Ln*Dn*Dn];
__device__ __half g_woS[Ln*Dn*Dn];
__device__ __half g_w1S[Ln*Dn*FFn];
__device__ __half g_w2S[Ln*Dn*FFn];
__device__ __half g_wfS[(size_t)Dn*Vn];

// ==================== helpers ====================
__device__ __forceinline__ uint32_t smem_u32(const void* p){
    uint32_t a;
    asm("{ .reg .u64 t; cvta.to.shared.u64 t, %1; cvt.u32.u64 %0, t; }" : "=r"(a) : "l"(p));
    return a;
}
#define CP16(dst, src) \
    asm volatile("cp.async.cg.shared.global [%0], [%1], 16;" :: "r"(dst), "l"(src))
#define CP_COMMIT() asm volatile("cp.async.commit_group;" ::: "memory")
#define CP_WAIT1() asm volatile("cp.async.wait_group 1;" ::: "memory")
#define CP_WAIT0() asm volatile("cp.async.wait_group 0;" ::: "memory")

#define LDSM4(r0,r1,r2,r3,addr) \
    asm volatile("ldmatrix.sync.aligned.m8n8.x4.shared.b16 {%0,%1,%2,%3}, [%4];" \
        : "=r"(r0),"=r"(r1),"=r"(r2),"=r"(r3) : "r"(addr))

#define MMA16816(d, a, b) \
    asm volatile("mma.sync.aligned.m16n8k16.row.col.f32.f16.f16.f32 " \
        "{%0,%1,%2,%3}, {%4,%5,%6,%7}, {%8,%9}, {%0,%1,%2,%3};" \
        : "+f"((d)[0]),"+f"((d)[1]),"+f"((d)[2]),"+f"((d)[3]) \
        : "r"((a)[0]),"r"((a)[1]),"r"((a)[2]),"r"((a)[3]), "r"((b)[0]),"r"((b)[1]))

// ==================== reductions ====================
__device__ __forceinline__ float warpSum(float v){
#pragma unroll
    for (int o = 16; o > 0; o >>= 1) v += __shfl_down_sync(0xffffffffu, v, o);
    return v;
}
__device__ __forceinline__ float warpMax(float v){
#pragma unroll
    for (int o = 16; o > 0; o >>= 1) v = fmaxf(v, __shfl_down_sync(0xffffffffu, v, o));
    return v;
}
__device__ __forceinline__ float blockSum(float v, float* sh){
    int lane = threadIdx.x & 31, w = threadIdx.x >> 5;
    v = warpSum(v);
    __syncthreads();
    if (lane == 0) sh[w] = v;
    __syncthreads();
    int nw = blockDim.x >> 5;
    v = (threadIdx.x < (unsigned)nw) ? sh[threadIdx.x] : 0.f;
    if (w == 0) v = warpSum(v);
    if (threadIdx.x == 0) sh[0] = v;
    __syncthreads();
    return sh[0];
}
__device__ __forceinline__ float blockMax(float v, float* sh){
    int lane = threadIdx.x & 31, w = threadIdx.x >> 5;
    v = warpMax(v);
    __syncthreads();
    if (lane == 0) sh[w] = v;
    __syncthreads();
    int nw = blockDim.x >> 5;
    v = (threadIdx.x < (unsigned)nw) ? sh[threadIdx.x] : -3.0e38f;
    if (w == 0) v = warpMax(v);
    if (threadIdx.x == 0) sh[0] = v;
    __syncthreads();
    return sh[0];
}

// ==================== small kernels ====================
__global__ void embed_k(const int* __restrict__ x, const float* __restrict__ ce,
                        const float* __restrict__ pe){
    int idx = blockIdx.x * blockDim.x + threadIdx.x;
    int d  = idx & (Dn - 1);
    int mt = idx >> 10;
    int t  = mt & (Tn - 1);
    g_h[idx] = ce[(size_t)x[mt] * Dn + d] + pe[t * Dn + d];
}

// LayerNorm fused with fp16 hi/lo plane output
__global__ __launch_bounds__(256) void ln_k(const float* __restrict__ in,
                                            __half* __restrict__ outH,
                                            __half* __restrict__ outL,
                                            const float* __restrict__ gs,
                                            const float* __restrict__ gb){
    __shared__ float sh[32];
    int row = blockIdx.x;
    const float* xr = in + (size_t)row * Dn;
    float s = 0.f, sq = 0.f;
    for (int i = threadIdx.x; i < Dn; i += 256){ float v = xr[i]; s += v; sq += v * v; }
    s  = blockSum(s, sh);
    sq = blockSum(sq, sh);
    float mean = s * (1.f / Dn);
    float var  = sq * (1.f / Dn) - mean * mean;
    float r = rsqrtf(var + 1e-5f);
    __half* oh = outH + (size_t)row * Dn;
    __half* ol = outL + (size_t)row * Dn;
    for (int i = threadIdx.x; i < Dn; i += 256){
        float v = (xr[i] - mean) * r * gs[i] + gb[i];
        __half h = __float2half_rn(v);
        oh[i] = h;
        ol[i] = __float2half_rn(v - __half2float(h));
    }
}

// causal softmax fused with fp16 hi/lo plane output (+ zero fill)
__global__ __launch_bounds__(128) void softmax_k(){
    __shared__ float sh[32];
    int row = blockIdx.x;           // 0 .. BHn*Tn-1
    int i = row & (Tn - 1);
    float* sr = g_s + (size_t)row * Tn;
    __half* ph = g_sH + (size_t)row * Tn;
    __half* pl = g_sL + (size_t)row * Tn;
    float mx = -3.0e38f;
    for (int j = threadIdx.x; j <= i; j += 128) mx = fmaxf(mx, sr[j]);
    mx = blockMax(mx, sh);
    float sum = 0.f;
    for (int j = threadIdx.x; j <= i; j += 128){
        float e = expf(sr[j] - mx);
        sr[j] = e;
        sum += e;
    }
    sum = blockSum(sum, sh);
    float inv = 1.f / sum;
    for (int j = threadIdx.x; j <= i; j += 128){
        float p = sr[j] * inv;
        __half h = __float2half_rn(p);
        ph[j] = h;
        pl[j] = __float2half_rn(p - __half2float(h));
    }
    __half z = __float2half_rn(0.f);
    for (int j = i + 1 + threadIdx.x; j < Tn; j += 128){ ph[j] = z; pl[j] = z; }
}

// transpose + convert: in [R,C] fp32 -> out [C,R] fp16 single plane
__global__ __launch_bounds__(256) void convTh(const float* __restrict__ in,
                                              __half* __restrict__ os,
                                              int ldin, int ldout, int zH,
                                              long long sIb, long long sIh,
                                              long long sOb, long long sOh){
    __shared__ float t[32][33];
    int z = blockIdx.z, bz = z / zH, hz = z % zH;
    const float* pin = in + bz * sIb + hz * sIh;
    __half* pos = os + bz * sOb + hz * sOh;
    int cb = blockIdx.x * 32, rb = blockIdx.y * 32;
    int tx = threadIdx.x, ty = threadIdx.y;  // (32, 8)
#pragma unroll
    for (int i = 0; i < 4; i++)
        t[ty + 8*i][tx] = pin[(size_t)(rb + ty + 8*i) * ldin + cb + tx];
    __syncthreads();
#pragma unroll
    for (int i = 0; i < 4; i++){
        float v = t[tx][ty + 8*i];
        pos[(size_t)(cb + ty + 8*i) * ldout + rb + tx] = __float2half_rn(v);
    }
}

// ==================== 2-pass split-fp16 mma.sync GEMM ====================
// C[z][M,N] = (Ah+Al)[M,K] @ B[N,K]^T  (2 passes: AhB + AlB), fp32 accum.
#define F_BIAS   1
#define F_RES    2
#define F_RELU   4
#define F_SCALE  8
#define F_CAUSAL 16
#define F_KCAUS  32

template<int BN>
__global__ __launch_bounds__(256) void gemm_mma(
    const __half* __restrict__ Ah, const __half* __restrict__ Al,
    const __half* __restrict__ Bs,
    const float* __restrict__ bias, const float* __restrict__ res,
    float* __restrict__ Cf, __half* __restrict__ Ch, __half* __restrict__ Cl,
    int K, int lda, int ldb, int ldc,
    int zH, long long sAb, long long sAh, long long sBb, long long sBh,
    long long sCb, long long sChh,
    int flags, float scale)
{
    constexpr int BM = 128, BK = 32;
    constexpr int SA = 40;                 // padded smem row (fp16 elems) -> 80B
    constexpr int ABYTES = BM * SA * 2;    // 10240
    constexpr int BBYTES = BN * SA * 2;
    constexpr int STAGE = 2 * ABYTES + BBYTES;
    constexpr int WN = BN / 2;
    constexpr int NA = WN / 8;             // n atoms per warp

    const int bm = blockIdx.y * BM, bn = blockIdx.x * BN;
    if ((flags & F_CAUSAL) && bn >= bm + BM) return;

    extern __shared__ char sm[];
    const uint32_t smb = smem_u32(sm);

    const int tid = threadIdx.x, lane = tid & 31, wid = tid >> 5;
    const int wm = wid & 3, wn = wid >> 2;

    const int z = blockIdx.z;
    const int bz = z / zH, hz = z % zH;
    const __half* pAh = Ah + bz * sAb + hz * sAh;
    const __half* pAl = Al + bz * sAb + hz * sAh;
    const __half* pB  = Bs + bz * sBb + hz * sBh;
    float* pCf = Cf ? (Cf + bz * sCb + hz * sChh) : nullptr;
    __half* pCh = Ch ? (Ch + bz * sCb + hz * sChh) : nullptr;
    __half* pCl = Cl ? (Cl + bz * sCb + hz * sChh) : nullptr;
    const float* pres = res ? (res + bz * sCb + hz * sChh) : nullptr;

    int nKB = K >> 5;
    if (flags & F_KCAUS){
        int lim = (bm + BM) >> 5;
        if (lim < nKB) nKB = lim;
    }

    auto loadStage = [&](int kb, int s){
        const int k0 = kb * BK;
        const uint32_t stg = smb + s * STAGE;
#pragma unroll
        for (int i = 0; i < 2; i++){             // A: 512 chunks/plane
            int idx = i * 256 + tid;
            int r = idx >> 2, c = idx & 3;
            uint32_t dst = stg + r * 80 + c * 16;
            CP16(dst,          pAh + (size_t)(bm + r) * lda + k0 + c * 8);
            CP16(dst + ABYTES, pAl + (size_t)(bm + r) * lda + k0 + c * 8);
        }
#pragma unroll
        for (int i = 0; i < BN / 64; i++){       // B single plane
            int idx = i * 256 + tid;
            int r = idx >> 2, c = idx & 3;
            uint32_t dst = stg + 2 * ABYTES + r * 80 + c * 16;
            CP16(dst, pB + (size_t)(bn + r) * ldb + k0 + c * 8);
        }
        CP_COMMIT();
    };

    float acc[2][NA][4];
#pragma unroll
    for (int i = 0; i < 2; i++)
#pragma unroll
        for (int j = 0; j < NA; j++)
#pragma unroll
            for (int q = 0; q < 4; q++) acc[i][j][q] = 0.f;

    loadStage(0, 0);

    for (int kb = 0; kb < nKB; kb++){
        const int s = kb & 1;
        if (kb + 1 < nKB){ loadStage(kb + 1, s ^ 1); CP_WAIT1(); }
        else             { CP_WAIT0(); }
        __syncthreads();

        const uint32_t stg = smb + s * STAGE;
#pragma unroll
        for (int ks = 0; ks < 2; ks++){
            const int kc = ks * 16;
            uint32_t a_h[2][4], a_l[2][4];
#pragma unroll
            for (int mi = 0; mi < 2; mi++){
                int row = wm * 32 + mi * 16 + (lane & 15);
                int colb = (kc + ((lane >> 4) << 3)) * 2;
                uint32_t ad = stg + row * 80 + colb;
                LDSM4(a_h[mi][0], a_h[mi][1], a_h[mi][2], a_h[mi][3], ad);
                LDSM4(a_l[mi][0], a_l[mi][1], a_l[mi][2], a_l[mi][3], ad + ABYTES);
            }
            uint32_t b_s[NA][2];
#pragma unroll
            for (int p = 0; p < NA / 2; p++){
                int rowb = wn * WN + p * 16 + (lane & 7) + ((lane >> 4) << 3);
                int colb = (kc + (((lane >> 3) & 1) << 3)) * 2;
                uint32_t ad = stg + 2 * ABYTES + rowb * 80 + colb;
                uint32_t r0, r1, r2, r3;
                LDSM4(r0, r1, r2, r3, ad);
                b_s[2*p][0] = r0; b_s[2*p][1] = r1;
                b_s[2*p+1][0] = r2; b_s[2*p+1][1] = r3;
            }
#pragma unroll
            for (int mi = 0; mi < 2; mi++)
#pragma unroll
                for (int ni = 0; ni < NA; ni++){
                    MMA16816(acc[mi][ni], a_h[mi], b_s[ni]);
                    MMA16816(acc[mi][ni], a_l[mi], b_s[ni]);
                }
        }
        __syncthreads();
    }

    // epilogue
#pragma unroll
    for (int mi = 0; mi < 2; mi++){
#pragma unroll
        for (int ni = 0; ni < NA; ni++){
            int r0 = bm + wm * 32 + mi * 16 + (lane >> 2);
            int c0 = bn + wn * WN + ni * 8 + (lane & 3) * 2;
#pragma unroll
            for (int half = 0; half < 2; half++){
                int r = r0 + half * 8;
                float vx = acc[mi][ni][half * 2 + 0];
                float vy = acc[mi][ni][half * 2 + 1];
                if (flags & F_SCALE){ vx *= scale; vy *= scale; }
                if (flags & F_BIAS){ vx += bias[c0]; vy += bias[c0 + 1]; }
                if (flags & F_RES){
                    const float* rp = pres + (size_t)r * ldc + c0;
                    vx += rp[0]; vy += rp[1];
                }
                if (flags & F_RELU){ vx = fmaxf(vx, 0.f); vy = fmaxf(vy, 0.f); }
                if (flags & F_CAUSAL){
                    if (c0 > r)     vx = -3.0e38f;
                    if (c0 + 1 > r) vy = -3.0e38f;
                }
                if (pCf){
                    float2 o2; o2.x = vx; o2.y = vy;
                    *(float2*)(pCf + (size_t)r * ldc + c0) = o2;
                }
                if (pCh){
                    __half hx = __float2half_rn(vx);
                    __half hy = __float2half_rn(vy);
                    *(__half2*)(pCh + (size_t)r * ldc + c0) = __half2(hx, hy);
                    if (pCl){
                        __half lx = __float2half_rn(vx - __half2float(hx));
                        __half ly = __float2half_rn(vy - __half2float(hy));
                        *(__half2*)(pCl + (size_t)r * ldc + c0) = __half2(lx, ly);
                    }
                }
            }
        }
    }
}

// ==================== host orchestration ====================
extern "C" void kernel_launch(void* const* d_in, const int* in_sizes, int n_in,
                              void* d_out, int out_size){
    (void)in_sizes; (void)n_in; (void)out_size;
    const int*   x     = (const int*)  d_in[0];
    const float* ce    = (const float*)d_in[1];
    const float* pe    = (const float*)d_in[2];
    const float* ln1_s = (const float*)d_in[5];
    const float* ln1_b = (const float*)d_in[6];
    const float* wq    = (const float*)d_in[7];
    const float* wk    = (const float*)d_in[8];
    const float* wv    = (const float*)d_in[9];
    const float* wo    = (const float*)d_in[10];
    const float* bo    = (const float*)d_in[11];
    const float* ln2_s = (const float*)d_in[12];
    const float* ln2_b = (const float*)d_in[13];
    const float* w1    = (const float*)d_in[14];
    const float* b1    = (const float*)d_in[15];
    const float* w2    = (const float*)d_in[16];
    const float* b2    = (const float*)d_in[17];
    const float* lnf_s = (const float*)d_in[18];
    const float* lnf_b = (const float*)d_in[19];
    const float* wf    = (const float*)d_in[20];
    const float* bf    = (const float*)d_in[21];

    float *h, *v, *s;
    cudaGetSymbolAddress((void**)&h, g_h);
    cudaGetSymbolAddress((void**)&v, g_v);
    cudaGetSymbolAddress((void**)&s, g_s);

    __half *yH,*yL,*qH,*qL,*kS,*vtS,*oH,*oL,*aH,*aL,*sH,*sL;
    cudaGetSymbolAddress((void**)&yH, g_yH);  cudaGetSymbolAddress((void**)&yL, g_yL);
    cudaGetSymbolAddress((void**)&qH, g_qH);  cudaGetSymbolAddress((void**)&qL, g_qL);
    cudaGetSymbolAddress((void**)&kS, g_kS);
    cudaGetSymbolAddress((void**)&vtS, g_vtS);
    cudaGetSymbolAddress((void**)&oH, g_oH);  cudaGetSymbolAddress((void**)&oL, g_oL);
    cudaGetSymbolAddress((void**)&aH, g_aH);  cudaGetSymbolAddress((void**)&aL, g_aL);
    cudaGetSymbolAddress((void**)&sH, g_sH);  cudaGetSymbolAddress((void**)&sL, g_sL);

    __half *wqS,*wkS,*wvS,*woS,*w1S,*w2S,*wfS;
    cudaGetSymbolAddress((void**)&wqS, g_wqS);
    cudaGetSymbolAddress((void**)&wkS, g_wkS);
    cudaGetSymbolAddress((void**)&wvS, g_wvS);
    cudaGetSymbolAddress((void**)&woS, g_woS);
    cudaGetSymbolAddress((void**)&w1S, g_w1S);
    cudaGetSymbolAddress((void**)&w2S, g_w2S);
    cudaGetSymbolAddress((void**)&wfS, g_wfS);

    // dyn smem: BN=128 -> 2*(2*10240+10240)=61440 ; BN=64 -> 2*(20480+5120)=51200
    const int SM128 = 61440, SM64 = 51200;
    cudaFuncSetAttribute(gemm_mma<128>, cudaFuncAttributeMaxDynamicSharedMemorySize, SM128);
    cudaFuncSetAttribute(gemm_mma<64>,  cudaFuncAttributeMaxDynamicSharedMemorySize, SM64);

    dim3 cb(32, 8);
    const long long DD = (long long)Dn * Dn;
    const long long DF = (long long)Dn * FFn;
    convTh<<<dim3(Dn/32, Dn/32, Ln), cb>>>(wq, wqS, Dn, Dn, 1, DD, 0, DD, 0);
    convTh<<<dim3(Dn/32, Dn/32, Ln), cb>>>(wk, wkS, Dn, Dn, 1, DD, 0, DD, 0);
    convTh<<<dim3(Dn/32, Dn/32, Ln), cb>>>(wv, wvS, Dn, Dn, 1, DD, 0, DD, 0);
    convTh<<<dim3(Dn/32, Dn/32, Ln), cb>>>(wo, woS, Dn, Dn, 1, DD, 0, DD, 0);
    convTh<<<dim3(FFn/32, Dn/32, Ln), cb>>>(w1, w1S, FFn, Dn, 1, DF, 0, DF, 0);
    convTh<<<dim3(Dn/32, FFn/32, Ln), cb>>>(w2, w2S, Dn, FFn, 1, DF, 0, DF, 0);
    convTh<<<dim3(Vn/32, Dn/32, 1),  cb>>>(wf, wfS, Vn, Dn, 1, 0, 0, 0, 0);

    embed_k<<<(Mn * Dn) / 256, 256>>>(x, ce, pe);

    const long long SAB = (long long)Tn * Dn;   // per-batch stride in q/k/v/o
    const long long SS1 = (long long)Tn * Tn;   // per-bh stride in s
    const long long SVT = (long long)HSn * Tn;  // per-bh stride in vt

    for (int l = 0; l < Ln; l++){
        ln_k<<<Mn, 256>>>(h, yH, yL, ln1_s + l*Dn, ln1_b + l*Dn);

        // QKV: q -> hi/lo planes; k -> single plane; v -> fp32 (for transpose)
        gemm_mma<128><<<dim3(8,16,1), 256, SM128>>>(yH, yL, wqS + (size_t)l*DD,
            nullptr, nullptr, nullptr, qH, qL, Dn, Dn, Dn, Dn, 1, 0,0,0,0,0,0, 0, 1.f);
        gemm_mma<128><<<dim3(8,16,1), 256, SM128>>>(yH, yL, wkS + (size_t)l*DD,
            nullptr, nullptr, nullptr, kS, nullptr, Dn, Dn, Dn, Dn, 1, 0,0,0,0,0,0, 0, 1.f);
        gemm_mma<128><<<dim3(8,16,1), 256, SM128>>>(yH, yL, wvS + (size_t)l*DD,
            nullptr, nullptr, v, nullptr, nullptr, Dn, Dn, Dn, Dn, 1, 0,0,0,0,0,0, 0, 1.f);

        convTh<<<dim3(HSn/32, Tn/32, BHn), cb>>>(v, vtS, Dn, Tn, Hn,
            SAB, (long long)HSn, (long long)Hn*SVT, SVT);

        // scores: S[bh] = scale * Q K^T (causal) -> fp32
        gemm_mma<128><<<dim3(4,4,BHn), 256, SM128>>>(qH, qL, kS, nullptr, nullptr,
            s, nullptr, nullptr,
            HSn, Dn, Dn, Tn, Hn, SAB, (long long)HSn, SAB, (long long)HSn,
            (long long)Hn*SS1, SS1, F_SCALE | F_CAUSAL, 0.125f);
        softmax_k<<<BHn*Tn, 128>>>();

        // O[bh] = S @ V  (K truncated causally) -> hi/lo planes
        gemm_mma<64><<<dim3(1,4,BHn), 256, SM64>>>(sH, sL, vtS, nullptr, nullptr,
            nullptr, oH, oL,
            Tn, Tn, Tn, Dn, Hn, (long long)Hn*SS1, SS1, (long long)Hn*SVT, SVT,
            SAB, (long long)HSn, F_KCAUS, 1.f);

        gemm_mma<128><<<dim3(8,16,1), 256, SM128>>>(oH, oL, woS + (size_t)l*DD,
            bo + l*Dn, h, h, nullptr, nullptr, Dn, Dn, Dn, Dn, 1, 0,0,0,0,0,0,
            F_BIAS | F_RES, 1.f);

        ln_k<<<Mn, 256>>>(h, yH, yL, ln2_s + l*Dn, ln2_b + l*Dn);
        gemm_mma<128><<<dim3(32,16,1), 256, SM128>>>(yH, yL, w1S + (size_t)l*DF,
            b1 + l*FFn, nullptr, nullptr, aH, aL, Dn, Dn, Dn, FFn, 1, 0,0,0,0,0,0,
            F_BIAS | F_RELU, 1.f);
        gemm_mma<128><<<dim3(8,16,1), 256, SM128>>>(aH, aL, w2S + (size_t)l*DF,
            b2 + l*Dn, h, h, nullptr, nullptr, FFn, FFn, FFn, Dn, 1, 0,0,0,0,0,0,
            F_BIAS | F_RES, 1.f);
    }

    ln_k<<<Mn, 256>>>(h, yH, yL, lnf_s, lnf_b);
    gemm_mma<128><<<dim3(Vn/128, 16, 1), 256, SM128>>>(yH, yL, wfS,
        bf, nullptr, (float*)d_out, nullptr, nullptr, Dn, Dn, Dn, Vn, 1, 0,0,0,0,0,0,
        F_BIAS, 1.f);
}

// round 8
// speedup vs baseline: 1.5498x; 1.0680x over previous
#include <cuda_runtime.h>
#include <cuda_fp16.h>
#include <cstdint>

#define Bn 4
#define Tn 512
#define Dn 1024
#define Hn 16
#define HSn 64
#define Ln 8
#define Vn 32000
#define Mn (Bn*Tn)       // 2048
#define FFn (4*Dn)       // 4096
#define BHn (Bn*Hn)      // 64

// ---------------- fp32 scratch ----------------
__device__ float g_h[Mn*Dn];
__device__ float g_v[Mn*Dn];
__device__ float g_s[(size_t)BHn*Tn*Tn];

// ---------------- fp16 planes ----------------
__device__ __half g_yH[Mn*Dn],  g_yL[Mn*Dn];
__device__ __half g_qH[Mn*Dn],  g_qL[Mn*Dn];
__device__ __half g_kS[Mn*Dn];
__device__ __half g_vtS[Mn*Dn];
__device__ __half g_oH[Mn*Dn],  g_oL[Mn*Dn];
__device__ __half g_aH[Mn*FFn], g_aL[Mn*FFn];
__device__ __half g_sH[(size_t)BHn*Tn*Tn], g_sL[(size_t)BHn*Tn*Tn];

// ---------------- fp16 weights (transposed [N,K], single plane) -----------
__device__ __half g_wqkvS[(size_t)Ln*3*Dn*Dn];   // packed [3072,1024] per layer
__device__ __half g_woS[Ln*Dn*Dn];
__device__ __half g_w1S[Ln*Dn*FFn];
__device__ __half g_w2S[Ln*Dn*FFn];
__device__ __half g_wfS[(size_t)Dn*Vn];

// ==================== helpers ====================
__device__ __forceinline__ uint32_t smem_u32(const void* p){
    uint32_t a;
    asm("{ .reg .u64 t; cvta.to.shared.u64 t, %1; cvt.u32.u64 %0, t; }" : "=r"(a) : "l"(p));
    return a;
}
#define CP16(dst, src) \
    asm volatile("cp.async.cg.shared.global [%0], [%1], 16;" :: "r"(dst), "l"(src))
#define CP_COMMIT() asm volatile("cp.async.commit_group;" ::: "memory")
#define CP_WAIT1() asm volatile("cp.async.wait_group 1;" ::: "memory")
#define CP_WAIT0() asm volatile("cp.async.wait_group 0;" ::: "memory")

#define LDSM4(r0,r1,r2,r3,addr) \
    asm volatile("ldmatrix.sync.aligned.m8n8.x4.shared.b16 {%0,%1,%2,%3}, [%4];" \
        : "=r"(r0),"=r"(r1),"=r"(r2),"=r"(r3) : "r"(addr))

#define MMA16816(d, a, b) \
    asm volatile("mma.sync.aligned.m16n8k16.row.col.f32.f16.f16.f32 " \
        "{%0,%1,%2,%3}, {%4,%5,%6,%7}, {%8,%9}, {%0,%1,%2,%3};" \
        : "+f"((d)[0]),"+f"((d)[1]),"+f"((d)[2]),"+f"((d)[3]) \
        : "r"((a)[0]),"r"((a)[1]),"r"((a)[2]),"r"((a)[3]), "r"((b)[0]),"r"((b)[1]))

// ==================== reductions ====================
__device__ __forceinline__ float warpSum(float v){
#pragma unroll
    for (int o = 16; o > 0; o >>= 1) v += __shfl_down_sync(0xffffffffu, v, o);
    return v;
}
__device__ __forceinline__ float warpMax(float v){
#pragma unroll
    for (int o = 16; o > 0; o >>= 1) v = fmaxf(v, __shfl_down_sync(0xffffffffu, v, o));
    return v;
}
__device__ __forceinline__ float blockSum(float v, float* sh){
    int lane = threadIdx.x & 31, w = threadIdx.x >> 5;
    v = warpSum(v);
    __syncthreads();
    if (lane == 0) sh[w] = v;
    __syncthreads();
    int nw = blockDim.x >> 5;
    v = (threadIdx.x < (unsigned)nw) ? sh[threadIdx.x] : 0.f;
    if (w == 0) v = warpSum(v);
    if (threadIdx.x == 0) sh[0] = v;
    __syncthreads();
    return sh[0];
}
__device__ __forceinline__ float blockMax(float v, float* sh){
    int lane = threadIdx.x & 31, w = threadIdx.x >> 5;
    v = warpMax(v);
    __syncthreads();
    if (lane == 0) sh[w] = v;
    __syncthreads();
    int nw = blockDim.x >> 5;
    v = (threadIdx.x < (unsigned)nw) ? sh[threadIdx.x] : -3.0e38f;
    if (w == 0) v = warpMax(v);
    if (threadIdx.x == 0) sh[0] = v;
    __syncthreads();
    return sh[0];
}

// ==================== small kernels ====================
__global__ void embed_k(const int* __restrict__ x, const float* __restrict__ ce,
                        const float* __restrict__ pe){
    int idx = blockIdx.x * blockDim.x + threadIdx.x;
    int d  = idx & (Dn - 1);
    int mt = idx >> 10;
    int t  = mt & (Tn - 1);
    g_h[idx] = ce[(size_t)x[mt] * Dn + d] + pe[t * Dn + d];
}

// LayerNorm fused with fp16 hi/lo plane output (register-cached row)
__global__ __launch_bounds__(256) void ln_k(const float* __restrict__ in,
                                            __half* __restrict__ outH,
                                            __half* __restrict__ outL,
                                            const float* __restrict__ gs,
                                            const float* __restrict__ gb){
    __shared__ float sh[32];
    int row = blockIdx.x;
    const float4* xr = (const float4*)(in + (size_t)row * Dn);
    float4 vv = xr[threadIdx.x];          // 256 threads x 4 = 1024
    float s  = vv.x + vv.y + vv.z + vv.w;
    float sq = vv.x*vv.x + vv.y*vv.y + vv.z*vv.z + vv.w*vv.w;
    s  = blockSum(s, sh);
    sq = blockSum(sq, sh);
    float mean = s * (1.f / Dn);
    float var  = sq * (1.f / Dn) - mean * mean;
    float r = rsqrtf(var + 1e-5f);
    int i0 = threadIdx.x * 4;
    float o[4];
    o[0] = (vv.x - mean) * r * gs[i0+0] + gb[i0+0];
    o[1] = (vv.y - mean) * r * gs[i0+1] + gb[i0+1];
    o[2] = (vv.z - mean) * r * gs[i0+2] + gb[i0+2];
    o[3] = (vv.w - mean) * r * gs[i0+3] + gb[i0+3];
    __half2 h2[2], l2[2];
#pragma unroll
    for (int p = 0; p < 2; p++){
        __half hx = __float2half_rn(o[2*p]);
        __half hy = __float2half_rn(o[2*p+1]);
        h2[p] = __half2(hx, hy);
        l2[p] = __half2(__float2half_rn(o[2*p]   - __half2float(hx)),
                        __float2half_rn(o[2*p+1] - __half2float(hy)));
    }
    *(uint2*)(outH + (size_t)row * Dn + i0) = *(uint2*)h2;
    *(uint2*)(outL + (size_t)row * Dn + i0) = *(uint2*)l2;
}

// causal softmax, register-cached, fp16 hi/lo planes out, zero fill to AV tile edge
__global__ __launch_bounds__(128) void softmax_k(){
    __shared__ float sh[32];
    int row = blockIdx.x;           // 0 .. BHn*Tn-1
    int i = row & (Tn - 1);
    int zend = ((i >> 7) + 1) << 7; // AV reads cols < zend only
    const float* sr = g_s + (size_t)row * Tn;
    __half* ph = g_sH + (size_t)row * Tn;
    __half* pl = g_sL + (size_t)row * Tn;
    float vals[4];
    float mx = -3.0e38f;
#pragma unroll
    for (int p = 0; p < 4; p++){
        int j = threadIdx.x + p * 128;
        vals[p] = (j <= i) ? sr[j] : -3.0e38f;
        mx = fmaxf(mx, vals[p]);
    }
    mx = blockMax(mx, sh);
    float sum = 0.f;
#pragma unroll
    for (int p = 0; p < 4; p++){
        int j = threadIdx.x + p * 128;
        float e = (j <= i) ? expf(vals[p] - mx) : 0.f;
        vals[p] = e;
        sum += e;
    }
    sum = blockSum(sum, sh);
    float inv = 1.f / sum;
#pragma unroll
    for (int p = 0; p < 4; p++){
        int j = threadIdx.x + p * 128;
        if (j < zend){
            float pr = vals[p] * inv;
            __half h = __float2half_rn(pr);
            ph[j] = h;
            pl[j] = __float2half_rn(pr - __half2float(h));
        }
    }
}

// transpose + convert: in [R,C] fp32 -> out [C,R] fp16 single plane
__global__ __launch_bounds__(256) void convTh(const float* __restrict__ in,
                                              __half* __restrict__ os,
                                              int ldin, int ldout, int zH,
                                              long long sIb, long long sIh,
                                              long long sOb, long long sOh){
    __shared__ float t[32][33];
    int z = blockIdx.z, bz = z / zH, hz = z % zH;
    const float* pin = in + bz * sIb + hz * sIh;
    __half* pos = os + bz * sOb + hz * sOh;
    int cb = blockIdx.x * 32, rb = blockIdx.y * 32;
    int tx = threadIdx.x, ty = threadIdx.y;  // (32, 8)
#pragma unroll
    for (int i = 0; i < 4; i++)
        t[ty + 8*i][tx] = pin[(size_t)(rb + ty + 8*i) * ldin + cb + tx];
    __syncthreads();
#pragma unroll
    for (int i = 0; i < 4; i++){
        float v = t[tx][ty + 8*i];
        pos[(size_t)(cb + ty + 8*i) * ldout + rb + tx] = __float2half_rn(v);
    }
}

// ==================== 2-pass split-fp16 mma.sync GEMM (3-stage pipeline) ===
#define F_BIAS   1
#define F_RES    2
#define F_RELU   4
#define F_SCALE  8
#define F_CAUSAL 16
#define F_KCAUS  32
#define F_QKV    64

template<int BN>
__global__ __launch_bounds__(256) void gemm_mma(
    const __half* __restrict__ Ah, const __half* __restrict__ Al,
    const __half* __restrict__ Bs,
    const float* __restrict__ bias, const float* __restrict__ res,
    float* __restrict__ Cf, __half* __restrict__ Ch, __half* __restrict__ Cl,
    __half* __restrict__ C2,
    int K, int lda, int ldb, int ldc,
    int zH, long long sAb, long long sAh, long long sBb, long long sBh,
    long long sCb, long long sChh,
    int flags, float scale)
{
    constexpr int BM = 128, BK = 32;
    constexpr int ABYTES = BM * 40 * 2;    // 10240 (padded 80B rows)
    constexpr int BBYTES = BN * 40 * 2;
    constexpr int STAGE = 2 * ABYTES + BBYTES;
    constexpr int WN = BN / 2;
    constexpr int NA = WN / 8;

    const int bm = blockIdx.y * BM, bn = blockIdx.x * BN;
    if ((flags & F_CAUSAL) && bn >= bm + BM) return;

    extern __shared__ char sm[];
    const uint32_t smb = smem_u32(sm);

    const int tid = threadIdx.x, lane = tid & 31, wid = tid >> 5;
    const int wm = wid & 3, wn = wid >> 2;

    const int z = blockIdx.z;
    const int bz = z / zH, hz = z % zH;
    const __half* pAh = Ah + bz * sAb + hz * sAh;
    const __half* pAl = Al + bz * sAb + hz * sAh;
    const __half* pB  = Bs + bz * sBb + hz * sBh;
    float* pCf = Cf ? (Cf + bz * sCb + hz * sChh) : nullptr;
    __half* pCh = Ch ? (Ch + bz * sCb + hz * sChh) : nullptr;
    __half* pCl = Cl ? (Cl + bz * sCb + hz * sChh) : nullptr;
    const float* pres = res ? (res + bz * sCb + hz * sChh) : nullptr;

    int nKB = K >> 5;
    if (flags & F_KCAUS){
        int lim = (bm + BM) >> 5;
        if (lim < nKB) nKB = lim;
    }

    auto loadStage = [&](int kb, int s){
        const int k0 = kb * BK;
        const uint32_t stg = smb + s * STAGE;
#pragma unroll
        for (int i = 0; i < 2; i++){
            int idx = i * 256 + tid;
            int r = idx >> 2, c = idx & 3;
            uint32_t dst = stg + r * 80 + c * 16;
            CP16(dst,          pAh + (size_t)(bm + r) * lda + k0 + c * 8);
            CP16(dst + ABYTES, pAl + (size_t)(bm + r) * lda + k0 + c * 8);
        }
#pragma unroll
        for (int i = 0; i < BN / 64; i++){
            int idx = i * 256 + tid;
            int r = idx >> 2, c = idx & 3;
            uint32_t dst = stg + 2 * ABYTES + r * 80 + c * 16;
            CP16(dst, pB + (size_t)(bn + r) * ldb + k0 + c * 8);
        }
        CP_COMMIT();
    };

    float acc[2][NA][4];
#pragma unroll
    for (int i = 0; i < 2; i++)
#pragma unroll
        for (int j = 0; j < NA; j++)
#pragma unroll
            for (int q = 0; q < 4; q++) acc[i][j][q] = 0.f;

    loadStage(0, 0);
    loadStage(1, 1);

    for (int kb = 0; kb < nKB; kb++){
        if (kb == nKB - 1) CP_WAIT0(); else CP_WAIT1();
        __syncthreads();
        if (kb + 2 < nKB){
            int s2 = kb + 2; while (s2 >= 3) s2 -= 3;
            loadStage(kb + 2, s2);
        }
        int s = kb; while (s >= 3) s -= 3;
        const uint32_t stg = smb + s * STAGE;
#pragma unroll
        for (int ks = 0; ks < 2; ks++){
            const int kc = ks * 16;
            uint32_t a_h[2][4], a_l[2][4];
#pragma unroll
            for (int mi = 0; mi < 2; mi++){
                int row = wm * 32 + mi * 16 + (lane & 15);
                int colb = (kc + ((lane >> 4) << 3)) * 2;
                uint32_t ad = stg + row * 80 + colb;
                LDSM4(a_h[mi][0], a_h[mi][1], a_h[mi][2], a_h[mi][3], ad);
                LDSM4(a_l[mi][0], a_l[mi][1], a_l[mi][2], a_l[mi][3], ad + ABYTES);
            }
            uint32_t b_s[NA][2];
#pragma unroll
            for (int p = 0; p < NA / 2; p++){
                int rowb = wn * WN + p * 16 + (lane & 7) + ((lane >> 4) << 3);
                int colb = (kc + (((lane >> 3) & 1) << 3)) * 2;
                uint32_t ad = stg + 2 * ABYTES + rowb * 80 + colb;
                uint32_t r0, r1, r2, r3;
                LDSM4(r0, r1, r2, r3, ad);
                b_s[2*p][0] = r0; b_s[2*p][1] = r1;
                b_s[2*p+1][0] = r2; b_s[2*p+1][1] = r3;
            }
#pragma unroll
            for (int mi = 0; mi < 2; mi++)
#pragma unroll
                for (int ni = 0; ni < NA; ni++){
                    MMA16816(acc[mi][ni], a_h[mi], b_s[ni]);
                    MMA16816(acc[mi][ni], a_l[mi], b_s[ni]);
                }
        }
    }

    // epilogue
#pragma unroll
    for (int mi = 0; mi < 2; mi++){
#pragma unroll
        for (int ni = 0; ni < NA; ni++){
            int r0 = bm + wm * 32 + mi * 16 + (lane >> 2);
            int c0 = bn + wn * WN + ni * 8 + (lane & 3) * 2;
#pragma unroll
            for (int half = 0; half < 2; half++){
                int r = r0 + half * 8;
                float vx = acc[mi][ni][half * 2 + 0];
                float vy = acc[mi][ni][half * 2 + 1];
                if (flags & F_QKV){
                    int range = c0 >> 10, cc = c0 & 1023;
                    if (range == 0){
                        __half hx = __float2half_rn(vx), hy = __float2half_rn(vy);
                        *(__half2*)(pCh + (size_t)r * ldc + cc) = __half2(hx, hy);
                        *(__half2*)(pCl + (size_t)r * ldc + cc) =
                            __half2(__float2half_rn(vx - __half2float(hx)),
                                    __float2half_rn(vy - __half2float(hy)));
                    } else if (range == 1){
                        *(__half2*)(C2 + (size_t)r * ldc + cc) =
                            __half2(__float2half_rn(vx), __float2half_rn(vy));
                    } else {
                        float2 o2; o2.x = vx; o2.y = vy;
                        *(float2*)(pCf + (size_t)r * ldc + cc) = o2;
                    }
                    continue;
                }
                if (flags & F_SCALE){ vx *= scale; vy *= scale; }
                if (flags & F_BIAS){ vx += bias[c0]; vy += bias[c0 + 1]; }
                if (flags & F_RES){
                    const float* rp = pres + (size_t)r * ldc + c0;
                    vx += rp[0]; vy += rp[1];
                }
                if (flags & F_RELU){ vx = fmaxf(vx, 0.f); vy = fmaxf(vy, 0.f); }
                if (flags & F_CAUSAL){
                    if (c0 > r)     vx = -3.0e38f;
                    if (c0 + 1 > r) vy = -3.0e38f;
                }
                if (pCf){
                    float2 o2; o2.x = vx; o2.y = vy;
                    *(float2*)(pCf + (size_t)r * ldc + c0) = o2;
                }
                if (pCh){
                    __half hx = __float2half_rn(vx);
                    __half hy = __float2half_rn(vy);
                    *(__half2*)(pCh + (size_t)r * ldc + c0) = __half2(hx, hy);
                    if (pCl){
                        __half lx = __float2half_rn(vx - __half2float(hx));
                        __half ly = __float2half_rn(vy - __half2float(hy));
                        *(__half2*)(pCl + (size_t)r * ldc + c0) = __half2(lx, ly);
                    }
                }
            }
        }
    }
}

// ==================== host orchestration ====================
extern "C" void kernel_launch(void* const* d_in, const int* in_sizes, int n_in,
                              void* d_out, int out_size){
    (void)in_sizes; (void)n_in; (void)out_size;
    const int*   x     = (const int*)  d_in[0];
    const float* ce    = (const float*)d_in[1];
    const float* pe    = (const float*)d_in[2];
    const float* ln1_s = (const float*)d_in[5];
    const float* ln1_b = (const float*)d_in[6];
    const float* wq    = (const float*)d_in[7];
    const float* wk    = (const float*)d_in[8];
    const float* wv    = (const float*)d_in[9];
    const float* wo    = (const float*)d_in[10];
    const float* bo    = (const float*)d_in[11];
    const float* ln2_s = (const float*)d_in[12];
    const float* ln2_b = (const float*)d_in[13];
    const float* w1    = (const float*)d_in[14];
    const float* b1    = (const float*)d_in[15];
    const float* w2    = (const float*)d_in[16];
    const float* b2    = (const float*)d_in[17];
    const float* lnf_s = (const float*)d_in[18];
    const float* lnf_b = (const float*)d_in[19];
    const float* wf    = (const float*)d_in[20];
    const float* bf    = (const float*)d_in[21];

    float *h, *v, *s;
    cudaGetSymbolAddress((void**)&h, g_h);
    cudaGetSymbolAddress((void**)&v, g_v);
    cudaGetSymbolAddress((void**)&s, g_s);

    __half *yH,*yL,*qH,*qL,*kS,*vtS,*oH,*oL,*aH,*aL,*sH,*sL;
    cudaGetSymbolAddress((void**)&yH, g_yH);  cudaGetSymbolAddress((void**)&yL, g_yL);
    cudaGetSymbolAddress((void**)&qH, g_qH);  cudaGetSymbolAddress((void**)&qL, g_qL);
    cudaGetSymbolAddress((void**)&kS, g_kS);
    cudaGetSymbolAddress((void**)&vtS, g_vtS);
    cudaGetSymbolAddress((void**)&oH, g_oH);  cudaGetSymbolAddress((void**)&oL, g_oL);
    cudaGetSymbolAddress((void**)&aH, g_aH);  cudaGetSymbolAddress((void**)&aL, g_aL);
    cudaGetSymbolAddress((void**)&sH, g_sH);  cudaGetSymbolAddress((void**)&sL, g_sL);

    __half *wqkvS,*woS,*w1S,*w2S,*wfS;
    cudaGetSymbolAddress((void**)&wqkvS, g_wqkvS);
    cudaGetSymbolAddress((void**)&woS, g_woS);
    cudaGetSymbolAddress((void**)&w1S, g_w1S);
    cudaGetSymbolAddress((void**)&w2S, g_w2S);
    cudaGetSymbolAddress((void**)&wfS, g_wfS);

    // dyn smem: 3 stages; BN=128 -> 3*30720=92160 ; BN=64 -> 3*25600=76800
    const int SM128 = 92160, SM64 = 76800;
    cudaFuncSetAttribute(gemm_mma<128>, cudaFuncAttributeMaxDynamicSharedMemorySize, SM128);
    cudaFuncSetAttribute(gemm_mma<64>,  cudaFuncAttributeMaxDynamicSharedMemorySize, SM64);

    dim3 cb(32, 8);
    const long long DD = (long long)Dn * Dn;
    const long long DF = (long long)Dn * FFn;
    // packed QKV weights: rows [0,1024)=wq^T, [1024,2048)=wk^T, [2048,3072)=wv^T
    convTh<<<dim3(Dn/32, Dn/32, Ln), cb>>>(wq, wqkvS,          Dn, Dn, 1, DD, 0, 3*DD, 0);
    convTh<<<dim3(Dn/32, Dn/32, Ln), cb>>>(wk, wqkvS + DD,     Dn, Dn, 1, DD, 0, 3*DD, 0);
    convTh<<<dim3(Dn/32, Dn/32, Ln), cb>>>(wv, wqkvS + 2*DD,   Dn, Dn, 1, DD, 0, 3*DD, 0);
    convTh<<<dim3(Dn/32, Dn/32, Ln), cb>>>(wo, woS, Dn, Dn, 1, DD, 0, DD, 0);
    convTh<<<dim3(FFn/32, Dn/32, Ln), cb>>>(w1, w1S, FFn, Dn, 1, DF, 0, DF, 0);
    convTh<<<dim3(Dn/32, FFn/32, Ln), cb>>>(w2, w2S, Dn, FFn, 1, DF, 0, DF, 0);
    convTh<<<dim3(Vn/32, Dn/32, 1),  cb>>>(wf, wfS, Vn, Dn, 1, 0, 0, 0, 0);

    embed_k<<<(Mn * Dn) / 256, 256>>>(x, ce, pe);

    const long long SAB = (long long)Tn * Dn;   // per-batch stride in q/k/v/o
    const long long SS1 = (long long)Tn * Tn;   // per-bh stride in s
    const long long SVT = (long long)HSn * Tn;  // per-bh stride in vt

    for (int l = 0; l < Ln; l++){
        ln_k<<<Mn, 256>>>(h, yH, yL, ln1_s + l*Dn, ln1_b + l*Dn);

        // fused QKV: q -> hi/lo, k -> single, v -> fp32
        gemm_mma<128><<<dim3(24,16,1), 256, SM128>>>(yH, yL, wqkvS + (size_t)l*3*DD,
            nullptr, nullptr, v, qH, qL, kS, Dn, Dn, Dn, Dn, 1, 0,0,0,0,0,0,
            F_QKV, 1.f);

        convTh<<<dim3(HSn/32, Tn/32, BHn), cb>>>(v, vtS, Dn, Tn, Hn,
            SAB, (long long)HSn, (long long)Hn*SVT, SVT);

        // scores: S[bh] = scale * Q K^T (causal) -> fp32
        gemm_mma<128><<<dim3(4,4,BHn), 256, SM128>>>(qH, qL, kS, nullptr, nullptr,
            s, nullptr, nullptr, nullptr,
            HSn, Dn, Dn, Tn, Hn, SAB, (long long)HSn, SAB, (long long)HSn,
            (long long)Hn*SS1, SS1, F_SCALE | F_CAUSAL, 0.125f);
        softmax_k<<<BHn*Tn, 128>>>();

        // O[bh] = S @ V  (K truncated causally) -> hi/lo planes
        gemm_mma<64><<<dim3(1,4,BHn), 256, SM64>>>(sH, sL, vtS, nullptr, nullptr,
            nullptr, oH, oL, nullptr,
            Tn, Tn, Tn, Dn, Hn, (long long)Hn*SS1, SS1, (long long)Hn*SVT, SVT,
            SAB, (long long)HSn, F_KCAUS, 1.f);

        gemm_mma<128><<<dim3(8,16,1), 256, SM128>>>(oH, oL, woS + (size_t)l*DD,
            bo + l*Dn, h, h, nullptr, nullptr, nullptr, Dn, Dn, Dn, Dn, 1, 0,0,0,0,0,0,
            F_BIAS | F_RES, 1.f);

        ln_k<<<Mn, 256>>>(h, yH, yL, ln2_s + l*Dn, ln2_b + l*Dn);
        gemm_mma<128><<<dim3(32,16,1), 256, SM128>>>(yH, yL, w1S + (size_t)l*DF,
            b1 + l*FFn, nullptr, nullptr, aH, aL, nullptr, Dn, Dn, Dn, FFn, 1, 0,0,0,0,0,0,
            F_BIAS | F_RELU, 1.f);
        gemm_mma<128><<<dim3(8,16,1), 256, SM128>>>(aH, aL, w2S + (size_t)l*DF,
            b2 + l*Dn, h, h, nullptr, nullptr, nullptr, FFn, FFn, FFn, Dn, 1, 0,0,0,0,0,0,
            F_BIAS | F_RES, 1.f);
    }

    ln_k<<<Mn, 256>>>(h, yH, yL, lnf_s, lnf_b);
    gemm_mma<128><<<dim3(Vn/128, 16, 1), 256, SM128>>>(yH, yL, wfS,
        bf, nullptr, (float*)d_out, nullptr, nullptr, nullptr, Dn, Dn, Dn, Vn, 1,
        0,0,0,0,0,0, F_BIAS, 1.f);
}

// round 9
// speedup vs baseline: 1.5710x; 1.0137x over previous
#include <cuda_runtime.h>
#include <cuda_fp16.h>
#include <cstdint>

#define Bn 4
#define Tn 512
#define Dn 1024
#define Hn 16
#define HSn 64
#define Ln 8
#define Vn 32000
#define Mn (Bn*Tn)       // 2048
#define FFn (4*Dn)       // 4096
#define BHn (Bn*Hn)      // 64

// ---------------- fp32 scratch ----------------
__device__ float g_h[Mn*Dn];
__device__ float g_s[(size_t)BHn*Tn*Tn];

// ---------------- fp16 planes ----------------
__device__ __half g_yH[Mn*Dn],  g_yL[Mn*Dn];
__device__ __half g_qH[Mn*Dn],  g_qL[Mn*Dn];
__device__ __half g_kS[Mn*Dn];
__device__ __half g_vS[Mn*Dn];                    // natural [t, d] layout
__device__ __half g_oH[Mn*Dn],  g_oL[Mn*Dn];
__device__ __half g_aH[Mn*FFn], g_aL[Mn*FFn];
__device__ __half g_sH[(size_t)BHn*Tn*Tn], g_sL[(size_t)BHn*Tn*Tn];

// ---------------- fp16 weights (transposed [N,K], single plane) -----------
__device__ __half g_wqkvS[(size_t)Ln*3*Dn*Dn];   // packed [3072,1024] per layer
__device__ __half g_woS[Ln*Dn*Dn];
__device__ __half g_w1S[Ln*Dn*FFn];
__device__ __half g_w2S[Ln*Dn*FFn];
__device__ __half g_wfS[(size_t)Dn*Vn];

// ==================== helpers ====================
__device__ __forceinline__ uint32_t smem_u32(const void* p){
    uint32_t a;
    asm("{ .reg .u64 t; cvta.to.shared.u64 t, %1; cvt.u32.u64 %0, t; }" : "=r"(a) : "l"(p));
    return a;
}
#define CP16(dst, src) \
    asm volatile("cp.async.cg.shared.global [%0], [%1], 16;" :: "r"(dst), "l"(src))
#define CP_COMMIT() asm volatile("cp.async.commit_group;" ::: "memory")
#define CP_WAIT1() asm volatile("cp.async.wait_group 1;" ::: "memory")
#define CP_WAIT0() asm volatile("cp.async.wait_group 0;" ::: "memory")

#define LDSM4(r0,r1,r2,r3,addr) \
    asm volatile("ldmatrix.sync.aligned.m8n8.x4.shared.b16 {%0,%1,%2,%3}, [%4];" \
        : "=r"(r0),"=r"(r1),"=r"(r2),"=r"(r3) : "r"(addr))
#define LDSM4T(r0,r1,r2,r3,addr) \
    asm volatile("ldmatrix.sync.aligned.m8n8.x4.trans.shared.b16 {%0,%1,%2,%3}, [%4];" \
        : "=r"(r0),"=r"(r1),"=r"(r2),"=r"(r3) : "r"(addr))

#define MMA16816(d, a, b) \
    asm volatile("mma.sync.aligned.m16n8k16.row.col.f32.f16.f16.f32 " \
        "{%0,%1,%2,%3}, {%4,%5,%6,%7}, {%8,%9}, {%0,%1,%2,%3};" \
        : "+f"((d)[0]),"+f"((d)[1]),"+f"((d)[2]),"+f"((d)[3]) \
        : "r"((a)[0]),"r"((a)[1]),"r"((a)[2]),"r"((a)[3]), "r"((b)[0]),"r"((b)[1]))

// ==================== reductions ====================
__device__ __forceinline__ float warpSum(float v){
#pragma unroll
    for (int o = 16; o > 0; o >>= 1) v += __shfl_down_sync(0xffffffffu, v, o);
    return v;
}
__device__ __forceinline__ float warpMax(float v){
#pragma unroll
    for (int o = 16; o > 0; o >>= 1) v = fmaxf(v, __shfl_down_sync(0xffffffffu, v, o));
    return v;
}
__device__ __forceinline__ float blockSum(float v, float* sh){
    int lane = threadIdx.x & 31, w = threadIdx.x >> 5;
    v = warpSum(v);
    __syncthreads();
    if (lane == 0) sh[w] = v;
    __syncthreads();
    int nw = blockDim.x >> 5;
    v = (threadIdx.x < (unsigned)nw) ? sh[threadIdx.x] : 0.f;
    if (w == 0) v = warpSum(v);
    if (threadIdx.x == 0) sh[0] = v;
    __syncthreads();
    return sh[0];
}
__device__ __forceinline__ float blockMax(float v, float* sh){
    int lane = threadIdx.x & 31, w = threadIdx.x >> 5;
    v = warpMax(v);
    __syncthreads();
    if (lane == 0) sh[w] = v;
    __syncthreads();
    int nw = blockDim.x >> 5;
    v = (threadIdx.x < (unsigned)nw) ? sh[threadIdx.x] : -3.0e38f;
    if (w == 0) v = warpMax(v);
    if (threadIdx.x == 0) sh[0] = v;
    __syncthreads();
    return sh[0];
}

// ==================== small kernels ====================
__global__ void embed_k(const int* __restrict__ x, const float* __restrict__ ce,
                        const float* __restrict__ pe){
    int idx = blockIdx.x * blockDim.x + threadIdx.x;
    int d  = idx & (Dn - 1);
    int mt = idx >> 10;
    int t  = mt & (Tn - 1);
    g_h[idx] = ce[(size_t)x[mt] * Dn + d] + pe[t * Dn + d];
}

// LayerNorm fused with fp16 hi/lo plane output (register-cached row)
__global__ __launch_bounds__(256) void ln_k(const float* __restrict__ in,
                                            __half* __restrict__ outH,
                                            __half* __restrict__ outL,
                                            const float* __restrict__ gs,
                                            const float* __restrict__ gb){
    __shared__ float sh[32];
    int row = blockIdx.x;
    const float4* xr = (const float4*)(in + (size_t)row * Dn);
    float4 vv = xr[threadIdx.x];
    float s  = vv.x + vv.y + vv.z + vv.w;
    float sq = vv.x*vv.x + vv.y*vv.y + vv.z*vv.z + vv.w*vv.w;
    s  = blockSum(s, sh);
    sq = blockSum(sq, sh);
    float mean = s * (1.f / Dn);
    float var  = sq * (1.f / Dn) - mean * mean;
    float r = rsqrtf(var + 1e-5f);
    int i0 = threadIdx.x * 4;
    float o[4];
    o[0] = (vv.x - mean) * r * gs[i0+0] + gb[i0+0];
    o[1] = (vv.y - mean) * r * gs[i0+1] + gb[i0+1];
    o[2] = (vv.z - mean) * r * gs[i0+2] + gb[i0+2];
    o[3] = (vv.w - mean) * r * gs[i0+3] + gb[i0+3];
    __half2 h2[2], l2[2];
#pragma unroll
    for (int p = 0; p < 2; p++){
        __half hx = __float2half_rn(o[2*p]);
        __half hy = __float2half_rn(o[2*p+1]);
        h2[p] = __half2(hx, hy);
        l2[p] = __half2(__float2half_rn(o[2*p]   - __half2float(hx)),
                        __float2half_rn(o[2*p+1] - __half2float(hy)));
    }
    *(uint2*)(outH + (size_t)row * Dn + i0) = *(uint2*)h2;
    *(uint2*)(outL + (size_t)row * Dn + i0) = *(uint2*)l2;
}

// causal softmax, register-cached, fp16 hi/lo planes out, zero fill to AV tile edge
__global__ __launch_bounds__(128) void softmax_k(){
    __shared__ float sh[32];
    int row = blockIdx.x;           // 0 .. BHn*Tn-1
    int i = row & (Tn - 1);
    int zend = ((i >> 7) + 1) << 7; // AV reads cols < zend only
    const float* sr = g_s + (size_t)row * Tn;
    __half* ph = g_sH + (size_t)row * Tn;
    __half* pl = g_sL + (size_t)row * Tn;
    float vals[4];
    float mx = -3.0e38f;
#pragma unroll
    for (int p = 0; p < 4; p++){
        int j = threadIdx.x + p * 128;
        vals[p] = (j <= i) ? sr[j] : -3.0e38f;
        mx = fmaxf(mx, vals[p]);
    }
    mx = blockMax(mx, sh);
    float sum = 0.f;
#pragma unroll
    for (int p = 0; p < 4; p++){
        int j = threadIdx.x + p * 128;
        float e = (j <= i) ? expf(vals[p] - mx) : 0.f;
        vals[p] = e;
        sum += e;
    }
    sum = blockSum(sum, sh);
    float inv = 1.f / sum;
#pragma unroll
    for (int p = 0; p < 4; p++){
        int j = threadIdx.x + p * 128;
        if (j < zend){
            float pr = vals[p] * inv;
            __half h = __float2half_rn(pr);
            ph[j] = h;
            pl[j] = __float2half_rn(pr - __half2float(h));
        }
    }
}

// transpose + convert: in [R,C] fp32 -> out [C,R] fp16 single plane (weights)
__global__ __launch_bounds__(256) void convTh(const float* __restrict__ in,
                                              __half* __restrict__ os,
                                              int ldin, int ldout, int zH,
                                              long long sIb, long long sIh,
                                              long long sOb, long long sOh){
    __shared__ float t[32][33];
    int z = blockIdx.z, bz = z / zH, hz = z % zH;
    const float* pin = in + bz * sIb + hz * sIh;
    __half* pos = os + bz * sOb + hz * sOh;
    int cb = blockIdx.x * 32, rb = blockIdx.y * 32;
    int tx = threadIdx.x, ty = threadIdx.y;  // (32, 8)
#pragma unroll
    for (int i = 0; i < 4; i++)
        t[ty + 8*i][tx] = pin[(size_t)(rb + ty + 8*i) * ldin + cb + tx];
    __syncthreads();
#pragma unroll
    for (int i = 0; i < 4; i++){
        float v = t[tx][ty + 8*i];
        pos[(size_t)(cb + ty + 8*i) * ldout + rb + tx] = __float2half_rn(v);
    }
}

// ==================== 2-pass split-fp16 mma.sync GEMM (3-stage pipeline) ===
// BTRANS=false: B is [N,K] K-major.  BTRANS=true: B is [K,N] row-major
// (fragments via ldmatrix.trans) — used for AV where B = V in natural layout.
#define F_BIAS   1
#define F_RES    2
#define F_RELU   4
#define F_SCALE  8
#define F_CAUSAL 16
#define F_KCAUS  32
#define F_QKV    64

template<int BN, bool BTRANS>
__global__ __launch_bounds__(256, 2) void gemm_mma(
    const __half* __restrict__ Ah, const __half* __restrict__ Al,
    const __half* __restrict__ Bs,
    const float* __restrict__ bias, const float* __restrict__ res,
    float* __restrict__ Cf, __half* __restrict__ Ch, __half* __restrict__ Cl,
    __half* __restrict__ C2, __half* __restrict__ C3,
    int K, int lda, int ldb, int ldc,
    int zH, long long sAb, long long sAh, long long sBb, long long sBh,
    long long sCb, long long sChh,
    int flags, float scale)
{
    constexpr int BM = 128, BK = 32;
    constexpr int ABYTES = BM * 40 * 2;    // 10240 (padded 80B rows)
    constexpr int BBYTES = BTRANS ? (BK * 144) : (BN * 40 * 2);
    constexpr int STAGE = 2 * ABYTES + BBYTES;
    constexpr int WN = BN / 2;
    constexpr int NA = WN / 8;

    const int bm = blockIdx.y * BM, bn = blockIdx.x * BN;
    if ((flags & F_CAUSAL) && bn >= bm + BM) return;

    extern __shared__ char sm[];
    const uint32_t smb = smem_u32(sm);

    const int tid = threadIdx.x, lane = tid & 31, wid = tid >> 5;
    const int wm = wid & 3, wn = wid >> 2;

    const int z = blockIdx.z;
    const int bz = z / zH, hz = z % zH;
    const __half* pAh = Ah + bz * sAb + hz * sAh;
    const __half* pAl = Al + bz * sAb + hz * sAh;
    const __half* pB  = Bs + bz * sBb + hz * sBh;
    float* pCf = Cf ? (Cf + bz * sCb + hz * sChh) : nullptr;
    __half* pCh = Ch ? (Ch + bz * sCb + hz * sChh) : nullptr;
    __half* pCl = Cl ? (Cl + bz * sCb + hz * sChh) : nullptr;
    const float* pres = res ? (res + bz * sCb + hz * sChh) : nullptr;

    int nKB = K >> 5;
    if (flags & F_KCAUS){
        int lim = (bm + BM) >> 5;
        if (lim < nKB) nKB = lim;
    }

    auto loadStage = [&](int kb, int s){
        const int k0 = kb * BK;
        const uint32_t stg = smb + s * STAGE;
#pragma unroll
        for (int i = 0; i < 2; i++){
            int idx = i * 256 + tid;
            int r = idx >> 2, c = idx & 3;
            uint32_t dst = stg + r * 80 + c * 16;
            CP16(dst,          pAh + (size_t)(bm + r) * lda + k0 + c * 8);
            CP16(dst + ABYTES, pAl + (size_t)(bm + r) * lda + k0 + c * 8);
        }
        if (BTRANS){
            // B tile: BK=32 rows (k) x BN cols, row pitch 144B (BN=64 -> 128B data)
            int r = tid >> 3, c = tid & 7;
            uint32_t dst = stg + 2 * ABYTES + r * 144 + c * 16;
            CP16(dst, pB + (size_t)(k0 + r) * ldb + bn + c * 8);
        } else {
#pragma unroll
            for (int i = 0; i < BN / 64; i++){
                int idx = i * 256 + tid;
                int r = idx >> 2, c = idx & 3;
                uint32_t dst = stg + 2 * ABYTES + r * 80 + c * 16;
                CP16(dst, pB + (size_t)(bn + r) * ldb + k0 + c * 8);
            }
        }
        CP_COMMIT();
    };

    float acc[2][NA][4];
#pragma unroll
    for (int i = 0; i < 2; i++)
#pragma unroll
        for (int j = 0; j < NA; j++)
#pragma unroll
            for (int q = 0; q < 4; q++) acc[i][j][q] = 0.f;

    loadStage(0, 0);
    loadStage(1, 1);

    for (int kb = 0; kb < nKB; kb++){
        if (kb == nKB - 1) CP_WAIT0(); else CP_WAIT1();
        __syncthreads();
        if (kb + 2 < nKB){
            int s2 = kb + 2; while (s2 >= 3) s2 -= 3;
            loadStage(kb + 2, s2);
        }
        int s = kb; while (s >= 3) s -= 3;
        const uint32_t stg = smb + s * STAGE;
#pragma unroll
        for (int ks = 0; ks < 2; ks++){
            const int kc = ks * 16;
            uint32_t a_h[2][4], a_l[2][4];
#pragma unroll
            for (int mi = 0; mi < 2; mi++){
                int row = wm * 32 + mi * 16 + (lane & 15);
                int colb = (kc + ((lane >> 4) << 3)) * 2;
                uint32_t ad = stg + row * 80 + colb;
                LDSM4(a_h[mi][0], a_h[mi][1], a_h[mi][2], a_h[mi][3], ad);
                LDSM4(a_l[mi][0], a_l[mi][1], a_l[mi][2], a_l[mi][3], ad + ABYTES);
            }
            uint32_t b_s[NA][2];
            if (BTRANS){
#pragma unroll
                for (int p = 0; p < NA / 2; p++){
                    int g = lane >> 3, rr = lane & 7;
                    int row = kc + (g & 1) * 8 + rr;
                    int colb = (wn * WN + p * 16 + (g >> 1) * 8) * 2;
                    uint32_t ad = stg + 2 * ABYTES + row * 144 + colb;
                    uint32_t r0, r1, r2, r3;
                    LDSM4T(r0, r1, r2, r3, ad);
                    b_s[2*p][0] = r0; b_s[2*p][1] = r1;
                    b_s[2*p+1][0] = r2; b_s[2*p+1][1] = r3;
                }
            } else {
#pragma unroll
                for (int p = 0; p < NA / 2; p++){
                    int rowb = wn * WN + p * 16 + (lane & 7) + ((lane >> 4) << 3);
                    int colb = (kc + (((lane >> 3) & 1) << 3)) * 2;
                    uint32_t ad = stg + 2 * ABYTES + rowb * 80 + colb;
                    uint32_t r0, r1, r2, r3;
                    LDSM4(r0, r1, r2, r3, ad);
                    b_s[2*p][0] = r0; b_s[2*p][1] = r1;
                    b_s[2*p+1][0] = r2; b_s[2*p+1][1] = r3;
                }
            }
#pragma unroll
            for (int mi = 0; mi < 2; mi++)
#pragma unroll
                for (int ni = 0; ni < NA; ni++){
                    MMA16816(acc[mi][ni], a_h[mi], b_s[ni]);
                    MMA16816(acc[mi][ni], a_l[mi], b_s[ni]);
                }
        }
    }

    // epilogue
#pragma unroll
    for (int mi = 0; mi < 2; mi++){
#pragma unroll
        for (int ni = 0; ni < NA; ni++){
            int r0 = bm + wm * 32 + mi * 16 + (lane >> 2);
            int c0 = bn + wn * WN + ni * 8 + (lane & 3) * 2;
#pragma unroll
            for (int half = 0; half < 2; half++){
                int r = r0 + half * 8;
                float vx = acc[mi][ni][half * 2 + 0];
                float vy = acc[mi][ni][half * 2 + 1];
                if (flags & F_QKV){
                    int range = c0 >> 10, cc = c0 & 1023;
                    if (range == 0){
                        __half hx = __float2half_rn(vx), hy = __float2half_rn(vy);
                        *(__half2*)(pCh + (size_t)r * ldc + cc) = __half2(hx, hy);
                        *(__half2*)(pCl + (size_t)r * ldc + cc) =
                            __half2(__float2half_rn(vx - __half2float(hx)),
                                    __float2half_rn(vy - __half2float(hy)));
                    } else if (range == 1){
                        *(__half2*)(C2 + (size_t)r * ldc + cc) =
                            __half2(__float2half_rn(vx), __float2half_rn(vy));
                    } else {
                        *(__half2*)(C3 + (size_t)r * ldc + cc) =
                            __half2(__float2half_rn(vx), __float2half_rn(vy));
                    }
                    continue;
                }
                if (flags & F_SCALE){ vx *= scale; vy *= scale; }
                if (flags & F_BIAS){ vx += bias[c0]; vy += bias[c0 + 1]; }
                if (flags & F_RES){
                    const float* rp = pres + (size_t)r * ldc + c0;
                    vx += rp[0]; vy += rp[1];
                }
                if (flags & F_RELU){ vx = fmaxf(vx, 0.f); vy = fmaxf(vy, 0.f); }
                if (flags & F_CAUSAL){
                    if (c0 > r)     vx = -3.0e38f;
                    if (c0 + 1 > r) vy = -3.0e38f;
                }
                if (pCf){
                    float2 o2; o2.x = vx; o2.y = vy;
                    *(float2*)(pCf + (size_t)r * ldc + c0) = o2;
                }
                if (pCh){
                    __half hx = __float2half_rn(vx);
                    __half hy = __float2half_rn(vy);
                    *(__half2*)(pCh + (size_t)r * ldc + c0) = __half2(hx, hy);
                    if (pCl){
                        __half lx = __float2half_rn(vx - __half2float(hx));
                        __half ly = __float2half_rn(vy - __half2float(hy));
                        *(__half2*)(pCl + (size_t)r * ldc + c0) = __half2(lx, ly);
                    }
                }
            }
        }
    }
}

// ==================== host orchestration ====================
extern "C" void kernel_launch(void* const* d_in, const int* in_sizes, int n_in,
                              void* d_out, int out_size){
    (void)in_sizes; (void)n_in; (void)out_size;
    const int*   x     = (const int*)  d_in[0];
    const float* ce    = (const float*)d_in[1];
    const float* pe    = (const float*)d_in[2];
    const float* ln1_s = (const float*)d_in[5];
    const float* ln1_b = (const float*)d_in[6];
    const float* wq    = (const float*)d_in[7];
    const float* wk    = (const float*)d_in[8];
    const float* wv    = (const float*)d_in[9];
    const float* wo    = (const float*)d_in[10];
    const float* bo    = (const float*)d_in[11];
    const float* ln2_s = (const float*)d_in[12];
    const float* ln2_b = (const float*)d_in[13];
    const float* w1    = (const float*)d_in[14];
    const float* b1    = (const float*)d_in[15];
    const float* w2    = (const float*)d_in[16];
    const float* b2    = (const float*)d_in[17];
    const float* lnf_s = (const float*)d_in[18];
    const float* lnf_b = (const float*)d_in[19];
    const float* wf    = (const float*)d_in[20];
    const float* bf    = (const float*)d_in[21];

    float *h, *s;
    cudaGetSymbolAddress((void**)&h, g_h);
    cudaGetSymbolAddress((void**)&s, g_s);

    __half *yH,*yL,*qH,*qL,*kS,*vS,*oH,*oL,*aH,*aL,*sH,*sL;
    cudaGetSymbolAddress((void**)&yH, g_yH);  cudaGetSymbolAddress((void**)&yL, g_yL);
    cudaGetSymbolAddress((void**)&qH, g_qH);  cudaGetSymbolAddress((void**)&qL, g_qL);
    cudaGetSymbolAddress((void**)&kS, g_kS);
    cudaGetSymbolAddress((void**)&vS, g_vS);
    cudaGetSymbolAddress((void**)&oH, g_oH);  cudaGetSymbolAddress((void**)&oL, g_oL);
    cudaGetSymbolAddress((void**)&aH, g_aH);  cudaGetSymbolAddress((void**)&aL, g_aL);
    cudaGetSymbolAddress((void**)&sH, g_sH);  cudaGetSymbolAddress((void**)&sL, g_sL);

    __half *wqkvS,*woS,*w1S,*w2S,*wfS;
    cudaGetSymbolAddress((void**)&wqkvS, g_wqkvS);
    cudaGetSymbolAddress((void**)&woS, g_woS);
    cudaGetSymbolAddress((void**)&w1S, g_w1S);
    cudaGetSymbolAddress((void**)&w2S, g_w2S);
    cudaGetSymbolAddress((void**)&wfS, g_wfS);

    // dyn smem: 3 stages; BN=128 -> 3*30720=92160 ; AV (BN=64,BTRANS) -> 3*(20480+4608)=75264
    const int SM128 = 92160, SMAV = 75264;
    cudaFuncSetAttribute((const void*)gemm_mma<128,false>, cudaFuncAttributeMaxDynamicSharedMemorySize, SM128);
    cudaFuncSetAttribute((const void*)gemm_mma<64,true>,   cudaFuncAttributeMaxDynamicSharedMemorySize, SMAV);

    dim3 cb(32, 8);
    const long long DD = (long long)Dn * Dn;
    const long long DF = (long long)Dn * FFn;
    // packed QKV weights: rows [0,1024)=wq^T, [1024,2048)=wk^T, [2048,3072)=wv^T
    convTh<<<dim3(Dn/32, Dn/32, Ln), cb>>>(wq, wqkvS,          Dn, Dn, 1, DD, 0, 3*DD, 0);
    convTh<<<dim3(Dn/32, Dn/32, Ln), cb>>>(wk, wqkvS + DD,     Dn, Dn, 1, DD, 0, 3*DD, 0);
    convTh<<<dim3(Dn/32, Dn/32, Ln), cb>>>(wv, wqkvS + 2*DD,   Dn, Dn, 1, DD, 0, 3*DD, 0);
    convTh<<<dim3(Dn/32, Dn/32, Ln), cb>>>(wo, woS, Dn, Dn, 1, DD, 0, DD, 0);
    convTh<<<dim3(FFn/32, Dn/32, Ln), cb>>>(w1, w1S, FFn, Dn, 1, DF, 0, DF, 0);
    convTh<<<dim3(Dn/32, FFn/32, Ln), cb>>>(w2, w2S, Dn, FFn, 1, DF, 0, DF, 0);
    convTh<<<dim3(Vn/32, Dn/32, 1),  cb>>>(wf, wfS, Vn, Dn, 1, 0, 0, 0, 0);

    embed_k<<<(Mn * Dn) / 256, 256>>>(x, ce, pe);

    const long long SAB = (long long)Tn * Dn;   // per-batch stride in q/k/v/o
    const long long SS1 = (long long)Tn * Tn;   // per-bh stride in s

    for (int l = 0; l < Ln; l++){
        ln_k<<<Mn, 256>>>(h, yH, yL, ln1_s + l*Dn, ln1_b + l*Dn);

        // fused QKV: q -> hi/lo, k -> single, v -> single (natural layout)
        gemm_mma<128,false><<<dim3(24,16,1), 256, SM128>>>(yH, yL, wqkvS + (size_t)l*3*DD,
            nullptr, nullptr, nullptr, qH, qL, kS, vS, Dn, Dn, Dn, Dn, 1, 0,0,0,0,0,0,
            F_QKV, 1.f);

        // scores: S[bh] = scale * Q K^T (causal) -> fp32
        gemm_mma<128,false><<<dim3(4,4,BHn), 256, SM128>>>(qH, qL, kS, nullptr, nullptr,
            s, nullptr, nullptr, nullptr, nullptr,
            HSn, Dn, Dn, Tn, Hn, SAB, (long long)HSn, SAB, (long long)HSn,
            (long long)Hn*SS1, SS1, F_SCALE | F_CAUSAL, 0.125f);
        softmax_k<<<BHn*Tn, 128>>>();

        // O[bh] = S @ V  (B = V natural [t,d], trans fragments; K truncated causally)
        gemm_mma<64,true><<<dim3(1,4,BHn), 256, SMAV>>>(sH, sL, vS, nullptr, nullptr,
            nullptr, oH, oL, nullptr, nullptr,
            Tn, Tn, Dn, Dn, Hn, (long long)Hn*SS1, SS1, SAB, (long long)HSn,
            SAB, (long long)HSn, F_KCAUS, 1.f);

        gemm_mma<128,false><<<dim3(8,16,1), 256, SM128>>>(oH, oL, woS + (size_t)l*DD,
            bo + l*Dn, h, h, nullptr, nullptr, nullptr, nullptr, Dn, Dn, Dn, Dn, 1,
            0,0,0,0,0,0, F_BIAS | F_RES, 1.f);

        ln_k<<<Mn, 256>>>(h, yH, yL, ln2_s + l*Dn, ln2_b + l*Dn);
        gemm_mma<128,false><<<dim3(32,16,1), 256, SM128>>>(yH, yL, w1S + (size_t)l*DF,
            b1 + l*FFn, nullptr, nullptr, aH, aL, nullptr, nullptr, Dn, Dn, Dn, FFn, 1,
            0,0,0,0,0,0, F_BIAS | F_RELU, 1.f);
        gemm_mma<128,false><<<dim3(8,16,1), 256, SM128>>>(aH, aL, w2S + (size_t)l*DF,
            b2 + l*Dn, h, h, nullptr, nullptr, nullptr, nullptr, FFn, FFn, FFn, Dn, 1,
            0,0,0,0,0,0, F_BIAS | F_RES, 1.f);
    }

    ln_k<<<Mn, 256>>>(h, yH, yL, lnf_s, lnf_b);
    gemm_mma<128,false><<<dim3(Vn/128, 16, 1), 256, SM128>>>(yH, yL, wfS,
        bf, nullptr, (float*)d_out, nullptr, nullptr, nullptr, nullptr, Dn, Dn, Dn, Vn, 1,
        0,0,0,0,0,0, F_BIAS, 1.f);
}

// round 10
// speedup vs baseline: 2.0344x; 1.2950x over previous
#include <cuda_runtime.h>
#include <cuda_fp16.h>
#include <cstdint>

#define Bn 4
#define Tn 512
#define Dn 1024
#define Hn 16
#define HSn 64
#define Ln 8
#define Vn 32000
#define Mn (Bn*Tn)       // 2048
#define FFn (4*Dn)       // 4096
#define BHn (Bn*Hn)      // 64

// ---------------- fp32 scratch ----------------
__device__ float g_h[Mn*Dn];
__device__ float g_s[(size_t)BHn*Tn*Tn];

// ---------------- fp16 planes ----------------
__device__ __half g_yH[Mn*Dn],  g_yL[Mn*Dn];
__device__ __half g_qH[Mn*Dn],  g_qL[Mn*Dn];
__device__ __half g_kS[Mn*Dn];
__device__ __half g_vS[Mn*Dn];                    // natural [t, d] layout
__device__ __half g_oH[Mn*Dn],  g_oL[Mn*Dn];
__device__ __half g_aH[Mn*FFn];
__device__ __half g_sH[(size_t)BHn*Tn*Tn], g_sL[(size_t)BHn*Tn*Tn];

// ---------------- fp16 weights (transposed [N,K], single plane) -----------
__device__ __half g_wqkvS[(size_t)Ln*3*Dn*Dn];   // packed [3072,1024] per layer
__device__ __half g_woS[Ln*Dn*Dn];
__device__ __half g_w1S[Ln*Dn*FFn];
__device__ __half g_w2S[Ln*Dn*FFn];
__device__ __half g_wfS[(size_t)Dn*Vn];

// ==================== helpers ====================
__device__ __forceinline__ uint32_t smem_u32(const void* p){
    uint32_t a;
    asm("{ .reg .u64 t; cvta.to.shared.u64 t, %1; cvt.u32.u64 %0, t; }" : "=r"(a) : "l"(p));
    return a;
}
#define CP16(dst, src) \
    asm volatile("cp.async.cg.shared.global [%0], [%1], 16;" :: "r"(dst), "l"(src))
#define CP_COMMIT() asm volatile("cp.async.commit_group;" ::: "memory")
#define CP_WAIT1() asm volatile("cp.async.wait_group 1;" ::: "memory")
#define CP_WAIT0() asm volatile("cp.async.wait_group 0;" ::: "memory")

#define LDSM4(r0,r1,r2,r3,addr) \
    asm volatile("ldmatrix.sync.aligned.m8n8.x4.shared.b16 {%0,%1,%2,%3}, [%4];" \
        : "=r"(r0),"=r"(r1),"=r"(r2),"=r"(r3) : "r"(addr))
#define LDSM4T(r0,r1,r2,r3,addr) \
    asm volatile("ldmatrix.sync.aligned.m8n8.x4.trans.shared.b16 {%0,%1,%2,%3}, [%4];" \
        : "=r"(r0),"=r"(r1),"=r"(r2),"=r"(r3) : "r"(addr))

#define MMA16816(d, a, b) \
    asm volatile("mma.sync.aligned.m16n8k16.row.col.f32.f16.f16.f32 " \
        "{%0,%1,%2,%3}, {%4,%5,%6,%7}, {%8,%9}, {%0,%1,%2,%3};" \
        : "+f"((d)[0]),"+f"((d)[1]),"+f"((d)[2]),"+f"((d)[3]) \
        : "r"((a)[0]),"r"((a)[1]),"r"((a)[2]),"r"((a)[3]), "r"((b)[0]),"r"((b)[1]))

// ==================== reductions ====================
__device__ __forceinline__ float warpSum(float v){
#pragma unroll
    for (int o = 16; o > 0; o >>= 1) v += __shfl_down_sync(0xffffffffu, v, o);
    return v;
}
__device__ __forceinline__ float warpMax(float v){
#pragma unroll
    for (int o = 16; o > 0; o >>= 1) v = fmaxf(v, __shfl_down_sync(0xffffffffu, v, o));
    return v;
}
__device__ __forceinline__ float blockSum(float v, float* sh){
    int lane = threadIdx.x & 31, w = threadIdx.x >> 5;
    v = warpSum(v);
    __syncthreads();
    if (lane == 0) sh[w] = v;
    __syncthreads();
    int nw = blockDim.x >> 5;
    v = (threadIdx.x < (unsigned)nw) ? sh[threadIdx.x] : 0.f;
    if (w == 0) v = warpSum(v);
    if (threadIdx.x == 0) sh[0] = v;
    __syncthreads();
    return sh[0];
}
__device__ __forceinline__ float blockMax(float v, float* sh){
    int lane = threadIdx.x & 31, w = threadIdx.x >> 5;
    v = warpMax(v);
    __syncthreads();
    if (lane == 0) sh[w] = v;
    __syncthreads();
    int nw = blockDim.x >> 5;
    v = (threadIdx.x < (unsigned)nw) ? sh[threadIdx.x] : -3.0e38f;
    if (w == 0) v = warpMax(v);
    if (threadIdx.x == 0) sh[0] = v;
    __syncthreads();
    return sh[0];
}

// ==================== small kernels ====================
__global__ void embed_k(const int* __restrict__ x, const float* __restrict__ ce,
                        const float* __restrict__ pe){
    int idx = blockIdx.x * blockDim.x + threadIdx.x;
    int d  = idx & (Dn - 1);
    int mt = idx >> 10;
    int t  = mt & (Tn - 1);
    g_h[idx] = ce[(size_t)x[mt] * Dn + d] + pe[t * Dn + d];
}

// LayerNorm fused with fp16 hi/lo plane output (register-cached row)
__global__ __launch_bounds__(256) void ln_k(const float* __restrict__ in,
                                            __half* __restrict__ outH,
                                            __half* __restrict__ outL,
                                            const float* __restrict__ gs,
                                            const float* __restrict__ gb){
    __shared__ float sh[32];
    int row = blockIdx.x;
    const float4* xr = (const float4*)(in + (size_t)row * Dn);
    float4 vv = xr[threadIdx.x];
    float s  = vv.x + vv.y + vv.z + vv.w;
    float sq = vv.x*vv.x + vv.y*vv.y + vv.z*vv.z + vv.w*vv.w;
    s  = blockSum(s, sh);
    sq = blockSum(sq, sh);
    float mean = s * (1.f / Dn);
    float var  = sq * (1.f / Dn) - mean * mean;
    float r = rsqrtf(var + 1e-5f);
    int i0 = threadIdx.x * 4;
    float o[4];
    o[0] = (vv.x - mean) * r * gs[i0+0] + gb[i0+0];
    o[1] = (vv.y - mean) * r * gs[i0+1] + gb[i0+1];
    o[2] = (vv.z - mean) * r * gs[i0+2] + gb[i0+2];
    o[3] = (vv.w - mean) * r * gs[i0+3] + gb[i0+3];
    __half2 h2[2], l2[2];
#pragma unroll
    for (int p = 0; p < 2; p++){
        __half hx = __float2half_rn(o[2*p]);
        __half hy = __float2half_rn(o[2*p+1]);
        h2[p] = __half2(hx, hy);
        l2[p] = __half2(__float2half_rn(o[2*p]   - __half2float(hx)),
                        __float2half_rn(o[2*p+1] - __half2float(hy)));
    }
    *(uint2*)(outH + (size_t)row * Dn + i0) = *(uint2*)h2;
    *(uint2*)(outL + (size_t)row * Dn + i0) = *(uint2*)l2;
}

// causal softmax, register-cached, fp16 hi/lo planes out, zero fill to AV tile edge
__global__ __launch_bounds__(128) void softmax_k(){
    __shared__ float sh[32];
    int row = blockIdx.x;           // 0 .. BHn*Tn-1
    int i = row & (Tn - 1);
    int zend = ((i >> 7) + 1) << 7; // AV reads cols < zend only
    const float* sr = g_s + (size_t)row * Tn;
    __half* ph = g_sH + (size_t)row * Tn;
    __half* pl = g_sL + (size_t)row * Tn;
    float vals[4];
    float mx = -3.0e38f;
#pragma unroll
    for (int p = 0; p < 4; p++){
        int j = threadIdx.x + p * 128;
        vals[p] = (j <= i) ? sr[j] : -3.0e38f;
        mx = fmaxf(mx, vals[p]);
    }
    mx = blockMax(mx, sh);
    float sum = 0.f;
#pragma unroll
    for (int p = 0; p < 4; p++){
        int j = threadIdx.x + p * 128;
        float e = (j <= i) ? expf(vals[p] - mx) : 0.f;
        vals[p] = e;
        sum += e;
    }
    sum = blockSum(sum, sh);
    float inv = 1.f / sum;
#pragma unroll
    for (int p = 0; p < 4; p++){
        int j = threadIdx.x + p * 128;
        if (j < zend){
            float pr = vals[p] * inv;
            __half h = __float2half_rn(pr);
            ph[j] = h;
            pl[j] = __float2half_rn(pr - __half2float(h));
        }
    }
}

// transpose + convert: in [R,C] fp32 -> out [C,R] fp16 single plane (weights)
__global__ __launch_bounds__(256) void convTh(const float* __restrict__ in,
                                              __half* __restrict__ os,
                                              int ldin, int ldout, int zH,
                                              long long sIb, long long sIh,
                                              long long sOb, long long sOh){
    __shared__ float t[32][33];
    int z = blockIdx.z, bz = z / zH, hz = z % zH;
    const float* pin = in + bz * sIb + hz * sIh;
    __half* pos = os + bz * sOb + hz * sOh;
    int cb = blockIdx.x * 32, rb = blockIdx.y * 32;
    int tx = threadIdx.x, ty = threadIdx.y;  // (32, 8)
#pragma unroll
    for (int i = 0; i < 4; i++)
        t[ty + 8*i][tx] = pin[(size_t)(rb + ty + 8*i) * ldin + cb + tx];
    __syncthreads();
#pragma unroll
    for (int i = 0; i < 4; i++){
        float v = t[tx][ty + 8*i];
        pos[(size_t)(cb + ty + 8*i) * ldout + rb + tx] = __float2half_rn(v);
    }
}

// ==================== split-fp16 mma.sync GEMM (3-stage pipeline) ==========
// TWOPASS=true : C = (Ah+Al) @ B^T  (2 MMA passes)
// TWOPASS=false: C = Ah @ B^T       (1 MMA pass, A-lo plane never touched)
// BTRANS=true  : B is [K,N] row-major (ldmatrix.trans) — AV path.
#define F_BIAS   1
#define F_RES    2
#define F_RELU   4
#define F_SCALE  8
#define F_CAUSAL 16
#define F_KCAUS  32
#define F_QKV    64

template<int BN, bool BTRANS, bool TWOPASS>
__global__ __launch_bounds__(256, 2) void gemm_mma(
    const __half* __restrict__ Ah, const __half* __restrict__ Al,
    const __half* __restrict__ Bs,
    const float* __restrict__ bias, const float* __restrict__ res,
    float* __restrict__ Cf, __half* __restrict__ Ch, __half* __restrict__ Cl,
    __half* __restrict__ C2, __half* __restrict__ C3,
    int K, int lda, int ldb, int ldc,
    int zH, long long sAb, long long sAh, long long sBb, long long sBh,
    long long sCb, long long sChh,
    int flags, float scale)
{
    constexpr int BM = 128, BK = 32;
    constexpr int ABYTES = BM * 40 * 2;    // 10240 (padded 80B rows)
    constexpr int NAPL = TWOPASS ? 2 : 1;  // A planes in smem
    constexpr int BOFF = NAPL * ABYTES;
    constexpr int BBYTES = BTRANS ? (BK * 144) : (BN * 40 * 2);
    constexpr int STAGE = BOFF + BBYTES;
    constexpr int WN = BN / 2;
    constexpr int NA = WN / 8;

    const int bm = blockIdx.y * BM, bn = blockIdx.x * BN;
    if ((flags & F_CAUSAL) && bn >= bm + BM) return;

    extern __shared__ char sm[];
    const uint32_t smb = smem_u32(sm);

    const int tid = threadIdx.x, lane = tid & 31, wid = tid >> 5;
    const int wm = wid & 3, wn = wid >> 2;

    const int z = blockIdx.z;
    const int bz = z / zH, hz = z % zH;
    const __half* pAh = Ah + bz * sAb + hz * sAh;
    const __half* pAl = TWOPASS ? (Al + bz * sAb + hz * sAh) : nullptr;
    const __half* pB  = Bs + bz * sBb + hz * sBh;
    float* pCf = Cf ? (Cf + bz * sCb + hz * sChh) : nullptr;
    __half* pCh = Ch ? (Ch + bz * sCb + hz * sChh) : nullptr;
    __half* pCl = Cl ? (Cl + bz * sCb + hz * sChh) : nullptr;
    const float* pres = res ? (res + bz * sCb + hz * sChh) : nullptr;

    int nKB = K >> 5;
    if (flags & F_KCAUS){
        int lim = (bm + BM) >> 5;
        if (lim < nKB) nKB = lim;
    }

    auto loadStage = [&](int kb, int s){
        const int k0 = kb * BK;
        const uint32_t stg = smb + s * STAGE;
#pragma unroll
        for (int i = 0; i < 2; i++){
            int idx = i * 256 + tid;
            int r = idx >> 2, c = idx & 3;
            uint32_t dst = stg + r * 80 + c * 16;
            CP16(dst, pAh + (size_t)(bm + r) * lda + k0 + c * 8);
            if (TWOPASS)
                CP16(dst + ABYTES, pAl + (size_t)(bm + r) * lda + k0 + c * 8);
        }
        if (BTRANS){
            int r = tid >> 3, c = tid & 7;
            uint32_t dst = stg + BOFF + r * 144 + c * 16;
            CP16(dst, pB + (size_t)(k0 + r) * ldb + bn + c * 8);
        } else {
#pragma unroll
            for (int i = 0; i < BN / 64; i++){
                int idx = i * 256 + tid;
                int r = idx >> 2, c = idx & 3;
                uint32_t dst = stg + BOFF + r * 80 + c * 16;
                CP16(dst, pB + (size_t)(bn + r) * ldb + k0 + c * 8);
            }
        }
        CP_COMMIT();
    };

    float acc[2][NA][4];
#pragma unroll
    for (int i = 0; i < 2; i++)
#pragma unroll
        for (int j = 0; j < NA; j++)
#pragma unroll
            for (int q = 0; q < 4; q++) acc[i][j][q] = 0.f;

    loadStage(0, 0);
    loadStage(1, 1);

    for (int kb = 0; kb < nKB; kb++){
        if (kb == nKB - 1) CP_WAIT0(); else CP_WAIT1();
        __syncthreads();
        if (kb + 2 < nKB){
            int s2 = kb + 2; while (s2 >= 3) s2 -= 3;
            loadStage(kb + 2, s2);
        }
        int s = kb; while (s >= 3) s -= 3;
        const uint32_t stg = smb + s * STAGE;
#pragma unroll
        for (int ks = 0; ks < 2; ks++){
            const int kc = ks * 16;
            uint32_t a_h[2][4], a_l[2][4];
#pragma unroll
            for (int mi = 0; mi < 2; mi++){
                int row = wm * 32 + mi * 16 + (lane & 15);
                int colb = (kc + ((lane >> 4) << 3)) * 2;
                uint32_t ad = stg + row * 80 + colb;
                LDSM4(a_h[mi][0], a_h[mi][1], a_h[mi][2], a_h[mi][3], ad);
                if (TWOPASS)
                    LDSM4(a_l[mi][0], a_l[mi][1], a_l[mi][2], a_l[mi][3], ad + ABYTES);
            }
            uint32_t b_s[NA][2];
            if (BTRANS){
#pragma unroll
                for (int p = 0; p < NA / 2; p++){
                    int g = lane >> 3, rr = lane & 7;
                    int row = kc + (g & 1) * 8 + rr;
                    int colb = (wn * WN + p * 16 + (g >> 1) * 8) * 2;
                    uint32_t ad = stg + BOFF + row * 144 + colb;
                    uint32_t r0, r1, r2, r3;
                    LDSM4T(r0, r1, r2, r3, ad);
                    b_s[2*p][0] = r0; b_s[2*p][1] = r1;
                    b_s[2*p+1][0] = r2; b_s[2*p+1][1] = r3;
                }
            } else {
#pragma unroll
                for (int p = 0; p < NA / 2; p++){
                    int rowb = wn * WN + p * 16 + (lane & 7) + ((lane >> 4) << 3);
                    int colb = (kc + (((lane >> 3) & 1) << 3)) * 2;
                    uint32_t ad = stg + BOFF + rowb * 80 + colb;
                    uint32_t r0, r1, r2, r3;
                    LDSM4(r0, r1, r2, r3, ad);
                    b_s[2*p][0] = r0; b_s[2*p][1] = r1;
                    b_s[2*p+1][0] = r2; b_s[2*p+1][1] = r3;
                }
            }
#pragma unroll
            for (int mi = 0; mi < 2; mi++)
#pragma unroll
                for (int ni = 0; ni < NA; ni++){
                    MMA16816(acc[mi][ni], a_h[mi], b_s[ni]);
                    if (TWOPASS)
                        MMA16816(acc[mi][ni], a_l[mi], b_s[ni]);
                }
        }
    }

    // epilogue
#pragma unroll
    for (int mi = 0; mi < 2; mi++){
#pragma unroll
        for (int ni = 0; ni < NA; ni++){
            int r0 = bm + wm * 32 + mi * 16 + (lane >> 2);
            int c0 = bn + wn * WN + ni * 8 + (lane & 3) * 2;
#pragma unroll
            for (int half = 0; half < 2; half++){
                int r = r0 + half * 8;
                float vx = acc[mi][ni][half * 2 + 0];
                float vy = acc[mi][ni][half * 2 + 1];
                if (flags & F_QKV){
                    int range = c0 >> 10, cc = c0 & 1023;
                    if (range == 0){
                        __half hx = __float2half_rn(vx), hy = __float2half_rn(vy);
                        *(__half2*)(pCh + (size_t)r * ldc + cc) = __half2(hx, hy);
                        *(__half2*)(pCl + (size_t)r * ldc + cc) =
                            __half2(__float2half_rn(vx - __half2float(hx)),
                                    __float2half_rn(vy - __half2float(hy)));
                    } else if (range == 1){
                        *(__half2*)(C2 + (size_t)r * ldc + cc) =
                            __half2(__float2half_rn(vx), __float2half_rn(vy));
                    } else {
                        *(__half2*)(C3 + (size_t)r * ldc + cc) =
                            __half2(__float2half_rn(vx), __float2half_rn(vy));
                    }
                    continue;
                }
                if (flags & F_SCALE){ vx *= scale; vy *= scale; }
                if (flags & F_BIAS){ vx += bias[c0]; vy += bias[c0 + 1]; }
                if (flags & F_RES){
                    const float* rp = pres + (size_t)r * ldc + c0;
                    vx += rp[0]; vy += rp[1];
                }
                if (flags & F_RELU){ vx = fmaxf(vx, 0.f); vy = fmaxf(vy, 0.f); }
                if (flags & F_CAUSAL){
                    if (c0 > r)     vx = -3.0e38f;
                    if (c0 + 1 > r) vy = -3.0e38f;
                }
                if (pCf){
                    float2 o2; o2.x = vx; o2.y = vy;
                    *(float2*)(pCf + (size_t)r * ldc + c0) = o2;
                }
                if (pCh){
                    __half hx = __float2half_rn(vx);
                    __half hy = __float2half_rn(vy);
                    *(__half2*)(pCh + (size_t)r * ldc + c0) = __half2(hx, hy);
                    if (pCl){
                        __half lx = __float2half_rn(vx - __half2float(hx));
                        __half ly = __float2half_rn(vy - __half2float(hy));
                        *(__half2*)(pCl + (size_t)r * ldc + c0) = __half2(lx, ly);
                    }
                }
            }
        }
    }
}

// ==================== host orchestration ====================
extern "C" void kernel_launch(void* const* d_in, const int* in_sizes, int n_in,
                              void* d_out, int out_size){
    (void)in_sizes; (void)n_in; (void)out_size;
    const int*   x     = (const int*)  d_in[0];
    const float* ce    = (const float*)d_in[1];
    const float* pe    = (const float*)d_in[2];
    const float* ln1_s = (const float*)d_in[5];
    const float* ln1_b = (const float*)d_in[6];
    const float* wq    = (const float*)d_in[7];
    const float* wk    = (const float*)d_in[8];
    const float* wv    = (const float*)d_in[9];
    const float* wo    = (const float*)d_in[10];
    const float* bo    = (const float*)d_in[11];
    const float* ln2_s = (const float*)d_in[12];
    const float* ln2_b = (const float*)d_in[13];
    const float* w1    = (const float*)d_in[14];
    const float* b1    = (const float*)d_in[15];
    const float* w2    = (const float*)d_in[16];
    const float* b2    = (const float*)d_in[17];
    const float* lnf_s = (const float*)d_in[18];
    const float* lnf_b = (const float*)d_in[19];
    const float* wf    = (const float*)d_in[20];
    const float* bf    = (const float*)d_in[21];

    float *h, *s;
    cudaGetSymbolAddress((void**)&h, g_h);
    cudaGetSymbolAddress((void**)&s, g_s);

    __half *yH,*yL,*qH,*qL,*kS,*vS,*oH,*oL,*aH,*sH,*sL;
    cudaGetSymbolAddress((void**)&yH, g_yH);  cudaGetSymbolAddress((void**)&yL, g_yL);
    cudaGetSymbolAddress((void**)&qH, g_qH);  cudaGetSymbolAddress((void**)&qL, g_qL);
    cudaGetSymbolAddress((void**)&kS, g_kS);
    cudaGetSymbolAddress((void**)&vS, g_vS);
    cudaGetSymbolAddress((void**)&oH, g_oH);  cudaGetSymbolAddress((void**)&oL, g_oL);
    cudaGetSymbolAddress((void**)&aH, g_aH);
    cudaGetSymbolAddress((void**)&sH, g_sH);  cudaGetSymbolAddress((void**)&sL, g_sL);

    __half *wqkvS,*woS,*w1S,*w2S,*wfS;
    cudaGetSymbolAddress((void**)&wqkvS, g_wqkvS);
    cudaGetSymbolAddress((void**)&woS, g_woS);
    cudaGetSymbolAddress((void**)&w1S, g_w1S);
    cudaGetSymbolAddress((void**)&w2S, g_w2S);
    cudaGetSymbolAddress((void**)&wfS, g_wfS);

    // dyn smem per instantiation (3 stages):
    //  2-pass BN=128:         3*(20480+10240) = 92160
    //  AV 2-pass BN=64 trans: 3*(20480+4608)  = 75264
    //  1-pass BN=128:         3*(10240+10240) = 61440
    const int SM2P = 92160, SMAV = 75264, SM1P = 61440;
    cudaFuncSetAttribute((const void*)gemm_mma<128,false,true>,  cudaFuncAttributeMaxDynamicSharedMemorySize, SM2P);
    cudaFuncSetAttribute((const void*)gemm_mma<64,true,true>,    cudaFuncAttributeMaxDynamicSharedMemorySize, SMAV);
    cudaFuncSetAttribute((const void*)gemm_mma<128,false,false>, cudaFuncAttributeMaxDynamicSharedMemorySize, SM1P);

    dim3 cb(32, 8);
    const long long DD = (long long)Dn * Dn;
    const long long DF = (long long)Dn * FFn;
    // packed QKV weights: rows [0,1024)=wq^T, [1024,2048)=wk^T, [2048,3072)=wv^T
    convTh<<<dim3(Dn/32, Dn/32, Ln), cb>>>(wq, wqkvS,          Dn, Dn, 1, DD, 0, 3*DD, 0);
    convTh<<<dim3(Dn/32, Dn/32, Ln), cb>>>(wk, wqkvS + DD,     Dn, Dn, 1, DD, 0, 3*DD, 0);
    convTh<<<dim3(Dn/32, Dn/32, Ln), cb>>>(wv, wqkvS + 2*DD,   Dn, Dn, 1, DD, 0, 3*DD, 0);
    convTh<<<dim3(Dn/32, Dn/32, Ln), cb>>>(wo, woS, Dn, Dn, 1, DD, 0, DD, 0);
    convTh<<<dim3(FFn/32, Dn/32, Ln), cb>>>(w1, w1S, FFn, Dn, 1, DF, 0, DF, 0);
    convTh<<<dim3(Dn/32, FFn/32, Ln), cb>>>(w2, w2S, Dn, FFn, 1, DF, 0, DF, 0);
    convTh<<<dim3(Vn/32, Dn/32, 1),  cb>>>(wf, wfS, Vn, Dn, 1, 0, 0, 0, 0);

    embed_k<<<(Mn * Dn) / 256, 256>>>(x, ce, pe);

    const long long SAB = (long long)Tn * Dn;   // per-batch stride in q/k/v/o
    const long long SS1 = (long long)Tn * Tn;   // per-bh stride in s

    for (int l = 0; l < Ln; l++){
        ln_k<<<Mn, 256>>>(h, yH, yL, ln1_s + l*Dn, ln1_b + l*Dn);

        // fused QKV (2-pass): q -> hi/lo, k -> single, v -> single (natural layout)
        gemm_mma<128,false,true><<<dim3(24,16,1), 256, SM2P>>>(yH, yL,
            wqkvS + (size_t)l*3*DD,
            nullptr, nullptr, nullptr, qH, qL, kS, vS, Dn, Dn, Dn, Dn, 1, 0,0,0,0,0,0,
            F_QKV, 1.f);

        // scores (2-pass): S[bh] = scale * Q K^T (causal) -> fp32
        gemm_mma<128,false,true><<<dim3(4,4,BHn), 256, SM2P>>>(qH, qL, kS,
            nullptr, nullptr, s, nullptr, nullptr, nullptr, nullptr,
            HSn, Dn, Dn, Tn, Hn, SAB, (long long)HSn, SAB, (long long)HSn,
            (long long)Hn*SS1, SS1, F_SCALE | F_CAUSAL, 0.125f);
        softmax_k<<<BHn*Tn, 128>>>();

        // O[bh] = S @ V (2-pass; V natural layout, trans frags; K truncated)
        gemm_mma<64,true,true><<<dim3(1,4,BHn), 256, SMAV>>>(sH, sL, vS,
            nullptr, nullptr, nullptr, oH, oL, nullptr, nullptr,
            Tn, Tn, Dn, Dn, Hn, (long long)Hn*SS1, SS1, SAB, (long long)HSn,
            SAB, (long long)HSn, F_KCAUS, 1.f);

        // O-proj (2-pass)
        gemm_mma<128,false,true><<<dim3(8,16,1), 256, SM2P>>>(oH, oL,
            woS + (size_t)l*DD,
            bo + l*Dn, h, h, nullptr, nullptr, nullptr, nullptr, Dn, Dn, Dn, Dn, 1,
            0,0,0,0,0,0, F_BIAS | F_RES, 1.f);

        ln_k<<<Mn, 256>>>(h, yH, yL, ln2_s + l*Dn, ln2_b + l*Dn);

        // MLP1 (1-pass): a = relu(y @ w1 + b1) -> single fp16 plane
        gemm_mma<128,false,false><<<dim3(32,16,1), 256, SM1P>>>(yH, nullptr,
            w1S + (size_t)l*DF,
            b1 + l*FFn, nullptr, nullptr, aH, nullptr, nullptr, nullptr,
            Dn, Dn, Dn, FFn, 1, 0,0,0,0,0,0, F_BIAS | F_RELU, 1.f);

        // MLP2 (1-pass): h += a @ w2 + b2
        gemm_mma<128,false,false><<<dim3(8,16,1), 256, SM1P>>>(aH, nullptr,
            w2S + (size_t)l*DF,
            b2 + l*Dn, h, h, nullptr, nullptr, nullptr, nullptr,
            FFn, FFn, FFn, Dn, 1, 0,0,0,0,0,0, F_BIAS | F_RES, 1.f);
    }

    ln_k<<<Mn, 256>>>(h, yH, yL, lnf_s, lnf_b);

    // logits (1-pass)
    gemm_mma<128,false,false><<<dim3(Vn/128, 16, 1), 256, SM1P>>>(yH, nullptr, wfS,
        bf, nullptr, (float*)d_out, nullptr, nullptr, nullptr, nullptr,
        Dn, Dn, Dn, Vn, 1, 0,0,0,0,0,0, F_BIAS, 1.f);
}

// round 11
// speedup vs baseline: 2.1364x; 1.0501x over previous
#include <cuda_runtime.h>
#include <cuda_fp16.h>
#include <cstdint>

#define Bn 4
#define Tn 512
#define Dn 1024
#define Hn 16
#define HSn 64
#define Ln 8
#define Vn 32000
#define Mn (Bn*Tn)       // 2048
#define FFn (4*Dn)       // 4096
#define BHn (Bn*Hn)      // 64

// ---------------- fp32 scratch ----------------
__device__ float g_h[Mn*Dn];
__device__ float g_s[(size_t)BHn*Tn*Tn];

// ---------------- fp16 planes ----------------
__device__ __half g_yH[Mn*Dn],  g_yL[Mn*Dn];
__device__ __half g_qS[Mn*Dn];
__device__ __half g_kS[Mn*Dn];
__device__ __half g_vS[Mn*Dn];                    // natural [t, d] layout
__device__ __half g_oH[Mn*Dn],  g_oL[Mn*Dn];
__device__ __half g_aH[Mn*FFn];
__device__ __half g_sH[(size_t)BHn*Tn*Tn];

// ---------------- fp16 weights (transposed [N,K], single plane) -----------
__device__ __half g_wqkvS[(size_t)Ln*3*Dn*Dn];   // packed [3072,1024] per layer
__device__ __half g_woS[Ln*Dn*Dn];
__device__ __half g_w1S[Ln*Dn*FFn];
__device__ __half g_w2S[Ln*Dn*FFn];
__device__ __half g_wfS[(size_t)Dn*Vn];

// ==================== helpers ====================
__device__ __forceinline__ uint32_t smem_u32(const void* p){
    uint32_t a;
    asm("{ .reg .u64 t; cvta.to.shared.u64 t, %1; cvt.u32.u64 %0, t; }" : "=r"(a) : "l"(p));
    return a;
}
#define CP16(dst, src) \
    asm volatile("cp.async.cg.shared.global [%0], [%1], 16;" :: "r"(dst), "l"(src))
#define CP_COMMIT() asm volatile("cp.async.commit_group;" ::: "memory")
#define CP_WAIT1() asm volatile("cp.async.wait_group 1;" ::: "memory")
#define CP_WAIT0() asm volatile("cp.async.wait_group 0;" ::: "memory")

#define LDSM4(r0,r1,r2,r3,addr) \
    asm volatile("ldmatrix.sync.aligned.m8n8.x4.shared.b16 {%0,%1,%2,%3}, [%4];" \
        : "=r"(r0),"=r"(r1),"=r"(r2),"=r"(r3) : "r"(addr))
#define LDSM4T(r0,r1,r2,r3,addr) \
    asm volatile("ldmatrix.sync.aligned.m8n8.x4.trans.shared.b16 {%0,%1,%2,%3}, [%4];" \
        : "=r"(r0),"=r"(r1),"=r"(r2),"=r"(r3) : "r"(addr))

#define MMA16816(d, a, b) \
    asm volatile("mma.sync.aligned.m16n8k16.row.col.f32.f16.f16.f32 " \
        "{%0,%1,%2,%3}, {%4,%5,%6,%7}, {%8,%9}, {%0,%1,%2,%3};" \
        : "+f"((d)[0]),"+f"((d)[1]),"+f"((d)[2]),"+f"((d)[3]) \
        : "r"((a)[0]),"r"((a)[1]),"r"((a)[2]),"r"((a)[3]), "r"((b)[0]),"r"((b)[1]))

// ==================== reductions ====================
__device__ __forceinline__ float warpSum(float v){
#pragma unroll
    for (int o = 16; o > 0; o >>= 1) v += __shfl_down_sync(0xffffffffu, v, o);
    return v;
}
__device__ __forceinline__ float warpMax(float v){
#pragma unroll
    for (int o = 16; o > 0; o >>= 1) v = fmaxf(v, __shfl_down_sync(0xffffffffu, v, o));
    return v;
}
__device__ __forceinline__ float blockSum(float v, float* sh){
    int lane = threadIdx.x & 31, w = threadIdx.x >> 5;
    v = warpSum(v);
    __syncthreads();
    if (lane == 0) sh[w] = v;
    __syncthreads();
    int nw = blockDim.x >> 5;
    v = (threadIdx.x < (unsigned)nw) ? sh[threadIdx.x] : 0.f;
    if (w == 0) v = warpSum(v);
    if (threadIdx.x == 0) sh[0] = v;
    __syncthreads();
    return sh[0];
}
__device__ __forceinline__ float blockMax(float v, float* sh){
    int lane = threadIdx.x & 31, w = threadIdx.x >> 5;
    v = warpMax(v);
    __syncthreads();
    if (lane == 0) sh[w] = v;
    __syncthreads();
    int nw = blockDim.x >> 5;
    v = (threadIdx.x < (unsigned)nw) ? sh[threadIdx.x] : -3.0e38f;
    if (w == 0) v = warpMax(v);
    if (threadIdx.x == 0) sh[0] = v;
    __syncthreads();
    return sh[0];
}

// ==================== small kernels ====================
__global__ void embed_k(const int* __restrict__ x, const float* __restrict__ ce,
                        const float* __restrict__ pe){
    int idx = blockIdx.x * blockDim.x + threadIdx.x;
    int d  = idx & (Dn - 1);
    int mt = idx >> 10;
    int t  = mt & (Tn - 1);
    g_h[idx] = ce[(size_t)x[mt] * Dn + d] + pe[t * Dn + d];
}

// LayerNorm fused with fp16 hi/lo plane output (register-cached row)
__global__ __launch_bounds__(256) void ln_k(const float* __restrict__ in,
                                            __half* __restrict__ outH,
                                            __half* __restrict__ outL,
                                            const float* __restrict__ gs,
                                            const float* __restrict__ gb){
    __shared__ float sh[32];
    int row = blockIdx.x;
    const float4* xr = (const float4*)(in + (size_t)row * Dn);
    float4 vv = xr[threadIdx.x];
    float s  = vv.x + vv.y + vv.z + vv.w;
    float sq = vv.x*vv.x + vv.y*vv.y + vv.z*vv.z + vv.w*vv.w;
    s  = blockSum(s, sh);
    sq = blockSum(sq, sh);
    float mean = s * (1.f / Dn);
    float var  = sq * (1.f / Dn) - mean * mean;
    float r = rsqrtf(var + 1e-5f);
    int i0 = threadIdx.x * 4;
    float o[4];
    o[0] = (vv.x - mean) * r * gs[i0+0] + gb[i0+0];
    o[1] = (vv.y - mean) * r * gs[i0+1] + gb[i0+1];
    o[2] = (vv.z - mean) * r * gs[i0+2] + gb[i0+2];
    o[3] = (vv.w - mean) * r * gs[i0+3] + gb[i0+3];
    __half2 h2[2], l2[2];
#pragma unroll
    for (int p = 0; p < 2; p++){
        __half hx = __float2half_rn(o[2*p]);
        __half hy = __float2half_rn(o[2*p+1]);
        h2[p] = __half2(hx, hy);
        l2[p] = __half2(__float2half_rn(o[2*p]   - __half2float(hx)),
                        __float2half_rn(o[2*p+1] - __half2float(hy)));
    }
    *(uint2*)(outH + (size_t)row * Dn + i0) = *(uint2*)h2;
    *(uint2*)(outL + (size_t)row * Dn + i0) = *(uint2*)l2;
}

// causal softmax, register-cached, single fp16 plane out, zero fill to AV tile edge
__global__ __launch_bounds__(128) void softmax_k(){
    __shared__ float sh[32];
    int row = blockIdx.x;           // 0 .. BHn*Tn-1
    int i = row & (Tn - 1);
    int zend = ((i >> 7) + 1) << 7; // AV reads cols < zend only
    const float* sr = g_s + (size_t)row * Tn;
    __half* ph = g_sH + (size_t)row * Tn;
    float vals[4];
    float mx = -3.0e38f;
#pragma unroll
    for (int p = 0; p < 4; p++){
        int j = threadIdx.x + p * 128;
        vals[p] = (j <= i) ? sr[j] : -3.0e38f;
        mx = fmaxf(mx, vals[p]);
    }
    mx = blockMax(mx, sh);
    float sum = 0.f;
#pragma unroll
    for (int p = 0; p < 4; p++){
        int j = threadIdx.x + p * 128;
        float e = (j <= i) ? expf(vals[p] - mx) : 0.f;
        vals[p] = e;
        sum += e;
    }
    sum = blockSum(sum, sh);
    float inv = 1.f / sum;
#pragma unroll
    for (int p = 0; p < 4; p++){
        int j = threadIdx.x + p * 128;
        if (j < zend)
            ph[j] = __float2half_rn(vals[p] * inv);
    }
}

// transpose + convert: in [R,C] fp32 -> out [C,R] fp16 (half2-coalesced writes)
// block (32,8); grid (C/32, R/64, z). Requires R % 64 == 0.
__global__ __launch_bounds__(256) void convTh(const float* __restrict__ in,
                                              __half* __restrict__ os,
                                              int ldin, int ldout, int zH,
                                              long long sIb, long long sIh,
                                              long long sOb, long long sOh){
    __shared__ float t[64][33];
    int z = blockIdx.z, bz = z / zH, hz = z % zH;
    const float* pin = in + bz * sIb + hz * sIh;
    __half* pos = os + bz * sOb + hz * sOh;
    int cb = blockIdx.x * 32, rb = blockIdx.y * 64;
    int tx = threadIdx.x, ty = threadIdx.y;  // (32, 8)
#pragma unroll
    for (int i = 0; i < 8; i++)
        t[ty + 8*i][tx] = pin[(size_t)(rb + ty + 8*i) * ldin + cb + tx];
    __syncthreads();
#pragma unroll
    for (int i = 0; i < 4; i++){
        int c = ty + 8*i;
        float v0 = t[2*tx][c], v1 = t[2*tx+1][c];
        __half2 hv(__float2half_rn(v0), __float2half_rn(v1));
        *(__half2*)(pos + (size_t)(cb + c) * ldout + rb + 2*tx) = hv;
    }
}

// ==================== split-fp16 mma.sync GEMM (3-stage pipeline) ==========
// TWOPASS=true : C = (Ah+Al) @ B^T  (2 MMA passes)
// TWOPASS=false: C = Ah @ B^T       (1 MMA pass)
// BTRANS=true  : B is [K,N] row-major (ldmatrix.trans) — AV path.
#define F_BIAS   1
#define F_RES    2
#define F_RELU   4
#define F_SCALE  8
#define F_CAUSAL 16
#define F_KCAUS  32
#define F_QKV    64

template<int BN, bool BTRANS, bool TWOPASS>
__global__ __launch_bounds__(256, 2) void gemm_mma(
    const __half* __restrict__ Ah, const __half* __restrict__ Al,
    const __half* __restrict__ Bs,
    const float* __restrict__ bias, const float* __restrict__ res,
    float* __restrict__ Cf, __half* __restrict__ Ch, __half* __restrict__ Cl,
    __half* __restrict__ C2, __half* __restrict__ C3,
    int K, int lda, int ldb, int ldc,
    int zH, long long sAb, long long sAh, long long sBb, long long sBh,
    long long sCb, long long sChh,
    int flags, float scale)
{
    constexpr int BM = 128, BK = 32;
    constexpr int ABYTES = BM * 40 * 2;    // 10240 (padded 80B rows)
    constexpr int NAPL = TWOPASS ? 2 : 1;
    constexpr int BOFF = NAPL * ABYTES;
    constexpr int BBYTES = BTRANS ? (BK * 144) : (BN * 40 * 2);
    constexpr int STAGE = BOFF + BBYTES;
    constexpr int WN = BN / 2;
    constexpr int NA = WN / 8;

    const int bm = blockIdx.y * BM, bn = blockIdx.x * BN;
    if ((flags & F_CAUSAL) && bn >= bm + BM) return;

    extern __shared__ char sm[];
    const uint32_t smb = smem_u32(sm);

    const int tid = threadIdx.x, lane = tid & 31, wid = tid >> 5;
    const int wm = wid & 3, wn = wid >> 2;

    const int z = blockIdx.z;
    const int bz = z / zH, hz = z % zH;
    const __half* pAh = Ah + bz * sAb + hz * sAh;
    const __half* pAl = TWOPASS ? (Al + bz * sAb + hz * sAh) : nullptr;
    const __half* pB  = Bs + bz * sBb + hz * sBh;
    float* pCf = Cf ? (Cf + bz * sCb + hz * sChh) : nullptr;
    __half* pCh = Ch ? (Ch + bz * sCb + hz * sChh) : nullptr;
    __half* pCl = Cl ? (Cl + bz * sCb + hz * sChh) : nullptr;
    const float* pres = res ? (res + bz * sCb + hz * sChh) : nullptr;

    int nKB = K >> 5;
    if (flags & F_KCAUS){
        int lim = (bm + BM) >> 5;
        if (lim < nKB) nKB = lim;
    }

    auto loadStage = [&](int kb, int s){
        const int k0 = kb * BK;
        const uint32_t stg = smb + s * STAGE;
#pragma unroll
        for (int i = 0; i < 2; i++){
            int idx = i * 256 + tid;
            int r = idx >> 2, c = idx & 3;
            uint32_t dst = stg + r * 80 + c * 16;
            CP16(dst, pAh + (size_t)(bm + r) * lda + k0 + c * 8);
            if (TWOPASS)
                CP16(dst + ABYTES, pAl + (size_t)(bm + r) * lda + k0 + c * 8);
        }
        if (BTRANS){
            int r = tid >> 3, c = tid & 7;
            uint32_t dst = stg + BOFF + r * 144 + c * 16;
            CP16(dst, pB + (size_t)(k0 + r) * ldb + bn + c * 8);
        } else {
#pragma unroll
            for (int i = 0; i < BN / 64; i++){
                int idx = i * 256 + tid;
                int r = idx >> 2, c = idx & 3;
                uint32_t dst = stg + BOFF + r * 80 + c * 16;
                CP16(dst, pB + (size_t)(bn + r) * ldb + k0 + c * 8);
            }
        }
        CP_COMMIT();
    };

    float acc[2][NA][4];
#pragma unroll
    for (int i = 0; i < 2; i++)
#pragma unroll
        for (int j = 0; j < NA; j++)
#pragma unroll
            for (int q = 0; q < 4; q++) acc[i][j][q] = 0.f;

    loadStage(0, 0);
    loadStage(1, 1);

    for (int kb = 0; kb < nKB; kb++){
        if (kb == nKB - 1) CP_WAIT0(); else CP_WAIT1();
        __syncthreads();
        if (kb + 2 < nKB){
            int s2 = kb + 2; while (s2 >= 3) s2 -= 3;
            loadStage(kb + 2, s2);
        }
        int s = kb; while (s >= 3) s -= 3;
        const uint32_t stg = smb + s * STAGE;
#pragma unroll
        for (int ks = 0; ks < 2; ks++){
            const int kc = ks * 16;
            uint32_t a_h[2][4], a_l[2][4];
#pragma unroll
            for (int mi = 0; mi < 2; mi++){
                int row = wm * 32 + mi * 16 + (lane & 15);
                int colb = (kc + ((lane >> 4) << 3)) * 2;
                uint32_t ad = stg + row * 80 + colb;
                LDSM4(a_h[mi][0], a_h[mi][1], a_h[mi][2], a_h[mi][3], ad);
                if (TWOPASS)
                    LDSM4(a_l[mi][0], a_l[mi][1], a_l[mi][2], a_l[mi][3], ad + ABYTES);
            }
            uint32_t b_s[NA][2];
            if (BTRANS){
#pragma unroll
                for (int p = 0; p < NA / 2; p++){
                    int g = lane >> 3, rr = lane & 7;
                    int row = kc + (g & 1) * 8 + rr;
                    int colb = (wn * WN + p * 16 + (g >> 1) * 8) * 2;
                    uint32_t ad = stg + BOFF + row * 144 + colb;
                    uint32_t r0, r1, r2, r3;
                    LDSM4T(r0, r1, r2, r3, ad);
                    b_s[2*p][0] = r0; b_s[2*p][1] = r1;
                    b_s[2*p+1][0] = r2; b_s[2*p+1][1] = r3;
                }
            } else {
#pragma unroll
                for (int p = 0; p < NA / 2; p++){
                    int rowb = wn * WN + p * 16 + (lane & 7) + ((lane >> 4) << 3);
                    int colb = (kc + (((lane >> 3) & 1) << 3)) * 2;
                    uint32_t ad = stg + BOFF + rowb * 80 + colb;
                    uint32_t r0, r1, r2, r3;
                    LDSM4(r0, r1, r2, r3, ad);
                    b_s[2*p][0] = r0; b_s[2*p][1] = r1;
                    b_s[2*p+1][0] = r2; b_s[2*p+1][1] = r3;
                }
            }
#pragma unroll
            for (int mi = 0; mi < 2; mi++)
#pragma unroll
                for (int ni = 0; ni < NA; ni++){
                    MMA16816(acc[mi][ni], a_h[mi], b_s[ni]);
                    if (TWOPASS)
                        MMA16816(acc[mi][ni], a_l[mi], b_s[ni]);
                }
        }
    }

    // epilogue
#pragma unroll
    for (int mi = 0; mi < 2; mi++){
#pragma unroll
        for (int ni = 0; ni < NA; ni++){
            int r0 = bm + wm * 32 + mi * 16 + (lane >> 2);
            int c0 = bn + wn * WN + ni * 8 + (lane & 3) * 2;
#pragma unroll
            for (int half = 0; half < 2; half++){
                int r = r0 + half * 8;
                float vx = acc[mi][ni][half * 2 + 0];
                float vy = acc[mi][ni][half * 2 + 1];
                if (flags & F_QKV){
                    // range 0 -> q (single plane, Ch); 1 -> k (C2); 2 -> v (C3)
                    int range = c0 >> 10, cc = c0 & 1023;
                    __half2 hv(__float2half_rn(vx), __float2half_rn(vy));
                    if (range == 0)
                        *(__half2*)(pCh + (size_t)r * ldc + cc) = hv;
                    else if (range == 1)
                        *(__half2*)(C2 + (size_t)r * ldc + cc) = hv;
                    else
                        *(__half2*)(C3 + (size_t)r * ldc + cc) = hv;
                    continue;
                }
                if (flags & F_SCALE){ vx *= scale; vy *= scale; }
                if (flags & F_BIAS){ vx += bias[c0]; vy += bias[c0 + 1]; }
                if (flags & F_RES){
                    const float* rp = pres + (size_t)r * ldc + c0;
                    vx += rp[0]; vy += rp[1];
                }
                if (flags & F_RELU){ vx = fmaxf(vx, 0.f); vy = fmaxf(vy, 0.f); }
                if (flags & F_CAUSAL){
                    if (c0 > r)     vx = -3.0e38f;
                    if (c0 + 1 > r) vy = -3.0e38f;
                }
                if (pCf){
                    float2 o2; o2.x = vx; o2.y = vy;
                    *(float2*)(pCf + (size_t)r * ldc + c0) = o2;
                }
                if (pCh){
                    __half hx = __float2half_rn(vx);
                    __half hy = __float2half_rn(vy);
                    *(__half2*)(pCh + (size_t)r * ldc + c0) = __half2(hx, hy);
                    if (pCl){
                        __half lx = __float2half_rn(vx - __half2float(hx));
                        __half ly = __float2half_rn(vy - __half2float(hy));
                        *(__half2*)(pCl + (size_t)r * ldc + c0) = __half2(lx, ly);
                    }
                }
            }
        }
    }
}

// ==================== host orchestration ====================
extern "C" void kernel_launch(void* const* d_in, const int* in_sizes, int n_in,
                              void* d_out, int out_size){
    (void)in_sizes; (void)n_in; (void)out_size;
    const int*   x     = (const int*)  d_in[0];
    const float* ce    = (const float*)d_in[1];
    const float* pe    = (const float*)d_in[2];
    const float* ln1_s = (const float*)d_in[5];
    const float* ln1_b = (const float*)d_in[6];
    const float* wq    = (const float*)d_in[7];
    const float* wk    = (const float*)d_in[8];
    const float* wv    = (const float*)d_in[9];
    const float* wo    = (const float*)d_in[10];
    const float* bo    = (const float*)d_in[11];
    const float* ln2_s = (const float*)d_in[12];
    const float* ln2_b = (const float*)d_in[13];
    const float* w1    = (const float*)d_in[14];
    const float* b1    = (const float*)d_in[15];
    const float* w2    = (const float*)d_in[16];
    const float* b2    = (const float*)d_in[17];
    const float* lnf_s = (const float*)d_in[18];
    const float* lnf_b = (const float*)d_in[19];
    const float* wf    = (const float*)d_in[20];
    const float* bf    = (const float*)d_in[21];

    float *h, *s;
    cudaGetSymbolAddress((void**)&h, g_h);
    cudaGetSymbolAddress((void**)&s, g_s);

    __half *yH,*yL,*qS,*kS,*vS,*oH,*oL,*aH,*sH;
    cudaGetSymbolAddress((void**)&yH, g_yH);  cudaGetSymbolAddress((void**)&yL, g_yL);
    cudaGetSymbolAddress((void**)&qS, g_qS);
    cudaGetSymbolAddress((void**)&kS, g_kS);
    cudaGetSymbolAddress((void**)&vS, g_vS);
    cudaGetSymbolAddress((void**)&oH, g_oH);  cudaGetSymbolAddress((void**)&oL, g_oL);
    cudaGetSymbolAddress((void**)&aH, g_aH);
    cudaGetSymbolAddress((void**)&sH, g_sH);

    __half *wqkvS,*woS,*w1S,*w2S,*wfS;
    cudaGetSymbolAddress((void**)&wqkvS, g_wqkvS);
    cudaGetSymbolAddress((void**)&woS, g_woS);
    cudaGetSymbolAddress((void**)&w1S, g_w1S);
    cudaGetSymbolAddress((void**)&w2S, g_w2S);
    cudaGetSymbolAddress((void**)&wfS, g_wfS);

    // dyn smem (3 stages):
    //  2-pass BN=128:          3*(20480+10240) = 92160
    //  1-pass BN=128:          3*(10240+10240) = 61440
    //  AV 1-pass BN=64 trans:  3*(10240+4608)  = 44544
    const int SM2P = 92160, SM1P = 61440, SMAV = 44544;
    cudaFuncSetAttribute((const void*)gemm_mma<128,false,true>,  cudaFuncAttributeMaxDynamicSharedMemorySize, SM2P);
    cudaFuncSetAttribute((const void*)gemm_mma<128,false,false>, cudaFuncAttributeMaxDynamicSharedMemorySize, SM1P);
    cudaFuncSetAttribute((const void*)gemm_mma<64,true,false>,   cudaFuncAttributeMaxDynamicSharedMemorySize, SMAV);

    dim3 cb(32, 8);
    const long long DD = (long long)Dn * Dn;
    const long long DF = (long long)Dn * FFn;
    // packed QKV weights: rows [0,1024)=wq^T, [1024,2048)=wk^T, [2048,3072)=wv^T
    convTh<<<dim3(Dn/32, Dn/64, Ln), cb>>>(wq, wqkvS,        Dn, Dn, 1, DD, 0, 3*DD, 0);
    convTh<<<dim3(Dn/32, Dn/64, Ln), cb>>>(wk, wqkvS + DD,   Dn, Dn, 1, DD, 0, 3*DD, 0);
    convTh<<<dim3(Dn/32, Dn/64, Ln), cb>>>(wv, wqkvS + 2*DD, Dn, Dn, 1, DD, 0, 3*DD, 0);
    convTh<<<dim3(Dn/32, Dn/64, Ln), cb>>>(wo, woS, Dn, Dn, 1, DD, 0, DD, 0);
    convTh<<<dim3(FFn/32, Dn/64, Ln), cb>>>(w1, w1S, FFn, Dn, 1, DF, 0, DF, 0);
    convTh<<<dim3(Dn/32, FFn/64, Ln), cb>>>(w2, w2S, Dn, FFn, 1, DF, 0, DF, 0);
    convTh<<<dim3(Vn/32, Dn/64, 1),  cb>>>(wf, wfS, Vn, Dn, 1, 0, 0, 0, 0);

    embed_k<<<(Mn * Dn) / 256, 256>>>(x, ce, pe);

    const long long SAB = (long long)Tn * Dn;   // per-batch stride in q/k/v/o
    const long long SS1 = (long long)Tn * Tn;   // per-bh stride in s

    for (int l = 0; l < Ln; l++){
        ln_k<<<Mn, 256>>>(h, yH, yL, ln1_s + l*Dn, ln1_b + l*Dn);

        // fused QKV (2-pass): q, k, v all single fp16 planes
        gemm_mma<128,false,true><<<dim3(24,16,1), 256, SM2P>>>(yH, yL,
            wqkvS + (size_t)l*3*DD,
            nullptr, nullptr, nullptr, qS, nullptr, kS, vS, Dn, Dn, Dn, Dn, 1,
            0,0,0,0,0,0, F_QKV, 1.f);

        // scores (1-pass): S[bh] = scale * Q K^T (causal) -> fp32
        gemm_mma<128,false,false><<<dim3(4,4,BHn), 256, SM1P>>>(qS, nullptr, kS,
            nullptr, nullptr, s, nullptr, nullptr, nullptr, nullptr,
            HSn, Dn, Dn, Tn, Hn, SAB, (long long)HSn, SAB, (long long)HSn,
            (long long)Hn*SS1, SS1, F_SCALE | F_CAUSAL, 0.125f);
        softmax_k<<<BHn*Tn, 128>>>();

        // O[bh] = S @ V (1-pass; V natural layout, trans frags; K truncated)
        gemm_mma<64,true,false><<<dim3(1,4,BHn), 256, SMAV>>>(sH, nullptr, vS,
            nullptr, nullptr, nullptr, oH, oL, nullptr, nullptr,
            Tn, Tn, Dn, Dn, Hn, (long long)Hn*SS1, SS1, SAB, (long long)HSn,
            SAB, (long long)HSn, F_KCAUS, 1.f);

        // O-proj (2-pass)
        gemm_mma<128,false,true><<<dim3(8,16,1), 256, SM2P>>>(oH, oL,
            woS + (size_t)l*DD,
            bo + l*Dn, h, h, nullptr, nullptr, nullptr, nullptr, Dn, Dn, Dn, Dn, 1,
            0,0,0,0,0,0, F_BIAS | F_RES, 1.f);

        ln_k<<<Mn, 256>>>(h, yH, yL, ln2_s + l*Dn, ln2_b + l*Dn);

        // MLP1 (1-pass): a = relu(y @ w1 + b1) -> single fp16 plane
        gemm_mma<128,false,false><<<dim3(32,16,1), 256, SM1P>>>(yH, nullptr,
            w1S + (size_t)l*DF,
            b1 + l*FFn, nullptr, nullptr, aH, nullptr, nullptr, nullptr,
            Dn, Dn, Dn, FFn, 1, 0,0,0,0,0,0, F_BIAS | F_RELU, 1.f);

        // MLP2 (1-pass): h += a @ w2 + b2
        gemm_mma<128,false,false><<<dim3(8,16,1), 256, SM1P>>>(aH, nullptr,
            w2S + (size_t)l*DF,
            b2 + l*Dn, h, h, nullptr, nullptr, nullptr, nullptr,
            FFn, FFn, FFn, Dn, 1, 0,0,0,0,0,0, F_BIAS | F_RES, 1.f);
    }

    ln_k<<<Mn, 256>>>(h, yH, yL, lnf_s, lnf_b);

    // logits (1-pass)
    gemm_mma<128,false,false><<<dim3(Vn/128, 16, 1), 256, SM1P>>>(yH, nullptr, wfS,
        bf, nullptr, (float*)d_out, nullptr, nullptr, nullptr, nullptr,
        Dn, Dn, Dn, Vn, 1, 0,0,0,0,0,0, F_BIAS, 1.f);
}

// round 12
// speedup vs baseline: 2.1739x; 1.0176x over previous
#include <cuda_runtime.h>
#include <cuda_fp16.h>
#include <cstdint>

#define Bn 4
#define Tn 512
#define Dn 1024
#define Hn 16
#define HSn 64
#define Ln 8
#define Vn 32000
#define Mn (Bn*Tn)       // 2048
#define FFn (4*Dn)       // 4096
#define BHn (Bn*Hn)      // 64

// ---------------- fp32 scratch ----------------
__device__ float g_h[Mn*Dn];

// ---------------- fp16 planes ----------------
__device__ __half g_yH[Mn*Dn],  g_yL[Mn*Dn];
__device__ __half g_qS[Mn*Dn];
__device__ __half g_kS[Mn*Dn];
__device__ __half g_vS[Mn*Dn];                    // natural [t, d] layout
__device__ __half g_oH[Mn*Dn],  g_oL[Mn*Dn];
__device__ __half g_aH[Mn*FFn];
__device__ __half g_s16[(size_t)BHn*Tn*Tn];       // raw scores (fp16)
__device__ __half g_sH[(size_t)BHn*Tn*Tn];        // softmax probs (fp16)

// ---------------- fp16 weights (NATIVE [K,N] row-major, single plane) ------
__device__ __half g_wqkvS[(size_t)Ln*3*Dn*Dn];   // [1024, 3072] per layer
__device__ __half g_woS[Ln*Dn*Dn];               // [1024, 1024]
__device__ __half g_w1S[Ln*Dn*FFn];              // [1024, 4096]
__device__ __half g_w2S[Ln*Dn*FFn];              // [4096, 1024]
__device__ __half g_wfS[(size_t)Dn*Vn];          // [1024, 32000]

// ==================== helpers ====================
__device__ __forceinline__ uint32_t smem_u32(const void* p){
    uint32_t a;
    asm("{ .reg .u64 t; cvta.to.shared.u64 t, %1; cvt.u32.u64 %0, t; }" : "=r"(a) : "l"(p));
    return a;
}
#define CP16(dst, src) \
    asm volatile("cp.async.cg.shared.global [%0], [%1], 16;" :: "r"(dst), "l"(src))
#define CP_COMMIT() asm volatile("cp.async.commit_group;" ::: "memory")
#define CP_WAIT1() asm volatile("cp.async.wait_group 1;" ::: "memory")
#define CP_WAIT0() asm volatile("cp.async.wait_group 0;" ::: "memory")

#define LDSM4(r0,r1,r2,r3,addr) \
    asm volatile("ldmatrix.sync.aligned.m8n8.x4.shared.b16 {%0,%1,%2,%3}, [%4];" \
        : "=r"(r0),"=r"(r1),"=r"(r2),"=r"(r3) : "r"(addr))
#define LDSM4T(r0,r1,r2,r3,addr) \
    asm volatile("ldmatrix.sync.aligned.m8n8.x4.trans.shared.b16 {%0,%1,%2,%3}, [%4];" \
        : "=r"(r0),"=r"(r1),"=r"(r2),"=r"(r3) : "r"(addr))

#define MMA16816(d, a, b) \
    asm volatile("mma.sync.aligned.m16n8k16.row.col.f32.f16.f16.f32 " \
        "{%0,%1,%2,%3}, {%4,%5,%6,%7}, {%8,%9}, {%0,%1,%2,%3};" \
        : "+f"((d)[0]),"+f"((d)[1]),"+f"((d)[2]),"+f"((d)[3]) \
        : "r"((a)[0]),"r"((a)[1]),"r"((a)[2]),"r"((a)[3]), "r"((b)[0]),"r"((b)[1]))

// ==================== reductions ====================
__device__ __forceinline__ float warpSum(float v){
#pragma unroll
    for (int o = 16; o > 0; o >>= 1) v += __shfl_down_sync(0xffffffffu, v, o);
    return v;
}
__device__ __forceinline__ float warpMax(float v){
#pragma unroll
    for (int o = 16; o > 0; o >>= 1) v = fmaxf(v, __shfl_down_sync(0xffffffffu, v, o));
    return v;
}
__device__ __forceinline__ float blockSum(float v, float* sh){
    int lane = threadIdx.x & 31, w = threadIdx.x >> 5;
    v = warpSum(v);
    __syncthreads();
    if (lane == 0) sh[w] = v;
    __syncthreads();
    int nw = blockDim.x >> 5;
    v = (threadIdx.x < (unsigned)nw) ? sh[threadIdx.x] : 0.f;
    if (w == 0) v = warpSum(v);
    if (threadIdx.x == 0) sh[0] = v;
    __syncthreads();
    return sh[0];
}
__device__ __forceinline__ float blockMax(float v, float* sh){
    int lane = threadIdx.x & 31, w = threadIdx.x >> 5;
    v = warpMax(v);
    __syncthreads();
    if (lane == 0) sh[w] = v;
    __syncthreads();
    int nw = blockDim.x >> 5;
    v = (threadIdx.x < (unsigned)nw) ? sh[threadIdx.x] : -3.0e38f;
    if (w == 0) v = warpMax(v);
    if (threadIdx.x == 0) sh[0] = v;
    __syncthreads();
    return sh[0];
}

// ==================== small kernels ====================
__global__ void embed_k(const int* __restrict__ x, const float* __restrict__ ce,
                        const float* __restrict__ pe){
    int idx = blockIdx.x * blockDim.x + threadIdx.x;
    int d  = idx & (Dn - 1);
    int mt = idx >> 10;
    int t  = mt & (Tn - 1);
    g_h[idx] = ce[(size_t)x[mt] * Dn + d] + pe[t * Dn + d];
}

// LayerNorm fused with fp16 hi/lo plane output (register-cached row)
__global__ __launch_bounds__(256) void ln_k(const float* __restrict__ in,
                                            __half* __restrict__ outH,
                                            __half* __restrict__ outL,
                                            const float* __restrict__ gs,
                                            const float* __restrict__ gb){
    __shared__ float sh[32];
    int row = blockIdx.x;
    const float4* xr = (const float4*)(in + (size_t)row * Dn);
    float4 vv = xr[threadIdx.x];
    float s  = vv.x + vv.y + vv.z + vv.w;
    float sq = vv.x*vv.x + vv.y*vv.y + vv.z*vv.z + vv.w*vv.w;
    s  = blockSum(s, sh);
    sq = blockSum(sq, sh);
    float mean = s * (1.f / Dn);
    float var  = sq * (1.f / Dn) - mean * mean;
    float r = rsqrtf(var + 1e-5f);
    int i0 = threadIdx.x * 4;
    float o[4];
    o[0] = (vv.x - mean) * r * gs[i0+0] + gb[i0+0];
    o[1] = (vv.y - mean) * r * gs[i0+1] + gb[i0+1];
    o[2] = (vv.z - mean) * r * gs[i0+2] + gb[i0+2];
    o[3] = (vv.w - mean) * r * gs[i0+3] + gb[i0+3];
    __half2 h2[2], l2[2];
#pragma unroll
    for (int p = 0; p < 2; p++){
        __half hx = __float2half_rn(o[2*p]);
        __half hy = __float2half_rn(o[2*p+1]);
        h2[p] = __half2(hx, hy);
        l2[p] = __half2(__float2half_rn(o[2*p]   - __half2float(hx)),
                        __float2half_rn(o[2*p+1] - __half2float(hy)));
    }
    *(uint2*)(outH + (size_t)row * Dn + i0) = *(uint2*)h2;
    *(uint2*)(outL + (size_t)row * Dn + i0) = *(uint2*)l2;
}

// causal softmax over fp16 scores, single fp16 plane out, zero fill to AV tile edge
__global__ __launch_bounds__(128) void softmax_k(){
    __shared__ float sh[32];
    int row = blockIdx.x;           // 0 .. BHn*Tn-1
    int i = row & (Tn - 1);
    int zend = ((i >> 7) + 1) << 7; // AV reads cols < zend only
    const __half* sr = g_s16 + (size_t)row * Tn;
    __half* ph = g_sH + (size_t)row * Tn;
    float vals[4];
    float mx = -3.0e38f;
#pragma unroll
    for (int p = 0; p < 4; p++){
        int j = threadIdx.x + p * 128;
        vals[p] = (j <= i) ? __half2float(sr[j]) : -3.0e38f;
        mx = fmaxf(mx, vals[p]);
    }
    mx = blockMax(mx, sh);
    float sum = 0.f;
#pragma unroll
    for (int p = 0; p < 4; p++){
        int j = threadIdx.x + p * 128;
        float e = (j <= i) ? expf(vals[p] - mx) : 0.f;
        vals[p] = e;
        sum += e;
    }
    sum = blockSum(sum, sh);
    float inv = 1.f / sum;
#pragma unroll
    for (int p = 0; p < 4; p++){
        int j = threadIdx.x + p * 128;
        if (j < zend)
            ph[j] = __float2half_rn(vals[p] * inv);
    }
}

// streaming fp32 -> fp16 convert, no transpose.
// out[r*ldout + colofs + c] = half(in[r*cols + c]); blockIdx.y = z slab.
__global__ __launch_bounds__(256) void convS_k(const float* __restrict__ in,
                                               __half* __restrict__ out,
                                               int cols, int ldout, int colofs,
                                               long long sIz, long long sOz){
    const float* pin = in + blockIdx.y * sIz;
    __half* pos = out + blockIdx.y * sOz;
    int idx = blockIdx.x * blockDim.x + threadIdx.x;   // over (rows*cols)/8
    int n8 = cols >> 3;
    int r = idx / n8, c = (idx - r * n8) << 3;
    const float4* src = (const float4*)(pin + (size_t)r * cols + c);
    float4 v0 = src[0], v1 = src[1];
    __half2 h[4];
    h[0] = __half2(__float2half_rn(v0.x), __float2half_rn(v0.y));
    h[1] = __half2(__float2half_rn(v0.z), __float2half_rn(v0.w));
    h[2] = __half2(__float2half_rn(v1.x), __float2half_rn(v1.y));
    h[3] = __half2(__float2half_rn(v1.z), __float2half_rn(v1.w));
    *(uint4*)(pos + (size_t)r * ldout + colofs + c) = *(uint4*)h;
}

// ==================== split-fp16 mma.sync GEMM (3-stage pipeline) ==========
// TWOPASS=true : C = (Ah+Al) @ B  (2 MMA passes)
// TWOPASS=false: C = Ah @ B       (1 MMA pass)
// BTRANS=true  : B is [K,N] row-major (ldmatrix.trans) — weights & V.
// BTRANS=false : B is [N,K] K-major — scores (B = K tensor).
#define F_BIAS   1
#define F_RES    2
#define F_RELU   4
#define F_SCALE  8
#define F_CAUSAL 16
#define F_KCAUS  32
#define F_QKV    64

template<int BN, bool BTRANS, bool TWOPASS>
__global__ __launch_bounds__(256, 2) void gemm_mma(
    const __half* __restrict__ Ah, const __half* __restrict__ Al,
    const __half* __restrict__ Bs,
    const float* __restrict__ bias, const float* __restrict__ res,
    float* __restrict__ Cf, __half* __restrict__ Ch, __half* __restrict__ Cl,
    __half* __restrict__ C2, __half* __restrict__ C3,
    int K, int lda, int ldb, int ldc,
    int zH, long long sAb, long long sAh, long long sBb, long long sBh,
    long long sCb, long long sChh,
    int flags, float scale)
{
    constexpr int BM = 128, BK = 32;
    constexpr int ABYTES = BM * 40 * 2;    // 10240 (padded 80B rows)
    constexpr int NAPL = TWOPASS ? 2 : 1;
    constexpr int BOFF = NAPL * ABYTES;
    constexpr int BPITCH = BTRANS ? (BN * 2 + 16) : 80;   // 272/144 or 80
    constexpr int BBYTES = BTRANS ? (BK * BPITCH) : (BN * 80);
    constexpr int STAGE = BOFF + BBYTES;
    constexpr int WN = BN / 2;
    constexpr int NA = WN / 8;

    const int bm = blockIdx.y * BM, bn = blockIdx.x * BN;
    if ((flags & F_CAUSAL) && bn >= bm + BM) return;

    extern __shared__ char sm[];
    const uint32_t smb = smem_u32(sm);

    const int tid = threadIdx.x, lane = tid & 31, wid = tid >> 5;
    const int wm = wid & 3, wn = wid >> 2;

    const int z = blockIdx.z;
    const int bz = z / zH, hz = z % zH;
    const __half* pAh = Ah + bz * sAb + hz * sAh;
    const __half* pAl = TWOPASS ? (Al + bz * sAb + hz * sAh) : nullptr;
    const __half* pB  = Bs + bz * sBb + hz * sBh;
    float* pCf = Cf ? (Cf + bz * sCb + hz * sChh) : nullptr;
    __half* pCh = Ch ? (Ch + bz * sCb + hz * sChh) : nullptr;
    __half* pCl = Cl ? (Cl + bz * sCb + hz * sChh) : nullptr;
    const float* pres = res ? (res + bz * sCb + hz * sChh) : nullptr;

    int nKB = K >> 5;
    if (flags & F_KCAUS){
        int lim = (bm + BM) >> 5;
        if (lim < nKB) nKB = lim;
    }

    auto loadStage = [&](int kb, int s){
        const int k0 = kb * BK;
        const uint32_t stg = smb + s * STAGE;
#pragma unroll
        for (int i = 0; i < 2; i++){
            int idx = i * 256 + tid;
            int r = idx >> 2, c = idx & 3;
            uint32_t dst = stg + r * 80 + c * 16;
            CP16(dst, pAh + (size_t)(bm + r) * lda + k0 + c * 8);
            if (TWOPASS)
                CP16(dst + ABYTES, pAl + (size_t)(bm + r) * lda + k0 + c * 8);
        }
        if (BTRANS){
            constexpr int CPR = BN / 8;            // 16B chunks per row
#pragma unroll
            for (int i = 0; i < (BK * CPR) / 256; i++){
                int idx = i * 256 + tid;
                int r = idx / CPR, c = idx % CPR;
                uint32_t dst = stg + BOFF + r * BPITCH + c * 16;
                CP16(dst, pB + (size_t)(k0 + r) * ldb + bn + c * 8);
            }
        } else {
#pragma unroll
            for (int i = 0; i < BN / 64; i++){
                int idx = i * 256 + tid;
                int r = idx >> 2, c = idx & 3;
                uint32_t dst = stg + BOFF + r * 80 + c * 16;
                CP16(dst, pB + (size_t)(bn + r) * ldb + k0 + c * 8);
            }
        }
        CP_COMMIT();
    };

    float acc[2][NA][4];
#pragma unroll
    for (int i = 0; i < 2; i++)
#pragma unroll
        for (int j = 0; j < NA; j++)
#pragma unroll
            for (int q = 0; q < 4; q++) acc[i][j][q] = 0.f;

    loadStage(0, 0);
    loadStage(1, 1);

    for (int kb = 0; kb < nKB; kb++){
        if (kb == nKB - 1) CP_WAIT0(); else CP_WAIT1();
        __syncthreads();
        if (kb + 2 < nKB){
            int s2 = kb + 2; while (s2 >= 3) s2 -= 3;
            loadStage(kb + 2, s2);
        }
        int s = kb; while (s >= 3) s -= 3;
        const uint32_t stg = smb + s * STAGE;
#pragma unroll
        for (int ks = 0; ks < 2; ks++){
            const int kc = ks * 16;
            uint32_t a_h[2][4], a_l[2][4];
#pragma unroll
            for (int mi = 0; mi < 2; mi++){
                int row = wm * 32 + mi * 16 + (lane & 15);
                int colb = (kc + ((lane >> 4) << 3)) * 2;
                uint32_t ad = stg + row * 80 + colb;
                LDSM4(a_h[mi][0], a_h[mi][1], a_h[mi][2], a_h[mi][3], ad);
                if (TWOPASS)
                    LDSM4(a_l[mi][0], a_l[mi][1], a_l[mi][2], a_l[mi][3], ad + ABYTES);
            }
            uint32_t b_s[NA][2];
            if (BTRANS){
#pragma unroll
                for (int p = 0; p < NA / 2; p++){
                    int g = lane >> 3, rr = lane & 7;
                    int row = kc + (g & 1) * 8 + rr;
                    int colb = (wn * WN + p * 16 + (g >> 1) * 8) * 2;
                    uint32_t ad = stg + BOFF + row * BPITCH + colb;
                    uint32_t r0, r1, r2, r3;
                    LDSM4T(r0, r1, r2, r3, ad);
                    b_s[2*p][0] = r0; b_s[2*p][1] = r1;
                    b_s[2*p+1][0] = r2; b_s[2*p+1][1] = r3;
                }
            } else {
#pragma unroll
                for (int p = 0; p < NA / 2; p++){
                    int rowb = wn * WN + p * 16 + (lane & 7) + ((lane >> 4) << 3);
                    int colb = (kc + (((lane >> 3) & 1) << 3)) * 2;
                    uint32_t ad = stg + BOFF + rowb * 80 + colb;
                    uint32_t r0, r1, r2, r3;
                    LDSM4(r0, r1, r2, r3, ad);
                    b_s[2*p][0] = r0; b_s[2*p][1] = r1;
                    b_s[2*p+1][0] = r2; b_s[2*p+1][1] = r3;
                }
            }
#pragma unroll
            for (int mi = 0; mi < 2; mi++)
#pragma unroll
                for (int ni = 0; ni < NA; ni++){
                    MMA16816(acc[mi][ni], a_h[mi], b_s[ni]);
                    if (TWOPASS)
                        MMA16816(acc[mi][ni], a_l[mi], b_s[ni]);
                }
        }
    }

    // epilogue
#pragma unroll
    for (int mi = 0; mi < 2; mi++){
#pragma unroll
        for (int ni = 0; ni < NA; ni++){
            int r0 = bm + wm * 32 + mi * 16 + (lane >> 2);
            int c0 = bn + wn * WN + ni * 8 + (lane & 3) * 2;
#pragma unroll
            for (int half = 0; half < 2; half++){
                int r = r0 + half * 8;
                float vx = acc[mi][ni][half * 2 + 0];
                float vy = acc[mi][ni][half * 2 + 1];
                if (flags & F_QKV){
                    // range 0 -> q (Ch); 1 -> k (C2); 2 -> v (C3)
                    int range = c0 >> 10, cc = c0 & 1023;
                    __half2 hv(__float2half_rn(vx), __float2half_rn(vy));
                    if (range == 0)
                        *(__half2*)(pCh + (size_t)r * ldc + cc) = hv;
                    else if (range == 1)
                        *(__half2*)(C2 + (size_t)r * ldc + cc) = hv;
                    else
                        *(__half2*)(C3 + (size_t)r * ldc + cc) = hv;
                    continue;
                }
                if (flags & F_SCALE){ vx *= scale; vy *= scale; }
                if (flags & F_BIAS){ vx += bias[c0]; vy += bias[c0 + 1]; }
                if (flags & F_RES){
                    const float* rp = pres + (size_t)r * ldc + c0;
                    vx += rp[0]; vy += rp[1];
                }
                if (flags & F_RELU){ vx = fmaxf(vx, 0.f); vy = fmaxf(vy, 0.f); }
                if (flags & F_CAUSAL){
                    if (c0 > r)     vx = -3.0e38f;
                    if (c0 + 1 > r) vy = -3.0e38f;
                }
                if (pCf){
                    float2 o2; o2.x = vx; o2.y = vy;
                    *(float2*)(pCf + (size_t)r * ldc + c0) = o2;
                }
                if (pCh){
                    __half hx = __float2half_rn(vx);
                    __half hy = __float2half_rn(vy);
                    *(__half2*)(pCh + (size_t)r * ldc + c0) = __half2(hx, hy);
                    if (pCl){
                        __half lx = __float2half_rn(vx - __half2float(hx));
                        __half ly = __float2half_rn(vy - __half2float(hy));
                        *(__half2*)(pCl + (size_t)r * ldc + c0) = __half2(lx, ly);
                    }
                }
            }
        }
    }
}

// ==================== host orchestration ====================
extern "C" void kernel_launch(void* const* d_in, const int* in_sizes, int n_in,
                              void* d_out, int out_size){
    (void)in_sizes; (void)n_in; (void)out_size;
    const int*   x     = (const int*)  d_in[0];
    const float* ce    = (const float*)d_in[1];
    const float* pe    = (const float*)d_in[2];
    const float* ln1_s = (const float*)d_in[5];
    const float* ln1_b = (const float*)d_in[6];
    const float* wq    = (const float*)d_in[7];
    const float* wk    = (const float*)d_in[8];
    const float* wv    = (const float*)d_in[9];
    const float* wo    = (const float*)d_in[10];
    const float* bo    = (const float*)d_in[11];
    const float* ln2_s = (const float*)d_in[12];
    const float* ln2_b = (const float*)d_in[13];
    const float* w1    = (const float*)d_in[14];
    const float* b1    = (const float*)d_in[15];
    const float* w2    = (const float*)d_in[16];
    const float* b2    = (const float*)d_in[17];
    const float* lnf_s = (const float*)d_in[18];
    const float* lnf_b = (const float*)d_in[19];
    const float* wf    = (const float*)d_in[20];
    const float* bf    = (const float*)d_in[21];

    float *h;
    cudaGetSymbolAddress((void**)&h, g_h);

    __half *yH,*yL,*qS,*kS,*vS,*oH,*oL,*aH,*s16,*sH;
    cudaGetSymbolAddress((void**)&yH, g_yH);  cudaGetSymbolAddress((void**)&yL, g_yL);
    cudaGetSymbolAddress((void**)&qS, g_qS);
    cudaGetSymbolAddress((void**)&kS, g_kS);
    cudaGetSymbolAddress((void**)&vS, g_vS);
    cudaGetSymbolAddress((void**)&oH, g_oH);  cudaGetSymbolAddress((void**)&oL, g_oL);
    cudaGetSymbolAddress((void**)&aH, g_aH);
    cudaGetSymbolAddress((void**)&s16, g_s16);
    cudaGetSymbolAddress((void**)&sH, g_sH);

    __half *wqkvS,*woS,*w1S,*w2S,*wfS;
    cudaGetSymbolAddress((void**)&wqkvS, g_wqkvS);
    cudaGetSymbolAddress((void**)&woS, g_woS);
    cudaGetSymbolAddress((void**)&w1S, g_w1S);
    cudaGetSymbolAddress((void**)&w2S, g_w2S);
    cudaGetSymbolAddress((void**)&wfS, g_wfS);

    // dyn smem (3 stages):
    //  QKV/O-proj 2-pass BN=128 BTRANS: 3*(20480 + 32*272) = 3*29184 = 87552
    //  MLP/logits 1-pass BN=128 BTRANS: 3*(10240 + 8704)   = 56832
    //  scores     1-pass BN=128 K-major:3*(10240 + 10240)  = 61440
    //  AV         1-pass BN=64  BTRANS: 3*(10240 + 4608)   = 44544
    const int SM2T = 87552, SM1T = 56832, SMSC = 61440, SMAV = 44544;
    cudaFuncSetAttribute((const void*)gemm_mma<128,true,true>,   cudaFuncAttributeMaxDynamicSharedMemorySize, SM2T);
    cudaFuncSetAttribute((const void*)gemm_mma<128,true,false>,  cudaFuncAttributeMaxDynamicSharedMemorySize, SM1T);
    cudaFuncSetAttribute((const void*)gemm_mma<128,false,false>, cudaFuncAttributeMaxDynamicSharedMemorySize, SMSC);
    cudaFuncSetAttribute((const void*)gemm_mma<64,true,false>,   cudaFuncAttributeMaxDynamicSharedMemorySize, SMAV);

    const long long DD = (long long)Dn * Dn;
    const long long DF = (long long)Dn * FFn;

    // weight converts (streaming, no transpose). wqkv packed along N: cols 0-1023=wq,...
    convS_k<<<dim3(DD/2048, Ln), 256>>>(wq, wqkvS, Dn, 3*Dn, 0,      DD, 3*DD);
    convS_k<<<dim3(DD/2048, Ln), 256>>>(wk, wqkvS, Dn, 3*Dn, Dn,     DD, 3*DD);
    convS_k<<<dim3(DD/2048, Ln), 256>>>(wv, wqkvS, Dn, 3*Dn, 2*Dn,   DD, 3*DD);
    convS_k<<<dim3(DD/2048, Ln), 256>>>(wo, woS, Dn, Dn, 0,          DD, DD);
    convS_k<<<dim3(DF/2048, Ln), 256>>>(w1, w1S, FFn, FFn, 0,        DF, DF);
    convS_k<<<dim3(DF/2048, Ln), 256>>>(w2, w2S, Dn, Dn, 0,          DF, DF);
    convS_k<<<dim3(((long long)Dn*Vn)/2048, 1), 256>>>(wf, wfS, Vn, Vn, 0, 0, 0);

    embed_k<<<(Mn * Dn) / 256, 256>>>(x, ce, pe);

    const long long SAB = (long long)Tn * Dn;   // per-batch stride in q/k/v/o
    const long long SS1 = (long long)Tn * Tn;   // per-bh stride in s

    for (int l = 0; l < Ln; l++){
        ln_k<<<Mn, 256>>>(h, yH, yL, ln1_s + l*Dn, ln1_b + l*Dn);

        // fused QKV (2-pass, B native [1024,3072]): q, k, v single fp16 planes
        gemm_mma<128,true,true><<<dim3(24,16,1), 256, SM2T>>>(yH, yL,
            wqkvS + (size_t)l*3*DD,
            nullptr, nullptr, nullptr, qS, nullptr, kS, vS, Dn, Dn, 3*Dn, Dn, 1,
            0,0,0,0,0,0, F_QKV, 1.f);

        // scores (1-pass, K-major B = kS): S16 = scale * Q K^T (causal), fp16 out
        gemm_mma<128,false,false><<<dim3(4,4,BHn), 256, SMSC>>>(qS, nullptr, kS,
            nullptr, nullptr, nullptr, s16, nullptr, nullptr, nullptr,
            HSn, Dn, Dn, Tn, Hn, SAB, (long long)HSn, SAB, (long long)HSn,
            (long long)Hn*SS1, SS1, F_SCALE | F_CAUSAL, 0.125f);
        softmax_k<<<BHn*Tn, 128>>>();

        // O[bh] = S @ V (1-pass; V natural layout; K truncated)
        gemm_mma<64,true,false><<<dim3(1,4,BHn), 256, SMAV>>>(sH, nullptr, vS,
            nullptr, nullptr, nullptr, oH, oL, nullptr, nullptr,
            Tn, Tn, Dn, Dn, Hn, (long long)Hn*SS1, SS1, SAB, (long long)HSn,
            SAB, (long long)HSn, F_KCAUS, 1.f);

        // O-proj (2-pass, B native [1024,1024])
        gemm_mma<128,true,true><<<dim3(8,16,1), 256, SM2T>>>(oH, oL,
            woS + (size_t)l*DD,
            bo + l*Dn, h, h, nullptr, nullptr, nullptr, nullptr, Dn, Dn, Dn, Dn, 1,
            0,0,0,0,0,0, F_BIAS | F_RES, 1.f);

        ln_k<<<Mn, 256>>>(h, yH, yL, ln2_s + l*Dn, ln2_b + l*Dn);

        // MLP1 (1-pass, B native [1024,4096]): a = relu(y @ w1 + b1)
        gemm_mma<128,true,false><<<dim3(32,16,1), 256, SM1T>>>(yH, nullptr,
            w1S + (size_t)l*DF,
            b1 + l*FFn, nullptr, nullptr, aH, nullptr, nullptr, nullptr,
            Dn, Dn, FFn, FFn, 1, 0,0,0,0,0,0, F_BIAS | F_RELU, 1.f);

        // MLP2 (1-pass, B native [4096,1024]): h += a @ w2 + b2
        gemm_mma<128,true,false><<<dim3(8,16,1), 256, SM1T>>>(aH, nullptr,
            w2S + (size_t)l*DF,
            b2 + l*Dn, h, h, nullptr, nullptr, nullptr, nullptr,
            FFn, FFn, Dn, Dn, 1, 0,0,0,0,0,0, F_BIAS | F_RES, 1.f);
    }

    ln_k<<<Mn, 256>>>(h, yH, yL, lnf_s, lnf_b);

    // logits (1-pass, B native [1024,32000])
    gemm_mma<128,true,false><<<dim3(Vn/128, 16, 1), 256, SM1T>>>(yH, nullptr, wfS,
        bf, nullptr, (float*)d_out, nullptr, nullptr, nullptr, nullptr,
        Dn, Dn, Vn, Vn, 1, 0,0,0,0,0,0, F_BIAS, 1.f);
}

// round 13
// speedup vs baseline: 2.4628x; 1.1329x over previous
#include <cuda_runtime.h>
#include <cuda_fp16.h>
#include <cstdint>

#define Bn 4
#define Tn 512
#define Dn 1024
#define Hn 16
#define HSn 64
#define Ln 8
#define Vn 32000
#define Mn (Bn*Tn)       // 2048
#define FFn (4*Dn)       // 4096
#define BHn (Bn*Hn)      // 64

// ---------------- fp32 scratch ----------------
__device__ float g_h[Mn*Dn];

// ---------------- fp16 planes ----------------
__device__ __half g_yS[Mn*Dn];
__device__ __half g_qS[Mn*Dn];
__device__ __half g_kS[Mn*Dn];
__device__ __half g_vS[Mn*Dn];                    // natural [t, d] layout
__device__ __half g_oS[Mn*Dn];
__device__ __half g_aS[Mn*FFn];
__device__ __half g_s16[(size_t)BHn*Tn*Tn];       // raw scores (fp16)
__device__ __half g_sH[(size_t)BHn*Tn*Tn];        // softmax probs (fp16)

// ---------------- fp16 weights (NATIVE [K,N] row-major, single plane) ------
__device__ __half g_wqkvS[(size_t)Ln*3*Dn*Dn];   // [1024, 3072] per layer
__device__ __half g_woS[Ln*Dn*Dn];               // [1024, 1024]
__device__ __half g_w1S[Ln*Dn*FFn];              // [1024, 4096]
__device__ __half g_w2S[Ln*Dn*FFn];              // [4096, 1024]
__device__ __half g_wfS[(size_t)Dn*Vn];          // [1024, 32000]

// ==================== helpers ====================
__device__ __forceinline__ uint32_t smem_u32(const void* p){
    uint32_t a;
    asm("{ .reg .u64 t; cvta.to.shared.u64 t, %1; cvt.u32.u64 %0, t; }" : "=r"(a) : "l"(p));
    return a;
}
#define CP16(dst, src) \
    asm volatile("cp.async.cg.shared.global [%0], [%1], 16;" :: "r"(dst), "l"(src))
#define CP_COMMIT() asm volatile("cp.async.commit_group;" ::: "memory")
#define CP_WAIT1() asm volatile("cp.async.wait_group 1;" ::: "memory")
#define CP_WAIT0() asm volatile("cp.async.wait_group 0;" ::: "memory")

#define LDSM4(r0,r1,r2,r3,addr) \
    asm volatile("ldmatrix.sync.aligned.m8n8.x4.shared.b16 {%0,%1,%2,%3}, [%4];" \
        : "=r"(r0),"=r"(r1),"=r"(r2),"=r"(r3) : "r"(addr))
#define LDSM4T(r0,r1,r2,r3,addr) \
    asm volatile("ldmatrix.sync.aligned.m8n8.x4.trans.shared.b16 {%0,%1,%2,%3}, [%4];" \
        : "=r"(r0),"=r"(r1),"=r"(r2),"=r"(r3) : "r"(addr))

#define MMA16816(d, a, b) \
    asm volatile("mma.sync.aligned.m16n8k16.row.col.f32.f16.f16.f32 " \
        "{%0,%1,%2,%3}, {%4,%5,%6,%7}, {%8,%9}, {%0,%1,%2,%3};" \
        : "+f"((d)[0]),"+f"((d)[1]),"+f"((d)[2]),"+f"((d)[3]) \
        : "r"((a)[0]),"r"((a)[1]),"r"((a)[2]),"r"((a)[3]), "r"((b)[0]),"r"((b)[1]))

// ==================== reductions ====================
__device__ __forceinline__ float warpSum(float v){
#pragma unroll
    for (int o = 16; o > 0; o >>= 1) v += __shfl_down_sync(0xffffffffu, v, o);
    return v;
}
__device__ __forceinline__ float warpMax(float v){
#pragma unroll
    for (int o = 16; o > 0; o >>= 1) v = fmaxf(v, __shfl_down_sync(0xffffffffu, v, o));
    return v;
}
__device__ __forceinline__ float blockSum(float v, float* sh){
    int lane = threadIdx.x & 31, w = threadIdx.x >> 5;
    v = warpSum(v);
    __syncthreads();
    if (lane == 0) sh[w] = v;
    __syncthreads();
    int nw = blockDim.x >> 5;
    v = (threadIdx.x < (unsigned)nw) ? sh[threadIdx.x] : 0.f;
    if (w == 0) v = warpSum(v);
    if (threadIdx.x == 0) sh[0] = v;
    __syncthreads();
    return sh[0];
}
__device__ __forceinline__ float blockMax(float v, float* sh){
    int lane = threadIdx.x & 31, w = threadIdx.x >> 5;
    v = warpMax(v);
    __syncthreads();
    if (lane == 0) sh[w] = v;
    __syncthreads();
    int nw = blockDim.x >> 5;
    v = (threadIdx.x < (unsigned)nw) ? sh[threadIdx.x] : -3.0e38f;
    if (w == 0) v = warpMax(v);
    if (threadIdx.x == 0) sh[0] = v;
    __syncthreads();
    return sh[0];
}

// ==================== small kernels ====================
__global__ void embed_k(const int* __restrict__ x, const float* __restrict__ ce,
                        const float* __restrict__ pe){
    int idx = blockIdx.x * blockDim.x + threadIdx.x;
    int d  = idx & (Dn - 1);
    int mt = idx >> 10;
    int t  = mt & (Tn - 1);
    g_h[idx] = ce[(size_t)x[mt] * Dn + d] + pe[t * Dn + d];
}

// LayerNorm fused with single fp16 plane output (register-cached row)
__global__ __launch_bounds__(256) void ln_k(const float* __restrict__ in,
                                            __half* __restrict__ outH,
                                            const float* __restrict__ gs,
                                            const float* __restrict__ gb){
    __shared__ float sh[32];
    int row = blockIdx.x;
    const float4* xr = (const float4*)(in + (size_t)row * Dn);
    float4 vv = xr[threadIdx.x];
    float s  = vv.x + vv.y + vv.z + vv.w;
    float sq = vv.x*vv.x + vv.y*vv.y + vv.z*vv.z + vv.w*vv.w;
    s  = blockSum(s, sh);
    sq = blockSum(sq, sh);
    float mean = s * (1.f / Dn);
    float var  = sq * (1.f / Dn) - mean * mean;
    float r = rsqrtf(var + 1e-5f);
    int i0 = threadIdx.x * 4;
    float o[4];
    o[0] = (vv.x - mean) * r * gs[i0+0] + gb[i0+0];
    o[1] = (vv.y - mean) * r * gs[i0+1] + gb[i0+1];
    o[2] = (vv.z - mean) * r * gs[i0+2] + gb[i0+2];
    o[3] = (vv.w - mean) * r * gs[i0+3] + gb[i0+3];
    __half2 h2[2];
    h2[0] = __half2(__float2half_rn(o[0]), __float2half_rn(o[1]));
    h2[1] = __half2(__float2half_rn(o[2]), __float2half_rn(o[3]));
    *(uint2*)(outH + (size_t)row * Dn + i0) = *(uint2*)h2;
}

// causal softmax over fp16 scores, single fp16 plane out, zero fill to AV tile edge
__global__ __launch_bounds__(128) void softmax_k(){
    __shared__ float sh[32];
    int row = blockIdx.x;           // 0 .. BHn*Tn-1
    int i = row & (Tn - 1);
    int zend = ((i >> 7) + 1) << 7; // AV reads cols < zend only
    const __half* sr = g_s16 + (size_t)row * Tn;
    __half* ph = g_sH + (size_t)row * Tn;
    float vals[4];
    float mx = -3.0e38f;
#pragma unroll
    for (int p = 0; p < 4; p++){
        int j = threadIdx.x + p * 128;
        vals[p] = (j <= i) ? __half2float(sr[j]) : -3.0e38f;
        mx = fmaxf(mx, vals[p]);
    }
    mx = blockMax(mx, sh);
    float sum = 0.f;
#pragma unroll
    for (int p = 0; p < 4; p++){
        int j = threadIdx.x + p * 128;
        float e = (j <= i) ? expf(vals[p] - mx) : 0.f;
        vals[p] = e;
        sum += e;
    }
    sum = blockSum(sum, sh);
    float inv = 1.f / sum;
#pragma unroll
    for (int p = 0; p < 4; p++){
        int j = threadIdx.x + p * 128;
        if (j < zend)
            ph[j] = __float2half_rn(vals[p] * inv);
    }
}

// streaming fp32 -> fp16 convert, no transpose.
__global__ __launch_bounds__(256) void convS_k(const float* __restrict__ in,
                                               __half* __restrict__ out,
                                               int cols, int ldout, int colofs,
                                               long long sIz, long long sOz){
    const float* pin = in + blockIdx.y * sIz;
    __half* pos = out + blockIdx.y * sOz;
    int idx = blockIdx.x * blockDim.x + threadIdx.x;   // over (rows*cols)/8
    int n8 = cols >> 3;
    int r = idx / n8, c = (idx - r * n8) << 3;
    const float4* src = (const float4*)(pin + (size_t)r * cols + c);
    float4 v0 = src[0], v1 = src[1];
    __half2 h[4];
    h[0] = __half2(__float2half_rn(v0.x), __float2half_rn(v0.y));
    h[1] = __half2(__float2half_rn(v0.z), __float2half_rn(v0.w));
    h[2] = __half2(__float2half_rn(v1.x), __float2half_rn(v1.y));
    h[3] = __half2(__float2half_rn(v1.z), __float2half_rn(v1.w));
    *(uint4*)(pos + (size_t)r * ldout + colofs + c) = *(uint4*)h;
}

// ==================== fp16 mma.sync GEMM (3-stage pipeline, 1-pass) ========
// BTRANS=true  : B is [K,N] row-major (ldmatrix.trans) — weights & V.
// BTRANS=false : B is [N,K] K-major — scores (B = K tensor).
#define F_BIAS   1
#define F_RES    2
#define F_RELU   4
#define F_SCALE  8
#define F_CAUSAL 16
#define F_KCAUS  32
#define F_QKV    64

template<int BN, bool BTRANS>
__global__ __launch_bounds__(256, 2) void gemm_mma(
    const __half* __restrict__ Ah,
    const __half* __restrict__ Bs,
    const float* __restrict__ bias, const float* __restrict__ res,
    float* __restrict__ Cf, __half* __restrict__ Ch,
    __half* __restrict__ C2, __half* __restrict__ C3,
    int K, int lda, int ldb, int ldc,
    int zH, long long sAb, long long sAh, long long sBb, long long sBh,
    long long sCb, long long sChh,
    int flags, float scale)
{
    constexpr int BM = 128, BK = 32;
    constexpr int ABYTES = BM * 40 * 2;    // 10240 (padded 80B rows)
    constexpr int BPITCH = BTRANS ? (BN * 2 + 16) : 80;
    constexpr int BBYTES = BTRANS ? (BK * BPITCH) : (BN * 80);
    constexpr int STAGE = ABYTES + BBYTES;
    constexpr int WN = BN / 2;
    constexpr int NA = WN / 8;

    const int bm = blockIdx.y * BM, bn = blockIdx.x * BN;
    if ((flags & F_CAUSAL) && bn >= bm + BM) return;

    extern __shared__ char sm[];
    const uint32_t smb = smem_u32(sm);

    const int tid = threadIdx.x, lane = tid & 31, wid = tid >> 5;
    const int wm = wid & 3, wn = wid >> 2;

    const int z = blockIdx.z;
    const int bz = z / zH, hz = z % zH;
    const __half* pAh = Ah + bz * sAb + hz * sAh;
    const __half* pB  = Bs + bz * sBb + hz * sBh;
    float* pCf = Cf ? (Cf + bz * sCb + hz * sChh) : nullptr;
    __half* pCh = Ch ? (Ch + bz * sCb + hz * sChh) : nullptr;
    const float* pres = res ? (res + bz * sCb + hz * sChh) : nullptr;

    int nKB = K >> 5;
    if (flags & F_KCAUS){
        int lim = (bm + BM) >> 5;
        if (lim < nKB) nKB = lim;
    }

    auto loadStage = [&](int kb, int s){
        const int k0 = kb * BK;
        const uint32_t stg = smb + s * STAGE;
#pragma unroll
        for (int i = 0; i < 2; i++){
            int idx = i * 256 + tid;
            int r = idx >> 2, c = idx & 3;
            uint32_t dst = stg + r * 80 + c * 16;
            CP16(dst, pAh + (size_t)(bm + r) * lda + k0 + c * 8);
        }
        if (BTRANS){
            constexpr int CPR = BN / 8;
#pragma unroll
            for (int i = 0; i < (BK * CPR) / 256; i++){
                int idx = i * 256 + tid;
                int r = idx / CPR, c = idx % CPR;
                uint32_t dst = stg + ABYTES + r * BPITCH + c * 16;
                CP16(dst, pB + (size_t)(k0 + r) * ldb + bn + c * 8);
            }
        } else {
#pragma unroll
            for (int i = 0; i < BN / 64; i++){
                int idx = i * 256 + tid;
                int r = idx >> 2, c = idx & 3;
                uint32_t dst = stg + ABYTES + r * 80 + c * 16;
                CP16(dst, pB + (size_t)(bn + r) * ldb + k0 + c * 8);
            }
        }
        CP_COMMIT();
    };

    float acc[2][NA][4];
#pragma unroll
    for (int i = 0; i < 2; i++)
#pragma unroll
        for (int j = 0; j < NA; j++)
#pragma unroll
            for (int q = 0; q < 4; q++) acc[i][j][q] = 0.f;

    loadStage(0, 0);
    loadStage(1, 1);

    for (int kb = 0; kb < nKB; kb++){
        if (kb == nKB - 1) CP_WAIT0(); else CP_WAIT1();
        __syncthreads();
        if (kb + 2 < nKB){
            int s2 = kb + 2; while (s2 >= 3) s2 -= 3;
            loadStage(kb + 2, s2);
        }
        int s = kb; while (s >= 3) s -= 3;
        const uint32_t stg = smb + s * STAGE;
#pragma unroll
        for (int ks = 0; ks < 2; ks++){
            const int kc = ks * 16;
            uint32_t a_h[2][4];
#pragma unroll
            for (int mi = 0; mi < 2; mi++){
                int row = wm * 32 + mi * 16 + (lane & 15);
                int colb = (kc + ((lane >> 4) << 3)) * 2;
                uint32_t ad = stg + row * 80 + colb;
                LDSM4(a_h[mi][0], a_h[mi][1], a_h[mi][2], a_h[mi][3], ad);
            }
            uint32_t b_s[NA][2];
            if (BTRANS){
#pragma unroll
                for (int p = 0; p < NA / 2; p++){
                    int g = lane >> 3, rr = lane & 7;
                    int row = kc + (g & 1) * 8 + rr;
                    int colb = (wn * WN + p * 16 + (g >> 1) * 8) * 2;
                    uint32_t ad = stg + ABYTES + row * BPITCH + colb;
                    uint32_t r0, r1, r2, r3;
                    LDSM4T(r0, r1, r2, r3, ad);
                    b_s[2*p][0] = r0; b_s[2*p][1] = r1;
                    b_s[2*p+1][0] = r2; b_s[2*p+1][1] = r3;
                }
            } else {
#pragma unroll
                for (int p = 0; p < NA / 2; p++){
                    int rowb = wn * WN + p * 16 + (lane & 7) + ((lane >> 4) << 3);
                    int colb = (kc + (((lane >> 3) & 1) << 3)) * 2;
                    uint32_t ad = stg + ABYTES + rowb * 80 + colb;
                    uint32_t r0, r1, r2, r3;
                    LDSM4(r0, r1, r2, r3, ad);
                    b_s[2*p][0] = r0; b_s[2*p][1] = r1;
                    b_s[2*p+1][0] = r2; b_s[2*p+1][1] = r3;
                }
            }
#pragma unroll
            for (int mi = 0; mi < 2; mi++)
#pragma unroll
                for (int ni = 0; ni < NA; ni++)
                    MMA16816(acc[mi][ni], a_h[mi], b_s[ni]);
        }
    }

    // epilogue
#pragma unroll
    for (int mi = 0; mi < 2; mi++){
#pragma unroll
        for (int ni = 0; ni < NA; ni++){
            int r0 = bm + wm * 32 + mi * 16 + (lane >> 2);
            int c0 = bn + wn * WN + ni * 8 + (lane & 3) * 2;
#pragma unroll
            for (int half = 0; half < 2; half++){
                int r = r0 + half * 8;
                float vx = acc[mi][ni][half * 2 + 0];
                float vy = acc[mi][ni][half * 2 + 1];
                if (flags & F_QKV){
                    // range 0 -> q (Ch); 1 -> k (C2); 2 -> v (C3)
                    int range = c0 >> 10, cc = c0 & 1023;
                    __half2 hv(__float2half_rn(vx), __float2half_rn(vy));
                    if (range == 0)
                        *(__half2*)(pCh + (size_t)r * ldc + cc) = hv;
                    else if (range == 1)
                        *(__half2*)(C2 + (size_t)r * ldc + cc) = hv;
                    else
                        *(__half2*)(C3 + (size_t)r * ldc + cc) = hv;
                    continue;
                }
                if (flags & F_SCALE){ vx *= scale; vy *= scale; }
                if (flags & F_BIAS){ vx += bias[c0]; vy += bias[c0 + 1]; }
                if (flags & F_RES){
                    const float* rp = pres + (size_t)r * ldc + c0;
                    vx += rp[0]; vy += rp[1];
                }
                if (flags & F_RELU){ vx = fmaxf(vx, 0.f); vy = fmaxf(vy, 0.f); }
                if (flags & F_CAUSAL){
                    if (c0 > r)     vx = -3.0e38f;
                    if (c0 + 1 > r) vy = -3.0e38f;
                }
                if (pCf){
                    float2 o2; o2.x = vx; o2.y = vy;
                    *(float2*)(pCf + (size_t)r * ldc + c0) = o2;
                }
                if (pCh){
                    __half2 hv(__float2half_rn(vx), __float2half_rn(vy));
                    *(__half2*)(pCh + (size_t)r * ldc + c0) = hv;
                }
            }
        }
    }
}

// ==================== host orchestration ====================
extern "C" void kernel_launch(void* const* d_in, const int* in_sizes, int n_in,
                              void* d_out, int out_size){
    (void)in_sizes; (void)n_in; (void)out_size;
    const int*   x     = (const int*)  d_in[0];
    const float* ce    = (const float*)d_in[1];
    const float* pe    = (const float*)d_in[2];
    const float* ln1_s = (const float*)d_in[5];
    const float* ln1_b = (const float*)d_in[6];
    const float* wq    = (const float*)d_in[7];
    const float* wk    = (const float*)d_in[8];
    const float* wv    = (const float*)d_in[9];
    const float* wo    = (const float*)d_in[10];
    const float* bo    = (const float*)d_in[11];
    const float* ln2_s = (const float*)d_in[12];
    const float* ln2_b = (const float*)d_in[13];
    const float* w1    = (const float*)d_in[14];
    const float* b1    = (const float*)d_in[15];
    const float* w2    = (const float*)d_in[16];
    const float* b2    = (const float*)d_in[17];
    const float* lnf_s = (const float*)d_in[18];
    const float* lnf_b = (const float*)d_in[19];
    const float* wf    = (const float*)d_in[20];
    const float* bf    = (const float*)d_in[21];

    float *h;
    cudaGetSymbolAddress((void**)&h, g_h);

    __half *yS,*qS,*kS,*vS,*oS,*aS,*s16,*sH;
    cudaGetSymbolAddress((void**)&yS, g_yS);
    cudaGetSymbolAddress((void**)&qS, g_qS);
    cudaGetSymbolAddress((void**)&kS, g_kS);
    cudaGetSymbolAddress((void**)&vS, g_vS);
    cudaGetSymbolAddress((void**)&oS, g_oS);
    cudaGetSymbolAddress((void**)&aS, g_aS);
    cudaGetSymbolAddress((void**)&s16, g_s16);
    cudaGetSymbolAddress((void**)&sH, g_sH);

    __half *wqkvS,*woS,*w1S,*w2S,*wfS;
    cudaGetSymbolAddress((void**)&wqkvS, g_wqkvS);
    cudaGetSymbolAddress((void**)&woS, g_woS);
    cudaGetSymbolAddress((void**)&w1S, g_w1S);
    cudaGetSymbolAddress((void**)&w2S, g_w2S);
    cudaGetSymbolAddress((void**)&wfS, g_wfS);

    // dyn smem (3 stages, 1-pass A):
    //  BTRANS BN=128: 3*(10240 + 32*272) = 3*18944 = 56832
    //  scores K-major BN=128: 3*(10240 + 10240) = 61440
    //  AV BTRANS BN=64: 3*(10240 + 32*144) = 3*14848 = 44544
    const int SMWT = 56832, SMSC = 61440, SMAV = 44544;
    cudaFuncSetAttribute((const void*)gemm_mma<128,true>,  cudaFuncAttributeMaxDynamicSharedMemorySize, SMWT);
    cudaFuncSetAttribute((const void*)gemm_mma<128,false>, cudaFuncAttributeMaxDynamicSharedMemorySize, SMSC);
    cudaFuncSetAttribute((const void*)gemm_mma<64,true>,   cudaFuncAttributeMaxDynamicSharedMemorySize, SMAV);

    const long long DD = (long long)Dn * Dn;
    const long long DF = (long long)Dn * FFn;

    // weight converts (streaming). wqkv packed along N: cols 0-1023=wq, 1024-2047=wk, 2048-3071=wv
    convS_k<<<dim3(DD/2048, Ln), 256>>>(wq, wqkvS, Dn, 3*Dn, 0,      DD, 3*DD);
    convS_k<<<dim3(DD/2048, Ln), 256>>>(wk, wqkvS, Dn, 3*Dn, Dn,     DD, 3*DD);
    convS_k<<<dim3(DD/2048, Ln), 256>>>(wv, wqkvS, Dn, 3*Dn, 2*Dn,   DD, 3*DD);
    convS_k<<<dim3(DD/2048, Ln), 256>>>(wo, woS, Dn, Dn, 0,          DD, DD);
    convS_k<<<dim3(DF/2048, Ln), 256>>>(w1, w1S, FFn, FFn, 0,        DF, DF);
    convS_k<<<dim3(DF/2048, Ln), 256>>>(w2, w2S, Dn, Dn, 0,          DF, DF);
    convS_k<<<dim3(((long long)Dn*Vn)/2048, 1), 256>>>(wf, wfS, Vn, Vn, 0, 0, 0);

    embed_k<<<(Mn * Dn) / 256, 256>>>(x, ce, pe);

    const long long SAB = (long long)Tn * Dn;   // per-batch stride in q/k/v/o
    const long long SS1 = (long long)Tn * Tn;   // per-bh stride in s

    for (int l = 0; l < Ln; l++){
        ln_k<<<Mn, 256>>>(h, yS, ln1_s + l*Dn, ln1_b + l*Dn);

        // fused QKV (1-pass, B native [1024,3072])
        gemm_mma<128,true><<<dim3(24,16,1), 256, SMWT>>>(yS,
            wqkvS + (size_t)l*3*DD,
            nullptr, nullptr, nullptr, qS, kS, vS, Dn, Dn, 3*Dn, Dn, 1,
            0,0,0,0,0,0, F_QKV, 1.f);

        // scores (1-pass, K-major B = kS): S16 = scale * Q K^T (causal), fp16 out
        gemm_mma<128,false><<<dim3(4,4,BHn), 256, SMSC>>>(qS, kS,
            nullptr, nullptr, nullptr, s16, nullptr, nullptr,
            HSn, Dn, Dn, Tn, Hn, SAB, (long long)HSn, SAB, (long long)HSn,
            (long long)Hn*SS1, SS1, F_SCALE | F_CAUSAL, 0.125f);
        softmax_k<<<BHn*Tn, 128>>>();

        // O[bh] = S @ V (1-pass; V natural layout; K truncated)
        gemm_mma<64,true><<<dim3(1,4,BHn), 256, SMAV>>>(sH, vS,
            nullptr, nullptr, nullptr, oS, nullptr, nullptr,
            Tn, Tn, Dn, Dn, Hn, (long long)Hn*SS1, SS1, SAB, (long long)HSn,
            SAB, (long long)HSn, F_KCAUS, 1.f);

        // O-proj (1-pass, B native [1024,1024])
        gemm_mma<128,true><<<dim3(8,16,1), 256, SMWT>>>(oS,
            woS + (size_t)l*DD,
            bo + l*Dn, h, h, nullptr, nullptr, nullptr, Dn, Dn, Dn, Dn, 1,
            0,0,0,0,0,0, F_BIAS | F_RES, 1.f);

        ln_k<<<Mn, 256>>>(h, yS, ln2_s + l*Dn, ln2_b + l*Dn);

        // MLP1 (1-pass, B native [1024,4096]): a = relu(y @ w1 + b1)
        gemm_mma<128,true><<<dim3(32,16,1), 256, SMWT>>>(yS,
            w1S + (size_t)l*DF,
            b1 + l*FFn, nullptr, nullptr, aS, nullptr, nullptr,
            Dn, Dn, FFn, FFn, 1, 0,0,0,0,0,0, F_BIAS | F_RELU, 1.f);

        // MLP2 (1-pass, B native [4096,1024]): h += a @ w2 + b2
        gemm_mma<128,true><<<dim3(8,16,1), 256, SMWT>>>(aS,
            w2S + (size_t)l*DF,
            b2 + l*Dn, h, h, nullptr, nullptr, nullptr,
            FFn, FFn, Dn, Dn, 1, 0,0,0,0,0,0, F_BIAS | F_RES, 1.f);
    }

    ln_k<<<Mn, 256>>>(h, yS, lnf_s, lnf_b);

    // logits (1-pass, B native [1024,32000])
    gemm_mma<128,true><<<dim3(Vn/128, 16, 1), 256, SMWT>>>(yS, wfS,
        bf, nullptr, (float*)d_out, nullptr, nullptr, nullptr,
        Dn, Dn, Vn, Vn, 1, 0,0,0,0,0,0, F_BIAS, 1.f);
}

// round 15
// speedup vs baseline: 2.8415x; 1.1538x over previous
#include <cuda_runtime.h>
#include <cuda_fp16.h>
#include <cstdint>

#define Bn 4
#define Tn 512
#define Dn 1024
#define Hn 16
#define HSn 64
#define Ln 8
#define Vn 32000
#define Mn (Bn*Tn)       // 2048
#define FFn (4*Dn)       // 4096
#define BHn (Bn*Hn)      // 64

// ---------------- fp32 scratch ----------------
__device__ float g_h[Mn*Dn];

// ---------------- fp16 planes ----------------
__device__ __half g_yS[Mn*Dn];
__device__ __half g_qS[Mn*Dn];                    // pre-scaled by 1/8
__device__ __half g_kS[Mn*Dn];
__device__ __half g_vS[Mn*Dn];                    // natural [t, d] layout
__device__ __half g_oS[Mn*Dn];
__device__ __half g_aS[Mn*FFn];

// ---------------- fp16 weights (NATIVE [K,N] row-major, single plane) ------
__device__ __half g_wqkvS[(size_t)Ln*3*Dn*Dn];   // [1024, 3072] per layer
__device__ __half g_woS[Ln*Dn*Dn];               // [1024, 1024]
__device__ __half g_w1S[Ln*Dn*FFn];              // [1024, 4096]
__device__ __half g_w2S[Ln*Dn*FFn];              // [4096, 1024]
__device__ __half g_wfS[(size_t)Dn*Vn];          // [1024, 32000]

// ==================== helpers ====================
__device__ __forceinline__ uint32_t smem_u32(const void* p){
    uint32_t a;
    asm("{ .reg .u64 t; cvta.to.shared.u64 t, %1; cvt.u32.u64 %0, t; }" : "=r"(a) : "l"(p));
    return a;
}
#define CP16(dst, src) \
    asm volatile("cp.async.cg.shared.global [%0], [%1], 16;" :: "r"(dst), "l"(src))
#define CP_COMMIT() asm volatile("cp.async.commit_group;" ::: "memory")
#define CP_WAIT1() asm volatile("cp.async.wait_group 1;" ::: "memory")
#define CP_WAIT0() asm volatile("cp.async.wait_group 0;" ::: "memory")

#define LDSM4(r0,r1,r2,r3,addr) \
    asm volatile("ldmatrix.sync.aligned.m8n8.x4.shared.b16 {%0,%1,%2,%3}, [%4];" \
        : "=r"(r0),"=r"(r1),"=r"(r2),"=r"(r3) : "r"(addr))
#define LDSM4T(r0,r1,r2,r3,addr) \
    asm volatile("ldmatrix.sync.aligned.m8n8.x4.trans.shared.b16 {%0,%1,%2,%3}, [%4];" \
        : "=r"(r0),"=r"(r1),"=r"(r2),"=r"(r3) : "r"(addr))

#define MMA16816(d, a, b) \
    asm volatile("mma.sync.aligned.m16n8k16.row.col.f32.f16.f16.f32 " \
        "{%0,%1,%2,%3}, {%4,%5,%6,%7}, {%8,%9}, {%0,%1,%2,%3};" \
        : "+f"((d)[0]),"+f"((d)[1]),"+f"((d)[2]),"+f"((d)[3]) \
        : "r"((a)[0]),"r"((a)[1]),"r"((a)[2]),"r"((a)[3]), "r"((b)[0]),"r"((b)[1]))

// ==================== reductions ====================
__device__ __forceinline__ float warpSum(float v){
#pragma unroll
    for (int o = 16; o > 0; o >>= 1) v += __shfl_down_sync(0xffffffffu, v, o);
    return v;
}
__device__ __forceinline__ float blockSum(float v, float* sh){
    int lane = threadIdx.x & 31, w = threadIdx.x >> 5;
    v = warpSum(v);
    __syncthreads();
    if (lane == 0) sh[w] = v;
    __syncthreads();
    int nw = blockDim.x >> 5;
    v = (threadIdx.x < (unsigned)nw) ? sh[threadIdx.x] : 0.f;
    if (w == 0) v = warpSum(v);
    if (threadIdx.x == 0) sh[0] = v;
    __syncthreads();
    return sh[0];
}

// ==================== small kernels ====================
__global__ void embed_k(const int* __restrict__ x, const float* __restrict__ ce,
                        const float* __restrict__ pe){
    int idx = blockIdx.x * blockDim.x + threadIdx.x;
    int d  = idx & (Dn - 1);
    int mt = idx >> 10;
    int t  = mt & (Tn - 1);
    g_h[idx] = ce[(size_t)x[mt] * Dn + d] + pe[t * Dn + d];
}

// LayerNorm fused with single fp16 plane output
__global__ __launch_bounds__(256) void ln_k(const float* __restrict__ in,
                                            __half* __restrict__ outH,
                                            const float* __restrict__ gs,
                                            const float* __restrict__ gb){
    __shared__ float sh[32];
    int row = blockIdx.x;
    const float4* xr = (const float4*)(in + (size_t)row * Dn);
    float4 vv = xr[threadIdx.x];
    float s  = vv.x + vv.y + vv.z + vv.w;
    float sq = vv.x*vv.x + vv.y*vv.y + vv.z*vv.z + vv.w*vv.w;
    s  = blockSum(s, sh);
    sq = blockSum(sq, sh);
    float mean = s * (1.f / Dn);
    float var  = sq * (1.f / Dn) - mean * mean;
    float r = rsqrtf(var + 1e-5f);
    int i0 = threadIdx.x * 4;
    float o[4];
    o[0] = (vv.x - mean) * r * gs[i0+0] + gb[i0+0];
    o[1] = (vv.y - mean) * r * gs[i0+1] + gb[i0+1];
    o[2] = (vv.z - mean) * r * gs[i0+2] + gb[i0+2];
    o[3] = (vv.w - mean) * r * gs[i0+3] + gb[i0+3];
    __half2 h2[2];
    h2[0] = __half2(__float2half_rn(o[0]), __float2half_rn(o[1]));
    h2[1] = __half2(__float2half_rn(o[2]), __float2half_rn(o[3]));
    *(uint2*)(outH + (size_t)row * Dn + i0) = *(uint2*)h2;
}

// streaming fp32 -> fp16 convert, no transpose.
__global__ __launch_bounds__(256) void convS_k(const float* __restrict__ in,
                                               __half* __restrict__ out,
                                               int cols, int ldout, int colofs,
                                               long long sIz, long long sOz){
    const float* pin = in + blockIdx.y * sIz;
    __half* pos = out + blockIdx.y * sOz;
    int idx = blockIdx.x * blockDim.x + threadIdx.x;
    int n8 = cols >> 3;
    int r = idx / n8, c = (idx - r * n8) << 3;
    const float4* src = (const float4*)(pin + (size_t)r * cols + c);
    float4 v0 = src[0], v1 = src[1];
    __half2 h[4];
    h[0] = __half2(__float2half_rn(v0.x), __float2half_rn(v0.y));
    h[1] = __half2(__float2half_rn(v0.z), __float2half_rn(v0.w));
    h[2] = __half2(__float2half_rn(v1.x), __float2half_rn(v1.y));
    h[3] = __half2(__float2half_rn(v1.z), __float2half_rn(v1.w));
    *(uint4*)(pos + (size_t)r * ldout + colofs + c) = *(uint4*)h;
}

// ==================== fused flash attention ====================
// grid (4 q-tiles, 64 bh), 256 threads (8 warps x 16 rows).
// Q pre-scaled by 1/8. K tile non-trans B frags; V tile trans B frags.
// Online softmax in registers; P fragments reuse S accumulator layout.
__global__ __launch_bounds__(256) void flash_k(
    const __half* __restrict__ q, const __half* __restrict__ k,
    const __half* __restrict__ v, __half* __restrict__ o)
{
    constexpr int PITCH = 144;                 // 64 halves + 16B pad
    constexpr int TILEB = 128 * PITCH;         // 18432
    extern __shared__ char sm[];
    const uint32_t smb = smem_u32(sm);
    const uint32_t Qs = smb, Ks = smb + TILEB, Vs = smb + 2 * TILEB;

    const int qt = blockIdx.x, bh = blockIdx.y;
    const int b = bh >> 4, h = bh & 15;
    const int tid = threadIdx.x, lane = tid & 31, w = tid >> 5;

    const __half* qbase = q + ((size_t)(b * Tn + qt * 128)) * Dn + h * HSn;
    const __half* kbase = k + ((size_t)(b * Tn)) * Dn + h * HSn;
    const __half* vbase = v + ((size_t)(b * Tn)) * Dn + h * HSn;

    // load Q tile (128 x 64 fp16)
#pragma unroll
    for (int i = 0; i < 4; i++){
        int idx = i * 256 + tid;
        int r = idx >> 3, c = idx & 7;
        CP16(Qs + r * PITCH + c * 16, qbase + (size_t)r * Dn + c * 8);
    }
    CP_COMMIT();

    float m0 = -1e30f, m1 = -1e30f, l0 = 0.f, l1 = 0.f;
    float acc_o[8][4];
#pragma unroll
    for (int i = 0; i < 8; i++)
#pragma unroll
        for (int j = 0; j < 4; j++) acc_o[i][j] = 0.f;

    for (int kt = 0; kt <= qt; kt++){
        __syncthreads();                        // smem reuse guard
        const __half* kb = kbase + (size_t)(kt * 128) * Dn;
        const __half* vb = vbase + (size_t)(kt * 128) * Dn;
#pragma unroll
        for (int i = 0; i < 4; i++){
            int idx = i * 256 + tid;
            int r = idx >> 3, c = idx & 7;
            CP16(Ks + r * PITCH + c * 16, kb + (size_t)r * Dn + c * 8);
            CP16(Vs + r * PITCH + c * 16, vb + (size_t)r * Dn + c * 8);
        }
        CP_COMMIT();
        CP_WAIT0();
        __syncthreads();

        // ---- S = Q K^T (scale pre-folded into q) ----
        float acc_s[16][4];
#pragma unroll
        for (int i = 0; i < 16; i++)
#pragma unroll
            for (int j = 0; j < 4; j++) acc_s[i][j] = 0.f;

#pragma unroll
        for (int kc = 0; kc < 4; kc++){
            uint32_t a[4];
            {
                int row = w * 16 + (lane & 15);
                int colb = (kc * 16 + ((lane >> 4) << 3)) * 2;
                LDSM4(a[0], a[1], a[2], a[3], Qs + row * PITCH + colb);
            }
#pragma unroll
            for (int p = 0; p < 8; p++){
                int rowb = p * 16 + (lane & 7) + ((lane >> 4) << 3);
                int colb = (kc * 16 + (((lane >> 3) & 1) << 3)) * 2;
                uint32_t r0, r1, r2, r3;
                LDSM4(r0, r1, r2, r3, Ks + rowb * PITCH + colb);
                uint32_t b0[2] = {r0, r1}, b1[2] = {r2, r3};
                MMA16816(acc_s[2*p],   a, b0);
                MMA16816(acc_s[2*p+1], a, b1);
            }
        }

        // ---- causal mask (diagonal tile only) ----
        if (kt == qt){
            int r0g = w * 16 + (lane >> 2);
#pragma unroll
            for (int ni = 0; ni < 16; ni++){
#pragma unroll
                for (int c = 0; c < 4; c++){
                    int col = ni * 8 + (lane & 3) * 2 + (c & 1);
                    int row = r0g + ((c >> 1) << 3);
                    if (col > row) acc_s[ni][c] = -1e30f;
                }
            }
        }

        // ---- online softmax ----
        float mx0 = -1e30f, mx1 = -1e30f;
#pragma unroll
        for (int ni = 0; ni < 16; ni++){
            mx0 = fmaxf(mx0, fmaxf(acc_s[ni][0], acc_s[ni][1]));
            mx1 = fmaxf(mx1, fmaxf(acc_s[ni][2], acc_s[ni][3]));
        }
        mx0 = fmaxf(mx0, __shfl_xor_sync(0xffffffffu, mx0, 1));
        mx0 = fmaxf(mx0, __shfl_xor_sync(0xffffffffu, mx0, 2));
        mx1 = fmaxf(mx1, __shfl_xor_sync(0xffffffffu, mx1, 1));
        mx1 = fmaxf(mx1, __shfl_xor_sync(0xffffffffu, mx1, 2));
        float mn0 = fmaxf(m0, mx0), mn1 = fmaxf(m1, mx1);
        float rs0 = __expf(m0 - mn0), rs1 = __expf(m1 - mn1);
        m0 = mn0; m1 = mn1;

        float sum0 = 0.f, sum1 = 0.f;
#pragma unroll
        for (int ni = 0; ni < 16; ni++){
            float p0 = __expf(acc_s[ni][0] - mn0);
            float p1 = __expf(acc_s[ni][1] - mn0);
            float p2 = __expf(acc_s[ni][2] - mn1);
            float p3 = __expf(acc_s[ni][3] - mn1);
            sum0 += p0 + p1; sum1 += p2 + p3;
            acc_s[ni][0] = p0; acc_s[ni][1] = p1;
            acc_s[ni][2] = p2; acc_s[ni][3] = p3;
        }
        // FULL row sum: quad reduction (lanes of a quad hold disjoint columns)
        sum0 += __shfl_xor_sync(0xffffffffu, sum0, 1);
        sum0 += __shfl_xor_sync(0xffffffffu, sum0, 2);
        sum1 += __shfl_xor_sync(0xffffffffu, sum1, 1);
        sum1 += __shfl_xor_sync(0xffffffffu, sum1, 2);
        l0 = l0 * rs0 + sum0;
        l1 = l1 * rs1 + sum1;
#pragma unroll
        for (int ni = 0; ni < 8; ni++){
            acc_o[ni][0] *= rs0; acc_o[ni][1] *= rs0;
            acc_o[ni][2] *= rs1; acc_o[ni][3] *= rs1;
        }

        // ---- O += P V  (P frags packed from acc_s on the fly) ----
#pragma unroll
        for (int j2 = 0; j2 < 8; j2++){
            uint32_t pa[4];
            {
                __half2 t0(__float2half_rn(acc_s[2*j2][0]),   __float2half_rn(acc_s[2*j2][1]));
                __half2 t1(__float2half_rn(acc_s[2*j2][2]),   __float2half_rn(acc_s[2*j2][3]));
                __half2 t2(__float2half_rn(acc_s[2*j2+1][0]), __float2half_rn(acc_s[2*j2+1][1]));
                __half2 t3(__float2half_rn(acc_s[2*j2+1][2]), __float2half_rn(acc_s[2*j2+1][3]));
                pa[0] = *(uint32_t*)&t0; pa[1] = *(uint32_t*)&t1;
                pa[2] = *(uint32_t*)&t2; pa[3] = *(uint32_t*)&t3;
            }
#pragma unroll
            for (int p = 0; p < 4; p++){
                int g = lane >> 3, rr = lane & 7;
                int row = j2 * 16 + (g & 1) * 8 + rr;
                int colb = (p * 16 + (g >> 1) * 8) * 2;
                uint32_t r0, r1, r2, r3;
                LDSM4T(r0, r1, r2, r3, Vs + row * PITCH + colb);
                uint32_t b0[2] = {r0, r1}, b1[2] = {r2, r3};
                MMA16816(acc_o[2*p],   pa, b0);
                MMA16816(acc_o[2*p+1], pa, b1);
            }
        }
    }

    // ---- epilogue: normalize + write O (fp16) ----
    float inv0 = 1.f / l0, inv1 = 1.f / l1;
    int row0 = qt * 128 + w * 16 + (lane >> 2);
    __half* ob = o + ((size_t)(b * Tn)) * Dn + h * HSn;
#pragma unroll
    for (int ni = 0; ni < 8; ni++){
        int col = ni * 8 + (lane & 3) * 2;
        __half2 v0(__float2half_rn(acc_o[ni][0] * inv0), __float2half_rn(acc_o[ni][1] * inv0));
        __half2 v1(__float2half_rn(acc_o[ni][2] * inv1), __float2half_rn(acc_o[ni][3] * inv1));
        *(__half2*)(ob + (size_t)row0 * Dn + col) = v0;
        *(__half2*)(ob + (size_t)(row0 + 8) * Dn + col) = v1;
    }
}

// ==================== fp16 mma.sync GEMM (3-stage pipeline, 1-pass) ========
#define F_BIAS   1
#define F_RES    2
#define F_RELU   4
#define F_QKV    64

template<int BN, bool BTRANS>
__global__ __launch_bounds__(256, 2) void gemm_mma(
    const __half* __restrict__ Ah,
    const __half* __restrict__ Bs,
    const float* __restrict__ bias, const float* __restrict__ res,
    float* __restrict__ Cf, __half* __restrict__ Ch,
    __half* __restrict__ C2, __half* __restrict__ C3,
    int K, int lda, int ldb, int ldc,
    int flags)
{
    constexpr int BM = 128, BK = 32;
    constexpr int ABYTES = BM * 40 * 2;
    constexpr int BPITCH = BTRANS ? (BN * 2 + 16) : 80;
    constexpr int BBYTES = BTRANS ? (BK * BPITCH) : (BN * 80);
    constexpr int STAGE = ABYTES + BBYTES;
    constexpr int WN = BN / 2;
    constexpr int NA = WN / 8;

    const int bm = blockIdx.y * BM, bn = blockIdx.x * BN;

    extern __shared__ char sm[];
    const uint32_t smb = smem_u32(sm);

    const int tid = threadIdx.x, lane = tid & 31, wid = tid >> 5;
    const int wm = wid & 3, wn = wid >> 2;

    const int nKB = K >> 5;

    auto loadStage = [&](int kb, int s){
        const int k0 = kb * BK;
        const uint32_t stg = smb + s * STAGE;
#pragma unroll
        for (int i = 0; i < 2; i++){
            int idx = i * 256 + tid;
            int r = idx >> 2, c = idx & 3;
            uint32_t dst = stg + r * 80 + c * 16;
            CP16(dst, Ah + (size_t)(bm + r) * lda + k0 + c * 8);
        }
        if (BTRANS){
            constexpr int CPR = BN / 8;
#pragma unroll
            for (int i = 0; i < (BK * CPR) / 256; i++){
                int idx = i * 256 + tid;
                int r = idx / CPR, c = idx % CPR;
                uint32_t dst = stg + ABYTES + r * BPITCH + c * 16;
                CP16(dst, Bs + (size_t)(k0 + r) * ldb + bn + c * 8);
            }
        } else {
#pragma unroll
            for (int i = 0; i < BN / 64; i++){
                int idx = i * 256 + tid;
                int r = idx >> 2, c = idx & 3;
                uint32_t dst = stg + ABYTES + r * 80 + c * 16;
                CP16(dst, Bs + (size_t)(bn + r) * ldb + k0 + c * 8);
            }
        }
        CP_COMMIT();
    };

    float acc[2][NA][4];
#pragma unroll
    for (int i = 0; i < 2; i++)
#pragma unroll
        for (int j = 0; j < NA; j++)
#pragma unroll
            for (int q = 0; q < 4; q++) acc[i][j][q] = 0.f;

    loadStage(0, 0);
    loadStage(1, 1);

    for (int kb = 0; kb < nKB; kb++){
        if (kb == nKB - 1) CP_WAIT0(); else CP_WAIT1();
        __syncthreads();
        if (kb + 2 < nKB){
            int s2 = kb + 2; while (s2 >= 3) s2 -= 3;
            loadStage(kb + 2, s2);
        }
        int s = kb; while (s >= 3) s -= 3;
        const uint32_t stg = smb + s * STAGE;
#pragma unroll
        for (int ks = 0; ks < 2; ks++){
            const int kc = ks * 16;
            uint32_t a_h[2][4];
#pragma unroll
            for (int mi = 0; mi < 2; mi++){
                int row = wm * 32 + mi * 16 + (lane & 15);
                int colb = (kc + ((lane >> 4) << 3)) * 2;
                uint32_t ad = stg + row * 80 + colb;
                LDSM4(a_h[mi][0], a_h[mi][1], a_h[mi][2], a_h[mi][3], ad);
            }
            uint32_t b_s[NA][2];
            if (BTRANS){
#pragma unroll
                for (int p = 0; p < NA / 2; p++){
                    int g = lane >> 3, rr = lane & 7;
                    int row = kc + (g & 1) * 8 + rr;
                    int colb = (wn * WN + p * 16 + (g >> 1) * 8) * 2;
                    uint32_t ad = stg + ABYTES + row * BPITCH + colb;
                    uint32_t r0, r1, r2, r3;
                    LDSM4T(r0, r1, r2, r3, ad);
                    b_s[2*p][0] = r0; b_s[2*p][1] = r1;
                    b_s[2*p+1][0] = r2; b_s[2*p+1][1] = r3;
                }
            } else {
#pragma unroll
                for (int p = 0; p < NA / 2; p++){
                    int rowb = wn * WN + p * 16 + (lane & 7) + ((lane >> 4) << 3);
                    int colb = (kc + (((lane >> 3) & 1) << 3)) * 2;
                    uint32_t ad = stg + ABYTES + rowb * 80 + colb;
                    uint32_t r0, r1, r2, r3;
                    LDSM4(r0, r1, r2, r3, ad);
                    b_s[2*p][0] = r0; b_s[2*p][1] = r1;
                    b_s[2*p+1][0] = r2; b_s[2*p+1][1] = r3;
                }
            }
#pragma unroll
            for (int mi = 0; mi < 2; mi++)
#pragma unroll
                for (int ni = 0; ni < NA; ni++)
                    MMA16816(acc[mi][ni], a_h[mi], b_s[ni]);
        }
    }

    // epilogue
#pragma unroll
    for (int mi = 0; mi < 2; mi++){
#pragma unroll
        for (int ni = 0; ni < NA; ni++){
            int r0 = bm + wm * 32 + mi * 16 + (lane >> 2);
            int c0 = bn + wn * WN + ni * 8 + (lane & 3) * 2;
#pragma unroll
            for (int half = 0; half < 2; half++){
                int r = r0 + half * 8;
                float vx = acc[mi][ni][half * 2 + 0];
                float vy = acc[mi][ni][half * 2 + 1];
                if (flags & F_QKV){
                    // range 0 -> q (Ch, pre-scaled 1/8); 1 -> k (C2); 2 -> v (C3)
                    int range = c0 >> 10, cc = c0 & 1023;
                    if (range == 0){ vx *= 0.125f; vy *= 0.125f; }
                    __half2 hv(__float2half_rn(vx), __float2half_rn(vy));
                    if (range == 0)
                        *(__half2*)(Ch + (size_t)r * ldc + cc) = hv;
                    else if (range == 1)
                        *(__half2*)(C2 + (size_t)r * ldc + cc) = hv;
                    else
                        *(__half2*)(C3 + (size_t)r * ldc + cc) = hv;
                    continue;
                }
                if (flags & F_BIAS){ vx += bias[c0]; vy += bias[c0 + 1]; }
                if (flags & F_RES){
                    const float* rp = res + (size_t)r * ldc + c0;
                    vx += rp[0]; vy += rp[1];
                }
                if (flags & F_RELU){ vx = fmaxf(vx, 0.f); vy = fmaxf(vy, 0.f); }
                if (Cf){
                    float2 o2; o2.x = vx; o2.y = vy;
                    *(float2*)(Cf + (size_t)r * ldc + c0) = o2;
                }
                if (Ch){
                    __half2 hv(__float2half_rn(vx), __float2half_rn(vy));
                    *(__half2*)(Ch + (size_t)r * ldc + c0) = hv;
                }
            }
        }
    }
}

// ==================== host orchestration ====================
extern "C" void kernel_launch(void* const* d_in, const int* in_sizes, int n_in,
                              void* d_out, int out_size){
    (void)in_sizes; (void)n_in; (void)out_size;
    const int*   x     = (const int*)  d_in[0];
    const float* ce    = (const float*)d_in[1];
    const float* pe    = (const float*)d_in[2];
    const float* ln1_s = (const float*)d_in[5];
    const float* ln1_b = (const float*)d_in[6];
    const float* wq    = (const float*)d_in[7];
    const float* wk    = (const float*)d_in[8];
    const float* wv    = (const float*)d_in[9];
    const float* wo    = (const float*)d_in[10];
    const float* bo    = (const float*)d_in[11];
    const float* ln2_s = (const float*)d_in[12];
    const float* ln2_b = (const float*)d_in[13];
    const float* w1    = (const float*)d_in[14];
    const float* b1    = (const float*)d_in[15];
    const float* w2    = (const float*)d_in[16];
    const float* b2    = (const float*)d_in[17];
    const float* lnf_s = (const float*)d_in[18];
    const float* lnf_b = (const float*)d_in[19];
    const float* wf    = (const float*)d_in[20];
    const float* bf    = (const float*)d_in[21];

    float *h;
    cudaGetSymbolAddress((void**)&h, g_h);

    __half *yS,*qS,*kS,*vS,*oS,*aS;
    cudaGetSymbolAddress((void**)&yS, g_yS);
    cudaGetSymbolAddress((void**)&qS, g_qS);
    cudaGetSymbolAddress((void**)&kS, g_kS);
    cudaGetSymbolAddress((void**)&vS, g_vS);
    cudaGetSymbolAddress((void**)&oS, g_oS);
    cudaGetSymbolAddress((void**)&aS, g_aS);

    __half *wqkvS,*woS,*w1S,*w2S,*wfS;
    cudaGetSymbolAddress((void**)&wqkvS, g_wqkvS);
    cudaGetSymbolAddress((void**)&woS, g_woS);
    cudaGetSymbolAddress((void**)&w1S, g_w1S);
    cudaGetSymbolAddress((void**)&w2S, g_w2S);
    cudaGetSymbolAddress((void**)&wfS, g_wfS);

    // dyn smem: weight GEMMs 3*(10240 + 32*272) = 56832 ; flash 3*18432 = 55296
    const int SMWT = 56832, SMFL = 55296;
    cudaFuncSetAttribute((const void*)gemm_mma<128,true>, cudaFuncAttributeMaxDynamicSharedMemorySize, SMWT);
    cudaFuncSetAttribute((const void*)flash_k,            cudaFuncAttributeMaxDynamicSharedMemorySize, SMFL);

    const long long DD = (long long)Dn * Dn;
    const long long DF = (long long)Dn * FFn;

    // weight converts (streaming). wqkv packed along N: cols 0-1023=wq, 1024-2047=wk, 2048-3071=wv
    convS_k<<<dim3(DD/2048, Ln), 256>>>(wq, wqkvS, Dn, 3*Dn, 0,      DD, 3*DD);
    convS_k<<<dim3(DD/2048, Ln), 256>>>(wk, wqkvS, Dn, 3*Dn, Dn,     DD, 3*DD);
    convS_k<<<dim3(DD/2048, Ln), 256>>>(wv, wqkvS, Dn, 3*Dn, 2*Dn,   DD, 3*DD);
    convS_k<<<dim3(DD/2048, Ln), 256>>>(wo, woS, Dn, Dn, 0,          DD, DD);
    convS_k<<<dim3(DF/2048, Ln), 256>>>(w1, w1S, FFn, FFn, 0,        DF, DF);
    convS_k<<<dim3(DF/2048, Ln), 256>>>(w2, w2S, Dn, Dn, 0,          DF, DF);
    convS_k<<<dim3(((long long)Dn*Vn)/2048, 1), 256>>>(wf, wfS, Vn, Vn, 0, 0, 0);

    embed_k<<<(Mn * Dn) / 256, 256>>>(x, ce, pe);

    for (int l = 0; l < Ln; l++){
        ln_k<<<Mn, 256>>>(h, yS, ln1_s + l*Dn, ln1_b + l*Dn);

        // fused QKV (1-pass): q (pre-scaled 1/8), k, v fp16 planes
        gemm_mma<128,true><<<dim3(24,16,1), 256, SMWT>>>(yS,
            wqkvS + (size_t)l*3*DD,
            nullptr, nullptr, nullptr, qS, kS, vS, Dn, Dn, 3*Dn, Dn, F_QKV);

        // fused flash attention: o = softmax(qk^T) v
        flash_k<<<dim3(4, BHn), 256, SMFL>>>(qS, kS, vS, oS);

        // O-proj
        gemm_mma<128,true><<<dim3(8,16,1), 256, SMWT>>>(oS,
            woS + (size_t)l*DD,
            bo + l*Dn, h, h, nullptr, nullptr, nullptr, Dn, Dn, Dn, Dn,
            F_BIAS | F_RES);

        ln_k<<<Mn, 256>>>(h, yS, ln2_s + l*Dn, ln2_b + l*Dn);

        // MLP1: a = relu(y @ w1 + b1)
        gemm_mma<128,true><<<dim3(32,16,1), 256, SMWT>>>(yS,
            w1S + (size_t)l*DF,
            b1 + l*FFn, nullptr, nullptr, aS, nullptr, nullptr,
            Dn, Dn, FFn, FFn, F_BIAS | F_RELU);

        // MLP2: h += a @ w2 + b2
        gemm_mma<128,true><<<dim3(8,16,1), 256, SMWT>>>(aS,
            w2S + (size_t)l*DF,
            b2 + l*Dn, h, h, nullptr, nullptr, nullptr,
            FFn, FFn, Dn, Dn, F_BIAS | F_RES);
    }

    ln_k<<<Mn, 256>>>(h, yS, lnf_s, lnf_b);

    // logits
    gemm_mma<128,true><<<dim3(Vn/128, 16, 1), 256, SMWT>>>(yS, wfS,
        bf, nullptr, (float*)d_out, nullptr, nullptr, nullptr,
        Dn, Dn, Vn, Vn, F_BIAS);
}

// round 16
// speedup vs baseline: 2.8467x; 1.0018x over previous
#include <cuda_runtime.h>
#include <cuda_fp16.h>
#include <cstdint>

#define Bn 4
#define Tn 512
#define Dn 1024
#define Hn 16
#define HSn 64
#define Ln 8
#define Vn 32000
#define Mn (Bn*Tn)       // 2048
#define FFn (4*Dn)       // 4096
#define BHn (Bn*Hn)      // 64

// ---------------- fp32 scratch ----------------
__device__ float g_h[Mn*Dn];

// ---------------- fp16 planes ----------------
__device__ __half g_yS[Mn*Dn];
__device__ __half g_qS[Mn*Dn];                    // pre-scaled by 1/8
__device__ __half g_kS[Mn*Dn];
__device__ __half g_vS[Mn*Dn];                    // natural [t, d] layout
__device__ __half g_oS[Mn*Dn];
__device__ __half g_aS[Mn*FFn];

// ---------------- fp16 weights (NATIVE [K,N] row-major, single plane) ------
__device__ __half g_wqkvS[(size_t)Ln*3*Dn*Dn];   // [1024, 3072] per layer
__device__ __half g_woS[Ln*Dn*Dn];               // [1024, 1024]
__device__ __half g_w1S[Ln*Dn*FFn];              // [1024, 4096]
__device__ __half g_w2S[Ln*Dn*FFn];              // [4096, 1024]
__device__ __half g_wfS[(size_t)Dn*Vn];          // [1024, 32000]

// ==================== helpers ====================
__device__ __forceinline__ uint32_t smem_u32(const void* p){
    uint32_t a;
    asm("{ .reg .u64 t; cvta.to.shared.u64 t, %1; cvt.u32.u64 %0, t; }" : "=r"(a) : "l"(p));
    return a;
}
#define CP16(dst, src) \
    asm volatile("cp.async.cg.shared.global [%0], [%1], 16;" :: "r"(dst), "l"(src))
#define CP_COMMIT() asm volatile("cp.async.commit_group;" ::: "memory")
#define CP_WAIT1() asm volatile("cp.async.wait_group 1;" ::: "memory")
#define CP_WAIT0() asm volatile("cp.async.wait_group 0;" ::: "memory")

#define LDSM4(r0,r1,r2,r3,addr) \
    asm volatile("ldmatrix.sync.aligned.m8n8.x4.shared.b16 {%0,%1,%2,%3}, [%4];" \
        : "=r"(r0),"=r"(r1),"=r"(r2),"=r"(r3) : "r"(addr))
#define LDSM4T(r0,r1,r2,r3,addr) \
    asm volatile("ldmatrix.sync.aligned.m8n8.x4.trans.shared.b16 {%0,%1,%2,%3}, [%4];" \
        : "=r"(r0),"=r"(r1),"=r"(r2),"=r"(r3) : "r"(addr))

#define MMA16816(d, a, b) \
    asm volatile("mma.sync.aligned.m16n8k16.row.col.f32.f16.f16.f32 " \
        "{%0,%1,%2,%3}, {%4,%5,%6,%7}, {%8,%9}, {%0,%1,%2,%3};" \
        : "+f"((d)[0]),"+f"((d)[1]),"+f"((d)[2]),"+f"((d)[3]) \
        : "r"((a)[0]),"r"((a)[1]),"r"((a)[2]),"r"((a)[3]), "r"((b)[0]),"r"((b)[1]))

// ==================== reductions ====================
__device__ __forceinline__ float warpSum(float v){
#pragma unroll
    for (int o = 16; o > 0; o >>= 1) v += __shfl_down_sync(0xffffffffu, v, o);
    return v;
}
__device__ __forceinline__ float blockSum(float v, float* sh){
    int lane = threadIdx.x & 31, w = threadIdx.x >> 5;
    v = warpSum(v);
    __syncthreads();
    if (lane == 0) sh[w] = v;
    __syncthreads();
    int nw = blockDim.x >> 5;
    v = (threadIdx.x < (unsigned)nw) ? sh[threadIdx.x] : 0.f;
    if (w == 0) v = warpSum(v);
    if (threadIdx.x == 0) sh[0] = v;
    __syncthreads();
    return sh[0];
}

// ==================== small kernels ====================
__global__ void embed_k(const int* __restrict__ x, const float* __restrict__ ce,
                        const float* __restrict__ pe){
    int idx = blockIdx.x * blockDim.x + threadIdx.x;
    int d  = idx & (Dn - 1);
    int mt = idx >> 10;
    int t  = mt & (Tn - 1);
    g_h[idx] = ce[(size_t)x[mt] * Dn + d] + pe[t * Dn + d];
}

// LayerNorm fused with single fp16 plane output
__global__ __launch_bounds__(256) void ln_k(const float* __restrict__ in,
                                            __half* __restrict__ outH,
                                            const float* __restrict__ gs,
                                            const float* __restrict__ gb){
    __shared__ float sh[32];
    int row = blockIdx.x;
    const float4* xr = (const float4*)(in + (size_t)row * Dn);
    float4 vv = xr[threadIdx.x];
    float s  = vv.x + vv.y + vv.z + vv.w;
    float sq = vv.x*vv.x + vv.y*vv.y + vv.z*vv.z + vv.w*vv.w;
    s  = blockSum(s, sh);
    sq = blockSum(sq, sh);
    float mean = s * (1.f / Dn);
    float var  = sq * (1.f / Dn) - mean * mean;
    float r = rsqrtf(var + 1e-5f);
    int i0 = threadIdx.x * 4;
    float o[4];
    o[0] = (vv.x - mean) * r * gs[i0+0] + gb[i0+0];
    o[1] = (vv.y - mean) * r * gs[i0+1] + gb[i0+1];
    o[2] = (vv.z - mean) * r * gs[i0+2] + gb[i0+2];
    o[3] = (vv.w - mean) * r * gs[i0+3] + gb[i0+3];
    __half2 h2[2];
    h2[0] = __half2(__float2half_rn(o[0]), __float2half_rn(o[1]));
    h2[1] = __half2(__float2half_rn(o[2]), __float2half_rn(o[3]));
    *(uint2*)(outH + (size_t)row * Dn + i0) = *(uint2*)h2;
}

// flat fp32 -> fp16 convert (pure copy-convert; n8 = elems/8)
__global__ __launch_bounds__(256) void convF_k(const float* __restrict__ in,
                                               __half* __restrict__ out, int n8){
    int idx = blockIdx.x * blockDim.x + threadIdx.x;
    if (idx >= n8) return;
    const float4* src = (const float4*)in + (size_t)idx * 2;
    float4 v0 = src[0], v1 = src[1];
    __half2 h[4];
    h[0] = __half2(__float2half_rn(v0.x), __float2half_rn(v0.y));
    h[1] = __half2(__float2half_rn(v0.z), __float2half_rn(v0.w));
    h[2] = __half2(__float2half_rn(v1.x), __float2half_rn(v1.y));
    h[3] = __half2(__float2half_rn(v1.z), __float2half_rn(v1.w));
    *(uint4*)(out + (size_t)idx * 8) = *(uint4*)h;
}

// QKV pack convert: in [1024,1024] per layer -> out rows of [1024,3072] at colofs.
// grid (1024 rows, nLayers), 128 threads x 8 elems.
__global__ __launch_bounds__(128) void convQ_k(const float* __restrict__ in,
                                               __half* __restrict__ out, int colofs){
    const long long DD = (long long)Dn * Dn;
    const float* pin = in + blockIdx.y * DD + (size_t)blockIdx.x * Dn;
    __half* pos = out + blockIdx.y * 3 * DD + (size_t)blockIdx.x * 3 * Dn + colofs;
    int c = threadIdx.x * 8;
    const float4* src = (const float4*)(pin + c);
    float4 v0 = src[0], v1 = src[1];
    __half2 h[4];
    h[0] = __half2(__float2half_rn(v0.x), __float2half_rn(v0.y));
    h[1] = __half2(__float2half_rn(v0.z), __float2half_rn(v0.w));
    h[2] = __half2(__float2half_rn(v1.x), __float2half_rn(v1.y));
    h[3] = __half2(__float2half_rn(v1.z), __float2half_rn(v1.w));
    *(uint4*)(pos + c) = *(uint4*)h;
}

// ==================== fused flash attention ====================
// grid (4 q-tiles, 64 bh), 256 threads (8 warps x 16 rows).
__global__ __launch_bounds__(256) void flash_k(
    const __half* __restrict__ q, const __half* __restrict__ k,
    const __half* __restrict__ v, __half* __restrict__ o)
{
    constexpr int PITCH = 144;                 // 64 halves + 16B pad
    constexpr int TILEB = 128 * PITCH;         // 18432
    extern __shared__ char sm[];
    const uint32_t smb = smem_u32(sm);
    const uint32_t Qs = smb, Ks = smb + TILEB, Vs = smb + 2 * TILEB;

    const int qt = blockIdx.x, bh = blockIdx.y;
    const int b = bh >> 4, h = bh & 15;
    const int tid = threadIdx.x, lane = tid & 31, w = tid >> 5;

    const __half* qbase = q + ((size_t)(b * Tn + qt * 128)) * Dn + h * HSn;
    const __half* kbase = k + ((size_t)(b * Tn)) * Dn + h * HSn;
    const __half* vbase = v + ((size_t)(b * Tn)) * Dn + h * HSn;

#pragma unroll
    for (int i = 0; i < 4; i++){
        int idx = i * 256 + tid;
        int r = idx >> 3, c = idx & 7;
        CP16(Qs + r * PITCH + c * 16, qbase + (size_t)r * Dn + c * 8);
    }
    CP_COMMIT();

    float m0 = -1e30f, m1 = -1e30f, l0 = 0.f, l1 = 0.f;
    float acc_o[8][4];
#pragma unroll
    for (int i = 0; i < 8; i++)
#pragma unroll
        for (int j = 0; j < 4; j++) acc_o[i][j] = 0.f;

    for (int kt = 0; kt <= qt; kt++){
        __syncthreads();
        const __half* kb = kbase + (size_t)(kt * 128) * Dn;
        const __half* vb = vbase + (size_t)(kt * 128) * Dn;
#pragma unroll
        for (int i = 0; i < 4; i++){
            int idx = i * 256 + tid;
            int r = idx >> 3, c = idx & 7;
            CP16(Ks + r * PITCH + c * 16, kb + (size_t)r * Dn + c * 8);
            CP16(Vs + r * PITCH + c * 16, vb + (size_t)r * Dn + c * 8);
        }
        CP_COMMIT();
        CP_WAIT0();
        __syncthreads();

        // ---- S = Q K^T (scale pre-folded into q) ----
        float acc_s[16][4];
#pragma unroll
        for (int i = 0; i < 16; i++)
#pragma unroll
            for (int j = 0; j < 4; j++) acc_s[i][j] = 0.f;

#pragma unroll
        for (int kc = 0; kc < 4; kc++){
            uint32_t a[4];
            {
                int row = w * 16 + (lane & 15);
                int colb = (kc * 16 + ((lane >> 4) << 3)) * 2;
                LDSM4(a[0], a[1], a[2], a[3], Qs + row * PITCH + colb);
            }
#pragma unroll
            for (int p = 0; p < 8; p++){
                int rowb = p * 16 + (lane & 7) + ((lane >> 4) << 3);
                int colb = (kc * 16 + (((lane >> 3) & 1) << 3)) * 2;
                uint32_t r0, r1, r2, r3;
                LDSM4(r0, r1, r2, r3, Ks + rowb * PITCH + colb);
                uint32_t b0[2] = {r0, r1}, b1[2] = {r2, r3};
                MMA16816(acc_s[2*p],   a, b0);
                MMA16816(acc_s[2*p+1], a, b1);
            }
        }

        // ---- causal mask (diagonal tile only) ----
        if (kt == qt){
            int r0g = w * 16 + (lane >> 2);
#pragma unroll
            for (int ni = 0; ni < 16; ni++){
#pragma unroll
                for (int c = 0; c < 4; c++){
                    int col = ni * 8 + (lane & 3) * 2 + (c & 1);
                    int row = r0g + ((c >> 1) << 3);
                    if (col > row) acc_s[ni][c] = -1e30f;
                }
            }
        }

        // ---- online softmax ----
        float mx0 = -1e30f, mx1 = -1e30f;
#pragma unroll
        for (int ni = 0; ni < 16; ni++){
            mx0 = fmaxf(mx0, fmaxf(acc_s[ni][0], acc_s[ni][1]));
            mx1 = fmaxf(mx1, fmaxf(acc_s[ni][2], acc_s[ni][3]));
        }
        mx0 = fmaxf(mx0, __shfl_xor_sync(0xffffffffu, mx0, 1));
        mx0 = fmaxf(mx0, __shfl_xor_sync(0xffffffffu, mx0, 2));
        mx1 = fmaxf(mx1, __shfl_xor_sync(0xffffffffu, mx1, 1));
        mx1 = fmaxf(mx1, __shfl_xor_sync(0xffffffffu, mx1, 2));
        float mn0 = fmaxf(m0, mx0), mn1 = fmaxf(m1, mx1);
        float rs0 = __expf(m0 - mn0), rs1 = __expf(m1 - mn1);
        m0 = mn0; m1 = mn1;

        float sum0 = 0.f, sum1 = 0.f;
#pragma unroll
        for (int ni = 0; ni < 16; ni++){
            float p0 = __expf(acc_s[ni][0] - mn0);
            float p1 = __expf(acc_s[ni][1] - mn0);
            float p2 = __expf(acc_s[ni][2] - mn1);
            float p3 = __expf(acc_s[ni][3] - mn1);
            sum0 += p0 + p1; sum1 += p2 + p3;
            acc_s[ni][0] = p0; acc_s[ni][1] = p1;
            acc_s[ni][2] = p2; acc_s[ni][3] = p3;
        }
        // FULL row sum: quad reduction (lanes hold disjoint columns)
        sum0 += __shfl_xor_sync(0xffffffffu, sum0, 1);
        sum0 += __shfl_xor_sync(0xffffffffu, sum0, 2);
        sum1 += __shfl_xor_sync(0xffffffffu, sum1, 1);
        sum1 += __shfl_xor_sync(0xffffffffu, sum1, 2);
        l0 = l0 * rs0 + sum0;
        l1 = l1 * rs1 + sum1;
#pragma unroll
        for (int ni = 0; ni < 8; ni++){
            acc_o[ni][0] *= rs0; acc_o[ni][1] *= rs0;
            acc_o[ni][2] *= rs1; acc_o[ni][3] *= rs1;
        }

        // ---- O += P V ----
#pragma unroll
        for (int j2 = 0; j2 < 8; j2++){
            uint32_t pa[4];
            {
                __half2 t0(__float2half_rn(acc_s[2*j2][0]),   __float2half_rn(acc_s[2*j2][1]));
                __half2 t1(__float2half_rn(acc_s[2*j2][2]),   __float2half_rn(acc_s[2*j2][3]));
                __half2 t2(__float2half_rn(acc_s[2*j2+1][0]), __float2half_rn(acc_s[2*j2+1][1]));
                __half2 t3(__float2half_rn(acc_s[2*j2+1][2]), __float2half_rn(acc_s[2*j2+1][3]));
                pa[0] = *(uint32_t*)&t0; pa[1] = *(uint32_t*)&t1;
                pa[2] = *(uint32_t*)&t2; pa[3] = *(uint32_t*)&t3;
            }
#pragma unroll
            for (int p = 0; p < 4; p++){
                int g = lane >> 3, rr = lane & 7;
                int row = j2 * 16 + (g & 1) * 8 + rr;
                int colb = (p * 16 + (g >> 1) * 8) * 2;
                uint32_t r0, r1, r2, r3;
                LDSM4T(r0, r1, r2, r3, Vs + row * PITCH + colb);
                uint32_t b0[2] = {r0, r1}, b1[2] = {r2, r3};
                MMA16816(acc_o[2*p],   pa, b0);
                MMA16816(acc_o[2*p+1], pa, b1);
            }
        }
    }

    // ---- epilogue ----
    float inv0 = 1.f / l0, inv1 = 1.f / l1;
    int row0 = qt * 128 + w * 16 + (lane >> 2);
    __half* ob = o + ((size_t)(b * Tn)) * Dn + h * HSn;
#pragma unroll
    for (int ni = 0; ni < 8; ni++){
        int col = ni * 8 + (lane & 3) * 2;
        __half2 v0(__float2half_rn(acc_o[ni][0] * inv0), __float2half_rn(acc_o[ni][1] * inv0));
        __half2 v1(__float2half_rn(acc_o[ni][2] * inv1), __float2half_rn(acc_o[ni][3] * inv1));
        *(__half2*)(ob + (size_t)row0 * Dn + col) = v0;
        *(__half2*)(ob + (size_t)(row0 + 8) * Dn + col) = v1;
    }
}

// ==================== fp16 mma.sync GEMM (3-stage pipeline, 1-pass) ========
#define F_BIAS   1
#define F_RES    2
#define F_RELU   4
#define F_QKV    64

template<int BN, bool BTRANS>
__global__ __launch_bounds__(256, 2) void gemm_mma(
    const __half* __restrict__ Ah,
    const __half* __restrict__ Bs,
    const float* __restrict__ bias, const float* __restrict__ res,
    float* __restrict__ Cf, __half* __restrict__ Ch,
    __half* __restrict__ C2, __half* __restrict__ C3,
    int K, int lda, int ldb, int ldc,
    int flags)
{
    constexpr int BM = 128, BK = 32;
    constexpr int ABYTES = BM * 40 * 2;
    constexpr int BPITCH = BTRANS ? (BN * 2 + 16) : 80;
    constexpr int BBYTES = BTRANS ? (BK * BPITCH) : (BN * 80);
    constexpr int STAGE = ABYTES + BBYTES;
    constexpr int WN = BN / 2;
    constexpr int NA = WN / 8;

    const int bm = blockIdx.y * BM, bn = blockIdx.x * BN;

    extern __shared__ char sm[];
    const uint32_t smb = smem_u32(sm);

    const int tid = threadIdx.x, lane = tid & 31, wid = tid >> 5;
    const int wm = wid & 3, wn = wid >> 2;

    const int nKB = K >> 5;

    auto loadStage = [&](int kb, int s){
        const int k0 = kb * BK;
        const uint32_t stg = smb + s * STAGE;
#pragma unroll
        for (int i = 0; i < 2; i++){
            int idx = i * 256 + tid;
            int r = idx >> 2, c = idx & 3;
            uint32_t dst = stg + r * 80 + c * 16;
            CP16(dst, Ah + (size_t)(bm + r) * lda + k0 + c * 8);
        }
        if (BTRANS){
            constexpr int CPR = BN / 8;
#pragma unroll
            for (int i = 0; i < (BK * CPR) / 256; i++){
                int idx = i * 256 + tid;
                int r = idx / CPR, c = idx % CPR;
                uint32_t dst = stg + ABYTES + r * BPITCH + c * 16;
                CP16(dst, Bs + (size_t)(k0 + r) * ldb + bn + c * 8);
            }
        } else {
#pragma unroll
            for (int i = 0; i < BN / 64; i++){
                int idx = i * 256 + tid;
                int r = idx >> 2, c = idx & 3;
                uint32_t dst = stg + ABYTES + r * 80 + c * 16;
                CP16(dst, Bs + (size_t)(bn + r) * ldb + k0 + c * 8);
            }
        }
        CP_COMMIT();
    };

    float acc[2][NA][4];
#pragma unroll
    for (int i = 0; i < 2; i++)
#pragma unroll
        for (int j = 0; j < NA; j++)
#pragma unroll
            for (int q = 0; q < 4; q++) acc[i][j][q] = 0.f;

    loadStage(0, 0);
    loadStage(1, 1);

    for (int kb = 0; kb < nKB; kb++){
        if (kb == nKB - 1) CP_WAIT0(); else CP_WAIT1();
        __syncthreads();
        if (kb + 2 < nKB){
            int s2 = kb + 2; while (s2 >= 3) s2 -= 3;
            loadStage(kb + 2, s2);
        }
        int s = kb; while (s >= 3) s -= 3;
        const uint32_t stg = smb + s * STAGE;
#pragma unroll
        for (int ks = 0; ks < 2; ks++){
            const int kc = ks * 16;
            uint32_t a_h[2][4];
#pragma unroll
            for (int mi = 0; mi < 2; mi++){
                int row = wm * 32 + mi * 16 + (lane & 15);
                int colb = (kc + ((lane >> 4) << 3)) * 2;
                uint32_t ad = stg + row * 80 + colb;
                LDSM4(a_h[mi][0], a_h[mi][1], a_h[mi][2], a_h[mi][3], ad);
            }
            uint32_t b_s[NA][2];
            if (BTRANS){
#pragma unroll
                for (int p = 0; p < NA / 2; p++){
                    int g = lane >> 3, rr = lane & 7;
                    int row = kc + (g & 1) * 8 + rr;
                    int colb = (wn * WN + p * 16 + (g >> 1) * 8) * 2;
                    uint32_t ad = stg + ABYTES + row * BPITCH + colb;
                    uint32_t r0, r1, r2, r3;
                    LDSM4T(r0, r1, r2, r3, ad);
                    b_s[2*p][0] = r0; b_s[2*p][1] = r1;
                    b_s[2*p+1][0] = r2; b_s[2*p+1][1] = r3;
                }
            } else {
#pragma unroll
                for (int p = 0; p < NA / 2; p++){
                    int rowb = wn * WN + p * 16 + (lane & 7) + ((lane >> 4) << 3);
                    int colb = (kc + (((lane >> 3) & 1) << 3)) * 2;
                    uint32_t ad = stg + ABYTES + rowb * 80 + colb;
                    uint32_t r0, r1, r2, r3;
                    LDSM4(r0, r1, r2, r3, ad);
                    b_s[2*p][0] = r0; b_s[2*p][1] = r1;
                    b_s[2*p+1][0] = r2; b_s[2*p+1][1] = r3;
                }
            }
#pragma unroll
            for (int mi = 0; mi < 2; mi++)
#pragma unroll
                for (int ni = 0; ni < NA; ni++)
                    MMA16816(acc[mi][ni], a_h[mi], b_s[ni]);
        }
    }

    // epilogue
#pragma unroll
    for (int mi = 0; mi < 2; mi++){
#pragma unroll
        for (int ni = 0; ni < NA; ni++){
            int r0 = bm + wm * 32 + mi * 16 + (lane >> 2);
            int c0 = bn + wn * WN + ni * 8 + (lane & 3) * 2;
#pragma unroll
            for (int half = 0; half < 2; half++){
                int r = r0 + half * 8;
                float vx = acc[mi][ni][half * 2 + 0];
                float vy = acc[mi][ni][half * 2 + 1];
                if (flags & F_QKV){
                    int range = c0 >> 10, cc = c0 & 1023;
                    if (range == 0){ vx *= 0.125f; vy *= 0.125f; }
                    __half2 hv(__float2half_rn(vx), __float2half_rn(vy));
                    if (range == 0)
                        *(__half2*)(Ch + (size_t)r * ldc + cc) = hv;
                    else if (range == 1)
                        *(__half2*)(C2 + (size_t)r * ldc + cc) = hv;
                    else
                        *(__half2*)(C3 + (size_t)r * ldc + cc) = hv;
                    continue;
                }
                if (flags & F_BIAS){ vx += bias[c0]; vy += bias[c0 + 1]; }
                if (flags & F_RES){
                    const float* rp = res + (size_t)r * ldc + c0;
                    vx += rp[0]; vy += rp[1];
                }
                if (flags & F_RELU){ vx = fmaxf(vx, 0.f); vy = fmaxf(vy, 0.f); }
                if (Cf){
                    float2 o2; o2.x = vx; o2.y = vy;
                    *(float2*)(Cf + (size_t)r * ldc + c0) = o2;
                }
                if (Ch){
                    __half2 hv(__float2half_rn(vx), __float2half_rn(vy));
                    *(__half2*)(Ch + (size_t)r * ldc + c0) = hv;
                }
            }
        }
    }
}

// ==================== host orchestration ====================
extern "C" void kernel_launch(void* const* d_in, const int* in_sizes, int n_in,
                              void* d_out, int out_size){
    (void)in_sizes; (void)n_in; (void)out_size;
    const int*   x     = (const int*)  d_in[0];
    const float* ce    = (const float*)d_in[1];
    const float* pe    = (const float*)d_in[2];
    const float* ln1_s = (const float*)d_in[5];
    const float* ln1_b = (const float*)d_in[6];
    const float* wq    = (const float*)d_in[7];
    const float* wk    = (const float*)d_in[8];
    const float* wv    = (const float*)d_in[9];
    const float* wo    = (const float*)d_in[10];
    const float* bo    = (const float*)d_in[11];
    const float* ln2_s = (const float*)d_in[12];
    const float* ln2_b = (const float*)d_in[13];
    const float* w1    = (const float*)d_in[14];
    const float* b1    = (const float*)d_in[15];
    const float* w2    = (const float*)d_in[16];
    const float* b2    = (const float*)d_in[17];
    const float* lnf_s = (const float*)d_in[18];
    const float* lnf_b = (const float*)d_in[19];
    const float* wf    = (const float*)d_in[20];
    const float* bf    = (const float*)d_in[21];

    float *h;
    cudaGetSymbolAddress((void**)&h, g_h);

    __half *yS,*qS,*kS,*vS,*oS,*aS;
    cudaGetSymbolAddress((void**)&yS, g_yS);
    cudaGetSymbolAddress((void**)&qS, g_qS);
    cudaGetSymbolAddress((void**)&kS, g_kS);
    cudaGetSymbolAddress((void**)&vS, g_vS);
    cudaGetSymbolAddress((void**)&oS, g_oS);
    cudaGetSymbolAddress((void**)&aS, g_aS);

    __half *wqkvS,*woS,*w1S,*w2S,*wfS;
    cudaGetSymbolAddress((void**)&wqkvS, g_wqkvS);
    cudaGetSymbolAddress((void**)&woS, g_woS);
    cudaGetSymbolAddress((void**)&w1S, g_w1S);
    cudaGetSymbolAddress((void**)&w2S, g_w2S);
    cudaGetSymbolAddress((void**)&wfS, g_wfS);

    const int SMWT = 56832, SMFL = 55296;
    cudaFuncSetAttribute((const void*)gemm_mma<128,true>, cudaFuncAttributeMaxDynamicSharedMemorySize, SMWT);
    cudaFuncSetAttribute((const void*)flash_k,            cudaFuncAttributeMaxDynamicSharedMemorySize, SMFL);

    // secondary stream + fork/join events (host resources, created once;
    // captured graph is identical on every call)
    static cudaStream_t s2 = nullptr;
    static cudaEvent_t evF = nullptr, evJ = nullptr;
    if (!s2){
        cudaStreamCreateWithFlags(&s2, cudaStreamNonBlocking);
        cudaEventCreateWithFlags(&evF, cudaEventDisableTiming);
        cudaEventCreateWithFlags(&evJ, cudaEventDisableTiming);
    }

    const long long DD = (long long)Dn * Dn;
    const long long DF = (long long)Dn * FFn;

    // ---- fork: stream2 converts layers 1..7 weights + wf (hidden under layer 0)
    cudaEventRecord(evF, 0);
    cudaStreamWaitEvent(s2, evF, 0);
    convQ_k<<<dim3(Dn, Ln-1), 128, 0, s2>>>(wq + DD, wqkvS + 3*DD, 0);
    convQ_k<<<dim3(Dn, Ln-1), 128, 0, s2>>>(wk + DD, wqkvS + 3*DD, Dn);
    convQ_k<<<dim3(Dn, Ln-1), 128, 0, s2>>>(wv + DD, wqkvS + 3*DD, 2*Dn);
    convF_k<<<(int)((Ln-1)*DD/8 + 255)/256, 256, 0, s2>>>(wo + DD, woS + DD, (int)((Ln-1)*DD/8));
    convF_k<<<(int)((Ln-1)*DF/8 + 255)/256, 256, 0, s2>>>(w1 + DF, w1S + DF, (int)((Ln-1)*DF/8));
    convF_k<<<(int)((Ln-1)*DF/8 + 255)/256, 256, 0, s2>>>(w2 + DF, w2S + DF, (int)((Ln-1)*DF/8));
    convF_k<<<(int)(((long long)Dn*Vn/8) + 255)/256, 256, 0, s2>>>(wf, wfS, (int)((long long)Dn*Vn/8));
    cudaEventRecord(evJ, s2);

    // ---- main stream: layer-0 weights only (small), then compute
    convQ_k<<<dim3(Dn, 1), 128>>>(wq, wqkvS, 0);
    convQ_k<<<dim3(Dn, 1), 128>>>(wk, wqkvS, Dn);
    convQ_k<<<dim3(Dn, 1), 128>>>(wv, wqkvS, 2*Dn);
    convF_k<<<(int)(DD/8/256), 256>>>(wo, woS, (int)(DD/8));
    convF_k<<<(int)(DF/8/256), 256>>>(w1, w1S, (int)(DF/8));
    convF_k<<<(int)(DF/8/256), 256>>>(w2, w2S, (int)(DF/8));

    embed_k<<<(Mn * Dn) / 256, 256>>>(x, ce, pe);

    for (int l = 0; l < Ln; l++){
        if (l == 1) cudaStreamWaitEvent(0, evJ, 0);   // join before layer-1 weights

        ln_k<<<Mn, 256>>>(h, yS, ln1_s + l*Dn, ln1_b + l*Dn);

        // fused QKV: q (pre-scaled 1/8), k, v fp16 planes
        gemm_mma<128,true><<<dim3(24,16,1), 256, SMWT>>>(yS,
            wqkvS + (size_t)l*3*DD,
            nullptr, nullptr, nullptr, qS, kS, vS, Dn, Dn, 3*Dn, Dn, F_QKV);

        // fused flash attention
        flash_k<<<dim3(4, BHn), 256, SMFL>>>(qS, kS, vS, oS);

        // O-proj
        gemm_mma<128,true><<<dim3(8,16,1), 256, SMWT>>>(oS,
            woS + (size_t)l*DD,
            bo + l*Dn, h, h, nullptr, nullptr, nullptr, Dn, Dn, Dn, Dn,
            F_BIAS | F_RES);

        ln_k<<<Mn, 256>>>(h, yS, ln2_s + l*Dn, ln2_b + l*Dn);

        // MLP1
        gemm_mma<128,true><<<dim3(32,16,1), 256, SMWT>>>(yS,
            w1S + (size_t)l*DF,
            b1 + l*FFn, nullptr, nullptr, aS, nullptr, nullptr,
            Dn, Dn, FFn, FFn, F_BIAS | F_RELU);

        // MLP2
        gemm_mma<128,true><<<dim3(8,16,1), 256, SMWT>>>(aS,
            w2S + (size_t)l*DF,
            b2 + l*Dn, h, h, nullptr, nullptr, nullptr,
            FFn, FFn, Dn, Dn, F_BIAS | F_RES);
    }

    ln_k<<<Mn, 256>>>(h, yS, lnf_s, lnf_b);

    // logits
    gemm_mma<128,true><<<dim3(Vn/128, 16, 1), 256, SMWT>>>(yS, wfS,
        bf, nullptr, (float*)d_out, nullptr, nullptr, nullptr,
        Dn, Dn, Vn, Vn, F_BIAS);
}